// round 1
// baseline (speedup 1.0000x reference)
#include <cuda_runtime.h>
#include <math.h>

// Problem constants (fixed by the dataset)
#define NN 4096      // nodes
#define NV 3         // vector channels
#define MMDIM 16     // equ feature dim
#define EE 256       // embed dim
#define HH 8         // heads
#define DD 32        // head dim
#define ROWS (NN*NV) // 12288

// ---------------------------------------------------------------------------
// Scratch: single __device__ global (no allocations allowed)
// ---------------------------------------------------------------------------
__device__ float scratch[26607616];

#define OFF_GSRC   0u          // [12288,256]
#define OFF_G2P    3145728u    // [12288,32]
#define OFF_GRAM   3538944u    // [4096,1024]
#define OFF_HID    7733248u    // [4096,512]
#define OFF_H2     9830400u    // [4096,512]
#define OFF_Q      11927552u   // [4096,256]
#define OFF_K      12976128u   // [4096,256]
#define OFF_V      14024704u   // [4096,256]
#define OFF_VG     15073280u   // [12288,256]
#define OFF_OUTV   18219008u   // [4096,256]
#define OFF_OUTG   19267584u   // [12288,256]
#define OFF_HSRC   22413312u   // [4096,256]
#define OFF_GSF    23461888u   // [12288,256]

// ---------------------------------------------------------------------------
// Generic SGEMM: C[m,n] = alpha*(sum_k A[m,k]*B[k,n] + bias[n]) + resScale*Res[m,n]
// optional relu. Tile 64x64, BK=16, 256 threads, 4x4 per thread.
// M must be a multiple of 64 (true for all call sites). N guarded.
// ---------------------------------------------------------------------------
template<bool RELU>
__global__ __launch_bounds__(256)
void sgemm_kernel(const float* __restrict__ A, int lda,
                  const float* __restrict__ B, int ldb,
                  const float* __restrict__ bias,
                  const float* __restrict__ Res, float resScale,
                  float alpha,
                  float* __restrict__ C, int ldc,
                  int M, int Nd, int K)
{
    __shared__ float As[16 * 68]; // A transposed [k][m], row stride 68 (pad)
    __shared__ float Bs[16 * 64]; // B [k][n]

    const int tid = threadIdx.x;
    const int tx  = tid & 15;
    const int ty  = tid >> 4;
    const int bm  = blockIdx.y * 64;
    const int bn  = blockIdx.x * 64;

    float acc[4][4] = {};

    for (int k0 = 0; k0 < K; k0 += 16) {
        // Load A tile (64x16) -> As[k][m]
        #pragma unroll
        for (int i = 0; i < 4; i++) {
            int idx = tid + i * 256;
            int m_  = idx >> 4;
            int kk  = idx & 15;
            As[kk * 68 + m_] = A[(size_t)(bm + m_) * lda + k0 + kk];
        }
        // Load B tile (16x64) -> Bs[k][n]
        #pragma unroll
        for (int i = 0; i < 4; i++) {
            int idx = tid + i * 256;
            int kk  = idx >> 6;
            int nn  = idx & 63;
            int gn  = bn + nn;
            Bs[kk * 64 + nn] = (gn < Nd) ? B[(size_t)(k0 + kk) * ldb + gn] : 0.f;
        }
        __syncthreads();

        #pragma unroll
        for (int kk = 0; kk < 16; kk++) {
            float4 a4 = *(const float4*)&As[kk * 68 + ty * 4];
            float4 b4 = *(const float4*)&Bs[kk * 64 + tx * 4];
            float a_[4] = {a4.x, a4.y, a4.z, a4.w};
            float b_[4] = {b4.x, b4.y, b4.z, b4.w};
            #pragma unroll
            for (int i = 0; i < 4; i++)
                #pragma unroll
                for (int j = 0; j < 4; j++)
                    acc[i][j] = fmaf(a_[i], b_[j], acc[i][j]);
        }
        __syncthreads();
    }

    #pragma unroll
    for (int i = 0; i < 4; i++) {
        int gm = bm + ty * 4 + i;
        #pragma unroll
        for (int j = 0; j < 4; j++) {
            int gn = bn + tx * 4 + j;
            if (gn < Nd) {
                float v = acc[i][j];
                if (bias) v += bias[gn];
                v *= alpha;
                if (Res) v = fmaf(resScale, Res[(size_t)gm * Nd + gn], v);
                if (RELU) v = fmaxf(v, 0.f);
                C[(size_t)gm * ldc + gn] = v;
            }
        }
    }
}

// ---------------------------------------------------------------------------
// Gram: per node, gram[a,b] = sum_{i<3} g2p[node,i,a]*g2p[node,i,b]
// ---------------------------------------------------------------------------
__global__ void gram_kernel(const float* __restrict__ g2p, float* __restrict__ gram)
{
    int node = blockIdx.x;
    __shared__ float s[96];
    int tid = threadIdx.x; // 128
    if (tid < 96) s[tid] = g2p[(size_t)node * 96 + tid];
    __syncthreads();
    #pragma unroll
    for (int o = tid; o < 1024; o += 128) {
        int a = o >> 5, b = o & 31;
        float v = s[a] * s[b] + s[32 + a] * s[32 + b] + s[64 + a] * s[64 + b];
        gram[(size_t)node * 1024 + o] = v;
    }
}

// h2[:, 256:512] = 16 * h
__global__ void h2fill_kernel(const float* __restrict__ h, float* __restrict__ h2)
{
    int idx = blockIdx.x * blockDim.x + threadIdx.x;
    if (idx < NN * EE) {
        int r = idx >> 8, c = idx & 255;
        h2[(size_t)r * 512 + 256 + c] = 16.f * h[idx];
    }
}

// ---------------------------------------------------------------------------
// Flash attention: per (head, 64-query block). Value dim = 128 (v | vg0|vg1|vg2).
// Online softmax over all N keys. Writes out_v [N,256] and out_g [N,3,256].
// ---------------------------------------------------------------------------
#define AQ 64
#define AK 64
#define QKP 68      // padded row stride for transposed Q/K tiles
#define PSP 65      // padded row stride for P tile
#define ATTN_SMEM ((2*32*QKP + 64*128 + 64*PSP + 3*64) * 4)

__global__ __launch_bounds__(256, 3)
void attn_kernel(const float* __restrict__ q,
                 const float* __restrict__ k,
                 const float* __restrict__ v,
                 const float* __restrict__ vg,
                 float* __restrict__ out_v,
                 float* __restrict__ out_g)
{
    extern __shared__ float sm[];
    float* Qs   = sm;                    // [32][QKP] (d-major)
    float* Ks   = Qs + 32 * QKP;         // [32][QKP]
    float* Vs   = Ks + 32 * QKP;         // [64][128]
    float* Ps   = Vs + 64 * 128;         // [64][PSP]
    float* rowm = Ps + 64 * PSP;         // [64]
    float* rowl = rowm + 64;             // [64]
    float* rowa = rowl + 64;             // [64]

    const int h   = blockIdx.y;
    const int qb  = blockIdx.x * AQ;
    const int tid = threadIdx.x;
    const int tx  = tid & 15;
    const int ty  = tid >> 4;
    const int hof = h * DD;

    // Load Q block transposed: Qs[d][m]
    for (int i = tid; i < AQ * 32; i += 256) {
        int m_ = i >> 5, d = i & 31;
        Qs[d * QKP + m_] = q[(size_t)(qb + m_) * EE + hof + d];
    }
    if (tid < 64) { rowm[tid] = -1e30f; rowl[tid] = 0.f; }

    float O[4][8] = {};

    __syncthreads();

    for (int kb = 0; kb < NN; kb += AK) {
        // K block transposed
        for (int i = tid; i < AK * 32; i += 256) {
            int m_ = i >> 5, d = i & 31;
            Ks[d * QKP + m_] = k[(size_t)(kb + m_) * EE + hof + d];
        }
        // V block: [row][0:32]=v, [32+j*32 : ...]=vg[:,j]
        for (int i4 = tid; i4 < AK * 128 / 4; i4 += 256) {
            int pos = i4 * 4;
            int row = pos >> 7;
            int c   = pos & 127;
            int chunk = c >> 5;
            int d0    = c & 31;
            const float* src = (chunk == 0)
                ? &v[(size_t)(kb + row) * EE + hof + d0]
                : &vg[((size_t)(kb + row) * 3 + (chunk - 1)) * EE + hof + d0];
            *(float4*)&Vs[pos] = *(const float4*)src;
        }
        __syncthreads();

        // S = Q K^T  (rows ty*4.., cols tx*4..)
        float acc[4][4] = {};
        #pragma unroll 8
        for (int d = 0; d < 32; d++) {
            float4 q4 = *(const float4*)&Qs[d * QKP + ty * 4];
            float4 k4 = *(const float4*)&Ks[d * QKP + tx * 4];
            float qv[4] = {q4.x, q4.y, q4.z, q4.w};
            float kv[4] = {k4.x, k4.y, k4.z, k4.w};
            #pragma unroll
            for (int i = 0; i < 4; i++)
                #pragma unroll
                for (int j = 0; j < 4; j++)
                    acc[i][j] = fmaf(qv[i], kv[j], acc[i][j]);
        }
        #pragma unroll
        for (int i = 0; i < 4; i++)
            #pragma unroll
            for (int j = 0; j < 4; j++)
                Ps[(ty * 4 + i) * PSP + tx * 4 + j] = acc[i][j];
        __syncthreads();

        // Online softmax per row (threads 0..63)
        if (tid < 64) {
            float* Pr = &Ps[tid * PSP];
            float mold = rowm[tid];
            float mx = mold;
            #pragma unroll 16
            for (int c = 0; c < 64; c++) mx = fmaxf(mx, Pr[c]);
            float al = __expf(mold - mx);
            float s = 0.f;
            #pragma unroll 16
            for (int c = 0; c < 64; c++) {
                float e = __expf(Pr[c] - mx);
                Pr[c] = e;
                s += e;
            }
            rowm[tid] = mx;
            rowl[tid] = rowl[tid] * al + s;
            rowa[tid] = al;
        }
        __syncthreads();

        // O = O*alpha + P @ V   (rows ty*4.., cols tx*8..)
        float al[4];
        #pragma unroll
        for (int i = 0; i < 4; i++) al[i] = rowa[ty * 4 + i];
        #pragma unroll
        for (int i = 0; i < 4; i++)
            #pragma unroll
            for (int j = 0; j < 8; j++)
                O[i][j] *= al[i];

        #pragma unroll 4
        for (int kk = 0; kk < AK; kk++) {
            float4 v0 = *(const float4*)&Vs[kk * 128 + tx * 8];
            float4 v1 = *(const float4*)&Vs[kk * 128 + tx * 8 + 4];
            #pragma unroll
            for (int i = 0; i < 4; i++) {
                float p = Ps[(ty * 4 + i) * PSP + kk];
                O[i][0] = fmaf(p, v0.x, O[i][0]);
                O[i][1] = fmaf(p, v0.y, O[i][1]);
                O[i][2] = fmaf(p, v0.z, O[i][2]);
                O[i][3] = fmaf(p, v0.w, O[i][3]);
                O[i][4] = fmaf(p, v1.x, O[i][4]);
                O[i][5] = fmaf(p, v1.y, O[i][5]);
                O[i][6] = fmaf(p, v1.z, O[i][6]);
                O[i][7] = fmaf(p, v1.w, O[i][7]);
            }
        }
        __syncthreads();
    }

    // Normalize + write out
    #pragma unroll
    for (int i = 0; i < 4; i++) {
        int qrow = qb + ty * 4 + i;
        float linv = 1.f / rowl[ty * 4 + i];
        #pragma unroll
        for (int j = 0; j < 8; j++) {
            int c = tx * 8 + j;
            float val = O[i][j] * linv;
            if (c < 32) {
                out_v[(size_t)qrow * EE + hof + c] = val;
            } else {
                int ch = (c - 32) >> 5;
                int d  = (c - 32) & 31;
                out_g[((size_t)qrow * 3 + ch) * EE + hof + d] = val;
            }
        }
    }
}

// ---------------------------------------------------------------------------
// Host orchestration
// ---------------------------------------------------------------------------
static void gemm(const float* A, int lda, const float* B, int ldb,
                 const float* bias, const float* Res, float resScale,
                 float alpha, float* C, int ldc, int M, int Nd, int K, bool relu)
{
    dim3 g((Nd + 63) / 64, M / 64), b(256);
    if (relu)
        sgemm_kernel<true><<<g, b>>>(A, lda, B, ldb, bias, Res, resScale, alpha, C, ldc, M, Nd, K);
    else
        sgemm_kernel<false><<<g, b>>>(A, lda, B, ldb, bias, Res, resScale, alpha, C, ldc, M, Nd, K);
}

extern "C" void kernel_launch(void* const* d_in, const int* in_sizes, int n_in,
                              void* d_out, int out_size)
{
    const float* equ    = (const float*)d_in[0];
    const float* h      = (const float*)d_in[1];
    const float* W_equ  = (const float*)d_in[4];
    const float* W_gproj= (const float*)d_in[5];
    const float* W_vg   = (const float*)d_in[6];
    const float* W_g1   = (const float*)d_in[7];
    const float* b_g1   = (const float*)d_in[8];
    const float* W_g2   = (const float*)d_in[9];
    const float* b_g2   = (const float*)d_in[10];
    const float* W_q    = (const float*)d_in[11];
    const float* b_q    = (const float*)d_in[12];
    const float* W_k    = (const float*)d_in[13];
    const float* b_k    = (const float*)d_in[14];
    const float* W_v    = (const float*)d_in[15];
    const float* b_v    = (const float*)d_in[16];
    const float* W_ng   = (const float*)d_in[17];
    const float* b_ng   = (const float*)d_in[18];
    const float* W_gout = (const float*)d_in[19];
    const float* W_gdec = (const float*)d_in[20];
    const float* W_hdec = (const float*)d_in[21];
    const float* b_hdec = (const float*)d_in[22];

    float* out = (float*)d_out;   // [equ_out (12288*16)] [h_out (4096*256)]

    float* S = nullptr;
    cudaGetSymbolAddress((void**)&S, scratch);
    cudaFuncSetAttribute(attn_kernel, cudaFuncAttributeMaxDynamicSharedMemorySize, ATTN_SMEM);

    float* g_src = S + OFF_GSRC;
    float* g2p   = S + OFF_G2P;
    float* gram  = S + OFF_GRAM;
    float* hid   = S + OFF_HID;
    float* h2    = S + OFF_H2;
    float* qd    = S + OFF_Q;
    float* kd    = S + OFF_K;
    float* vd    = S + OFF_V;
    float* vgd   = S + OFF_VG;
    float* outv  = S + OFF_OUTV;
    float* outg  = S + OFF_OUTG;
    float* hsrc  = S + OFF_HSRC;
    float* gsf   = S + OFF_GSF;

    const float scaling = 0.17677669529663687f; // 32^-0.5

    // g_src = (equ @ W_equ) * 16
    gemm(equ, MMDIM, W_equ, EE, nullptr, nullptr, 0.f, 16.f, g_src, EE, ROWS, EE, MMDIM, false);
    // g2p = g_src @ W_gproj
    gemm(g_src, EE, W_gproj, 32, nullptr, nullptr, 0.f, 1.f, g2p, 32, ROWS, 32, EE, false);
    // gram
    gram_kernel<<<NN, 128>>>(g2p, gram);
    // hid = relu(gram @ W_g1 + b_g1)
    gemm(gram, 1024, W_g1, 512, b_g1, nullptr, 0.f, 1.f, hid, 512, NN, 512, 1024, true);
    // h2[:, :256] = hid @ W_g2 + b_g2
    gemm(hid, 512, W_g2, EE, b_g2, nullptr, 0.f, 1.f, h2, 512, NN, EE, 512, false);
    // h2[:, 256:] = 16*h
    h2fill_kernel<<<(NN * EE + 255) / 256, 256>>>(h, h2);
    // q = (h2 @ W_q + b_q) * scaling ; k ; v
    gemm(h2, 512, W_q, EE, b_q, nullptr, 0.f, scaling, qd, EE, NN, EE, 512, false);
    gemm(h2, 512, W_k, EE, b_k, nullptr, 0.f, 1.f, kd, EE, NN, EE, 512, false);
    gemm(h2, 512, W_v, EE, b_v, nullptr, 0.f, 1.f, vd, EE, NN, EE, 512, false);
    // vg = g_src @ W_vg
    gemm(g_src, EE, W_vg, EE, nullptr, nullptr, 0.f, 1.f, vgd, EE, ROWS, EE, EE, false);

    // attention -> out_v, out_g
    attn_kernel<<<dim3(NN / AQ, HH), 256, ATTN_SMEM>>>(qd, kd, vd, vgd, outv, outg);

    // h_src_final = out_v @ W_ng + b_ng + 16*h
    gemm(outv, EE, W_ng, EE, b_ng, h, 16.f, 1.f, hsrc, EE, NN, EE, EE, false);
    // g_src_final = out_g @ W_gout + g_src
    gemm(outg, EE, W_gout, EE, nullptr, g_src, 1.f, 1.f, gsf, EE, ROWS, EE, EE, false);
    // equ_out = g_src_final @ W_gdec
    gemm(gsf, EE, W_gdec, MMDIM, nullptr, nullptr, 0.f, 1.f, out, MMDIM, ROWS, MMDIM, EE, false);
    // h_out = h_src_final @ W_hdec + b_hdec
    gemm(hsrc, EE, W_hdec, EE, b_hdec, nullptr, 0.f, 1.f, out + ROWS * MMDIM, EE, NN, EE, EE, false);
}

// round 2
// speedup vs baseline: 2.7395x; 2.7395x over previous
#include <cuda_runtime.h>
#include <math.h>

#define NN 4096
#define NV 3
#define MMDIM 16
#define EE 256
#define HH 8
#define DD 32
#define ROWS (NN*NV)

__device__ float scratch[26607616];

#define OFF_GSRC   0u
#define OFF_G2P    3145728u
#define OFF_GRAM   3538944u
#define OFF_HID    7733248u
#define OFF_H2     9830400u
#define OFF_Q      11927552u
#define OFF_K      12976128u
#define OFF_V      14024704u
#define OFF_VG     15073280u
#define OFF_OUTV   18219008u
#define OFF_OUTG   19267584u
#define OFF_HSRC   22413312u
#define OFF_GSF    23461888u

// ---------------------------------------------------------------------------
// tf32 helpers
// ---------------------------------------------------------------------------
__device__ __forceinline__ float to_tf32(float x) {
    unsigned u;
    asm("cvt.rna.tf32.f32 %0, %1;" : "=r"(u) : "f"(x));
    return __uint_as_float(u);
}

__device__ __forceinline__ void mma_tf32(float c[4],
                                         float a0, float a1, float a2, float a3,
                                         float b0, float b1) {
    unsigned A0 = __float_as_uint(a0), A1 = __float_as_uint(a1);
    unsigned A2 = __float_as_uint(a2), A3 = __float_as_uint(a3);
    unsigned B0 = __float_as_uint(b0), B1 = __float_as_uint(b1);
    asm volatile(
        "mma.sync.aligned.m16n8k8.row.col.f32.tf32.tf32.f32 "
        "{%0,%1,%2,%3}, {%4,%5,%6,%7}, {%8,%9}, {%0,%1,%2,%3};"
        : "+f"(c[0]), "+f"(c[1]), "+f"(c[2]), "+f"(c[3])
        : "r"(A0), "r"(A1), "r"(A2), "r"(A3), "r"(B0), "r"(B1));
}

// ---------------------------------------------------------------------------
// fp32 SGEMM (kept for precision-critical / tiny-N GEMMs)
// 64x64 tile, BK=16, 256 threads, 4x4 per thread.
// ---------------------------------------------------------------------------
template<bool RELU>
__global__ __launch_bounds__(256)
void sgemm_kernel(const float* __restrict__ A, int lda,
                  const float* __restrict__ B, int ldb,
                  const float* __restrict__ bias,
                  const float* __restrict__ Res, float resScale,
                  float alpha,
                  float* __restrict__ C, int ldc,
                  int M, int Nd, int K)
{
    __shared__ float As[16 * 68];
    __shared__ float Bs[16 * 64];

    const int tid = threadIdx.x;
    const int tx  = tid & 15;
    const int ty  = tid >> 4;
    const int bm  = blockIdx.y * 64;
    const int bn  = blockIdx.x * 64;

    float acc[4][4] = {};

    for (int k0 = 0; k0 < K; k0 += 16) {
        #pragma unroll
        for (int i = 0; i < 4; i++) {
            int idx = tid + i * 256;
            int m_  = idx >> 4;
            int kk  = idx & 15;
            As[kk * 68 + m_] = A[(size_t)(bm + m_) * lda + k0 + kk];
        }
        #pragma unroll
        for (int i = 0; i < 4; i++) {
            int idx = tid + i * 256;
            int kk  = idx >> 6;
            int nn  = idx & 63;
            int gn  = bn + nn;
            Bs[kk * 64 + nn] = (gn < Nd) ? B[(size_t)(k0 + kk) * ldb + gn] : 0.f;
        }
        __syncthreads();

        #pragma unroll
        for (int kk = 0; kk < 16; kk++) {
            float4 a4 = *(const float4*)&As[kk * 68 + ty * 4];
            float4 b4 = *(const float4*)&Bs[kk * 64 + tx * 4];
            float a_[4] = {a4.x, a4.y, a4.z, a4.w};
            float b_[4] = {b4.x, b4.y, b4.z, b4.w};
            #pragma unroll
            for (int i = 0; i < 4; i++)
                #pragma unroll
                for (int j = 0; j < 4; j++)
                    acc[i][j] = fmaf(a_[i], b_[j], acc[i][j]);
        }
        __syncthreads();
    }

    #pragma unroll
    for (int i = 0; i < 4; i++) {
        int gm = bm + ty * 4 + i;
        #pragma unroll
        for (int j = 0; j < 4; j++) {
            int gn = bn + tx * 4 + j;
            if (gn < Nd) {
                float v = acc[i][j];
                if (bias) v += bias[gn];
                v *= alpha;
                if (Res) v = fmaf(resScale, Res[(size_t)gm * ldc + gn], v);
                if (RELU) v = fmaxf(v, 0.f);
                C[(size_t)gm * ldc + gn] = v;
            }
        }
    }
}

// ---------------------------------------------------------------------------
// TF32 GEMM: block 128x128, BK=16, 8 warps, warp tile 64x32.
// A row-major [M,K]; B natural k-major [K,N]. Requires M%128==0, Nd%128==0, K%16==0.
// ---------------------------------------------------------------------------
#define GA_STR 20    // A smem row stride (16 + 4 pad, ==4 mod 32)
#define GB_STR 136   // B smem row stride (128 + 8 pad, ==8 mod 32)

template<bool RELU>
__global__ __launch_bounds__(256)
void tf32_gemm(const float* __restrict__ A, int lda,
               const float* __restrict__ B, int ldb,
               const float* __restrict__ bias,
               const float* __restrict__ Res, float resScale, float alpha,
               float* __restrict__ C, int ldc,
               int M, int Nd, int K)
{
    __shared__ float As[128 * GA_STR];
    __shared__ float Bs[16 * GB_STR];

    const int tid  = threadIdx.x;
    const int lane = tid & 31;
    const int warp = tid >> 5;
    const int bm   = blockIdx.y * 128;
    const int bn   = blockIdx.x * 128;
    const int wM   = (warp >> 2) * 64;   // 0 or 64
    const int wN   = (warp & 3) * 32;    // 0,32,64,96

    const int lr = lane >> 2;   // 0..7
    const int lc = lane & 3;    // 0..3

    float acc[4][4][4];
    #pragma unroll
    for (int i = 0; i < 4; i++)
        #pragma unroll
        for (int j = 0; j < 4; j++)
            #pragma unroll
            for (int v = 0; v < 4; v++) acc[i][j][v] = 0.f;

    for (int k0 = 0; k0 < K; k0 += 16) {
        // stage A: 128x16, 512 float4
        #pragma unroll
        for (int i = 0; i < 2; i++) {
            int idx = tid + i * 256;
            int row = idx >> 2;
            int seg = idx & 3;
            float4 v = *(const float4*)&A[(size_t)(bm + row) * lda + k0 + seg * 4];
            v.x = to_tf32(v.x); v.y = to_tf32(v.y); v.z = to_tf32(v.z); v.w = to_tf32(v.w);
            *(float4*)&As[row * GA_STR + seg * 4] = v;
        }
        // stage B: 16x128, 512 float4
        #pragma unroll
        for (int i = 0; i < 2; i++) {
            int idx = tid + i * 256;
            int row = idx >> 5;
            int seg = idx & 31;
            float4 v = *(const float4*)&B[(size_t)(k0 + row) * ldb + bn + seg * 4];
            v.x = to_tf32(v.x); v.y = to_tf32(v.y); v.z = to_tf32(v.z); v.w = to_tf32(v.w);
            *(float4*)&Bs[row * GB_STR + seg * 4] = v;
        }
        __syncthreads();

        #pragma unroll
        for (int ks = 0; ks < 2; ks++) {
            float af[4][4];
            #pragma unroll
            for (int mt = 0; mt < 4; mt++) {
                int rb = wM + mt * 16 + lr;
                int c  = ks * 8 + lc;
                af[mt][0] = As[rb * GA_STR + c];
                af[mt][1] = As[(rb + 8) * GA_STR + c];
                af[mt][2] = As[rb * GA_STR + c + 4];
                af[mt][3] = As[(rb + 8) * GA_STR + c + 4];
            }
            float bf[4][2];
            #pragma unroll
            for (int nt = 0; nt < 4; nt++) {
                int n = wN + nt * 8 + lr;
                bf[nt][0] = Bs[(ks * 8 + lc) * GB_STR + n];
                bf[nt][1] = Bs[(ks * 8 + 4 + lc) * GB_STR + n];
            }
            #pragma unroll
            for (int mt = 0; mt < 4; mt++)
                #pragma unroll
                for (int nt = 0; nt < 4; nt++)
                    mma_tf32(acc[mt][nt], af[mt][0], af[mt][1], af[mt][2], af[mt][3],
                             bf[nt][0], bf[nt][1]);
        }
        __syncthreads();
    }

    // epilogue
    #pragma unroll
    for (int mt = 0; mt < 4; mt++) {
        #pragma unroll
        for (int nt = 0; nt < 4; nt++) {
            int col = bn + wN + nt * 8 + 2 * lc;
            #pragma unroll
            for (int half = 0; half < 2; half++) {
                int r = bm + wM + mt * 16 + lr + half * 8;
                float v0 = acc[mt][nt][half * 2 + 0];
                float v1 = acc[mt][nt][half * 2 + 1];
                if (bias) { v0 += bias[col]; v1 += bias[col + 1]; }
                v0 *= alpha; v1 *= alpha;
                if (Res) {
                    v0 = fmaf(resScale, Res[(size_t)r * ldc + col], v0);
                    v1 = fmaf(resScale, Res[(size_t)r * ldc + col + 1], v1);
                }
                if (RELU) { v0 = fmaxf(v0, 0.f); v1 = fmaxf(v1, 0.f); }
                *(float2*)&C[(size_t)r * ldc + col] = make_float2(v0, v1);
            }
        }
    }
}

// ---------------------------------------------------------------------------
// Gram + h2 fill
// ---------------------------------------------------------------------------
__global__ void gram_kernel(const float* __restrict__ g2p, float* __restrict__ gram)
{
    int node = blockIdx.x;
    __shared__ float s[96];
    int tid = threadIdx.x;
    if (tid < 96) s[tid] = g2p[(size_t)node * 96 + tid];
    __syncthreads();
    #pragma unroll
    for (int o = tid; o < 1024; o += 128) {
        int a = o >> 5, b = o & 31;
        gram[(size_t)node * 1024 + o] =
            s[a] * s[b] + s[32 + a] * s[32 + b] + s[64 + a] * s[64 + b];
    }
}

__global__ void h2fill_kernel(const float* __restrict__ h, float* __restrict__ h2)
{
    int idx = blockIdx.x * blockDim.x + threadIdx.x;
    if (idx < NN * EE) {
        int r = idx >> 8, c = idx & 255;
        h2[(size_t)r * 512 + 256 + c] = 16.f * h[idx];
    }
}

// ---------------------------------------------------------------------------
// Flash attention (tf32 tensor cores).
// Block: 128 q rows x head. Key tiles of 32. 8 warps; warp w owns q rows [w*16, w*16+16).
// S = QK^T via tf32x3 (Q,K split hi/lo). PV single-pass tf32.
// Value dim 128 = v | vg0 | vg1 | vg2.
// ---------------------------------------------------------------------------
#define AQ 128
#define AK 32
#define QSTR 36     // ==4 mod 32 : clean A-frag reads
#define KSTR 36     // ==4 mod 32 : clean B-frag reads from [n][k]
#define VSTR 136    // ==8 mod 32 : clean B-frag reads from [k][n]
#define PSTR 36

#define SM_QH 0
#define SM_QL (SM_QH + AQ*QSTR)
#define SM_KH (SM_QL + AQ*QSTR)
#define SM_KL (SM_KH + AK*KSTR)
#define SM_VS (SM_KL + AK*KSTR)
#define SM_PS (SM_VS + AK*VSTR)
#define ATTN_SMEM_FLOATS (SM_PS + AQ*PSTR)
#define ATTN_SMEM (ATTN_SMEM_FLOATS * 4)

__global__ __launch_bounds__(256, 2)
void attn_kernel(const float* __restrict__ q,
                 const float* __restrict__ k,
                 const float* __restrict__ v,
                 const float* __restrict__ vg,
                 float* __restrict__ out_v,
                 float* __restrict__ out_g)
{
    extern __shared__ float sm[];
    float* Qh = sm + SM_QH;
    float* Ql = sm + SM_QL;
    float* Kh = sm + SM_KH;
    float* Kl = sm + SM_KL;
    float* Vs = sm + SM_VS;
    float* Ps = sm + SM_PS;

    const int head = blockIdx.y;
    const int qb   = blockIdx.x * AQ;
    const int tid  = threadIdx.x;
    const int lane = tid & 31;
    const int warp = tid >> 5;
    const int hof  = head * DD;
    const int lr   = lane >> 2;
    const int lc   = lane & 3;
    const int wRow = warp * 16;

    // load Q tile, split hi/lo
    #pragma unroll
    for (int i = 0; i < 4; i++) {
        int idx = tid + i * 256;      // 1024 float4s = 128 rows * 8 segs
        int row = idx >> 3;
        int seg = idx & 7;
        float4 x = *(const float4*)&q[(size_t)(qb + row) * EE + hof + seg * 4];
        float4 hi, lo;
        hi.x = to_tf32(x.x); lo.x = to_tf32(x.x - hi.x);
        hi.y = to_tf32(x.y); lo.y = to_tf32(x.y - hi.y);
        hi.z = to_tf32(x.z); lo.z = to_tf32(x.z - hi.z);
        hi.w = to_tf32(x.w); lo.w = to_tf32(x.w - hi.w);
        *(float4*)&Qh[row * QSTR + seg * 4] = hi;
        *(float4*)&Ql[row * QSTR + seg * 4] = lo;
    }

    float O[16][4];
    #pragma unroll
    for (int nt = 0; nt < 16; nt++)
        #pragma unroll
        for (int j = 0; j < 4; j++) O[nt][j] = 0.f;
    float m0 = -1e30f, m1 = -1e30f, l0 = 0.f, l1 = 0.f;

    __syncthreads();

    for (int kb = 0; kb < NN; kb += AK) {
        // load K tile (32x32) split hi/lo: 256 float4
        {
            int row = tid >> 3;
            int seg = tid & 7;
            float4 x = *(const float4*)&k[(size_t)(kb + row) * EE + hof + seg * 4];
            float4 hi, lo;
            hi.x = to_tf32(x.x); lo.x = to_tf32(x.x - hi.x);
            hi.y = to_tf32(x.y); lo.y = to_tf32(x.y - hi.y);
            hi.z = to_tf32(x.z); lo.z = to_tf32(x.z - hi.z);
            hi.w = to_tf32(x.w); lo.w = to_tf32(x.w - hi.w);
            *(float4*)&Kh[row * KSTR + seg * 4] = hi;
            *(float4*)&Kl[row * KSTR + seg * 4] = lo;
        }
        // load V tile: 32 keys x 128 feats, natural [k][n]: 1024 float4
        #pragma unroll
        for (int i = 0; i < 4; i++) {
            int idx = tid + i * 256;
            int key = idx >> 5;
            int c4  = idx & 31;
            int chunk = c4 >> 3;
            int w = c4 & 7;
            const float* src = (chunk == 0)
                ? &v[(size_t)(kb + key) * EE + hof + w * 4]
                : &vg[((size_t)(kb + key) * 3 + (chunk - 1)) * EE + hof + w * 4];
            float4 x = *(const float4*)src;
            x.x = to_tf32(x.x); x.y = to_tf32(x.y); x.z = to_tf32(x.z); x.w = to_tf32(x.w);
            *(float4*)&Vs[key * VSTR + c4 * 4] = x;
        }
        __syncthreads();

        // S = Q K^T (tf32x3): warp computes 16 rows x 32 keys
        float s[4][4];
        #pragma unroll
        for (int nt = 0; nt < 4; nt++)
            #pragma unroll
            for (int j = 0; j < 4; j++) s[nt][j] = 0.f;

        #pragma unroll
        for (int ks = 0; ks < 4; ks++) {
            int rb = wRow + lr;
            int c  = ks * 8 + lc;
            float ah0 = Qh[rb * QSTR + c],       ah1 = Qh[(rb + 8) * QSTR + c];
            float ah2 = Qh[rb * QSTR + c + 4],   ah3 = Qh[(rb + 8) * QSTR + c + 4];
            float al0 = Ql[rb * QSTR + c],       al1 = Ql[(rb + 8) * QSTR + c];
            float al2 = Ql[rb * QSTR + c + 4],   al3 = Ql[(rb + 8) * QSTR + c + 4];
            #pragma unroll
            for (int nt = 0; nt < 4; nt++) {
                int n = nt * 8 + lr;
                float bh0 = Kh[n * KSTR + ks * 8 + lc];
                float bh1 = Kh[n * KSTR + ks * 8 + 4 + lc];
                float bl0 = Kl[n * KSTR + ks * 8 + lc];
                float bl1 = Kl[n * KSTR + ks * 8 + 4 + lc];
                mma_tf32(s[nt], ah0, ah1, ah2, ah3, bh0, bh1);
                mma_tf32(s[nt], ah0, ah1, ah2, ah3, bl0, bl1);
                mma_tf32(s[nt], al0, al1, al2, al3, bh0, bh1);
            }
        }

        // online softmax: row0 = wRow+lr holds s[nt][0..1]; row1 = +8 holds s[nt][2..3]
        float mx0 = m0, mx1 = m1;
        #pragma unroll
        for (int nt = 0; nt < 4; nt++) {
            mx0 = fmaxf(mx0, fmaxf(s[nt][0], s[nt][1]));
            mx1 = fmaxf(mx1, fmaxf(s[nt][2], s[nt][3]));
        }
        mx0 = fmaxf(mx0, __shfl_xor_sync(0xffffffff, mx0, 1));
        mx0 = fmaxf(mx0, __shfl_xor_sync(0xffffffff, mx0, 2));
        mx1 = fmaxf(mx1, __shfl_xor_sync(0xffffffff, mx1, 1));
        mx1 = fmaxf(mx1, __shfl_xor_sync(0xffffffff, mx1, 2));

        float alpha0 = __expf(m0 - mx0);
        float alpha1 = __expf(m1 - mx1);
        float sum0 = 0.f, sum1 = 0.f;
        #pragma unroll
        for (int nt = 0; nt < 4; nt++) {
            float p00 = __expf(s[nt][0] - mx0);
            float p01 = __expf(s[nt][1] - mx0);
            float p10 = __expf(s[nt][2] - mx1);
            float p11 = __expf(s[nt][3] - mx1);
            sum0 += p00 + p01;
            sum1 += p10 + p11;
            int col = nt * 8 + 2 * lc;
            *(float2*)&Ps[(wRow + lr) * PSTR + col] =
                make_float2(to_tf32(p00), to_tf32(p01));
            *(float2*)&Ps[(wRow + lr + 8) * PSTR + col] =
                make_float2(to_tf32(p10), to_tf32(p11));
        }
        sum0 += __shfl_xor_sync(0xffffffff, sum0, 1);
        sum0 += __shfl_xor_sync(0xffffffff, sum0, 2);
        sum1 += __shfl_xor_sync(0xffffffff, sum1, 1);
        sum1 += __shfl_xor_sync(0xffffffff, sum1, 2);

        l0 = l0 * alpha0 + sum0;  m0 = mx0;
        l1 = l1 * alpha1 + sum1;  m1 = mx1;

        __syncthreads();

        // rescale O and accumulate PV
        #pragma unroll
        for (int nt = 0; nt < 16; nt++) {
            O[nt][0] *= alpha0; O[nt][1] *= alpha0;
            O[nt][2] *= alpha1; O[nt][3] *= alpha1;
        }
        #pragma unroll
        for (int ks = 0; ks < 4; ks++) {
            int rb = wRow + lr;
            int c  = ks * 8 + lc;
            float a0 = Ps[rb * PSTR + c];
            float a1 = Ps[(rb + 8) * PSTR + c];
            float a2 = Ps[rb * PSTR + c + 4];
            float a3 = Ps[(rb + 8) * PSTR + c + 4];
            #pragma unroll
            for (int nt = 0; nt < 16; nt++) {
                int n = nt * 8 + lr;
                float b0 = Vs[(ks * 8 + lc) * VSTR + n];
                float b1 = Vs[(ks * 8 + 4 + lc) * VSTR + n];
                mma_tf32(O[nt], a0, a1, a2, a3, b0, b1);
            }
        }
        __syncthreads();
    }

    // epilogue
    float linv0 = 1.f / l0;
    float linv1 = 1.f / l1;
    int r0 = qb + wRow + lr;
    int r1 = r0 + 8;
    #pragma unroll
    for (int nt = 0; nt < 16; nt++) {
        int c = nt * 8 + 2 * lc;   // feature in [0,128)
        #pragma unroll
        for (int b = 0; b < 2; b++) {
            int cc = c + b;
            float v0 = O[nt][b] * linv0;
            float v1 = O[nt][2 + b] * linv1;
            if (cc < 32) {
                out_v[(size_t)r0 * EE + hof + cc] = v0;
                out_v[(size_t)r1 * EE + hof + cc] = v1;
            } else {
                int ch = (cc - 32) >> 5;
                int d  = (cc - 32) & 31;
                out_g[((size_t)r0 * 3 + ch) * EE + hof + d] = v0;
                out_g[((size_t)r1 * 3 + ch) * EE + hof + d] = v1;
            }
        }
    }
}

// ---------------------------------------------------------------------------
// Host orchestration
// ---------------------------------------------------------------------------
static void gemm_f32(const float* A, int lda, const float* B, int ldb,
                     const float* bias, const float* Res, float resScale,
                     float alpha, float* C, int ldc, int M, int Nd, int K, bool relu)
{
    dim3 g((Nd + 63) / 64, M / 64), b(256);
    if (relu)
        sgemm_kernel<true><<<g, b>>>(A, lda, B, ldb, bias, Res, resScale, alpha, C, ldc, M, Nd, K);
    else
        sgemm_kernel<false><<<g, b>>>(A, lda, B, ldb, bias, Res, resScale, alpha, C, ldc, M, Nd, K);
}

static void gemm_tf32(const float* A, int lda, const float* B, int ldb,
                      const float* bias, const float* Res, float resScale,
                      float alpha, float* C, int ldc, int M, int Nd, int K, bool relu)
{
    dim3 g(Nd / 128, M / 128), b(256);
    if (relu)
        tf32_gemm<true><<<g, b>>>(A, lda, B, ldb, bias, Res, resScale, alpha, C, ldc, M, Nd, K);
    else
        tf32_gemm<false><<<g, b>>>(A, lda, B, ldb, bias, Res, resScale, alpha, C, ldc, M, Nd, K);
}

extern "C" void kernel_launch(void* const* d_in, const int* in_sizes, int n_in,
                              void* d_out, int out_size)
{
    const float* equ    = (const float*)d_in[0];
    const float* h      = (const float*)d_in[1];
    const float* W_equ  = (const float*)d_in[4];
    const float* W_gproj= (const float*)d_in[5];
    const float* W_vg   = (const float*)d_in[6];
    const float* W_g1   = (const float*)d_in[7];
    const float* b_g1   = (const float*)d_in[8];
    const float* W_g2   = (const float*)d_in[9];
    const float* b_g2   = (const float*)d_in[10];
    const float* W_q    = (const float*)d_in[11];
    const float* b_q    = (const float*)d_in[12];
    const float* W_k    = (const float*)d_in[13];
    const float* b_k    = (const float*)d_in[14];
    const float* W_v    = (const float*)d_in[15];
    const float* b_v    = (const float*)d_in[16];
    const float* W_ng   = (const float*)d_in[17];
    const float* b_ng   = (const float*)d_in[18];
    const float* W_gout = (const float*)d_in[19];
    const float* W_gdec = (const float*)d_in[20];
    const float* W_hdec = (const float*)d_in[21];
    const float* b_hdec = (const float*)d_in[22];

    float* out = (float*)d_out;

    float* S = nullptr;
    cudaGetSymbolAddress((void**)&S, scratch);
    cudaFuncSetAttribute(attn_kernel, cudaFuncAttributeMaxDynamicSharedMemorySize, ATTN_SMEM);

    float* g_src = S + OFF_GSRC;
    float* g2p   = S + OFF_G2P;
    float* gram  = S + OFF_GRAM;
    float* hid   = S + OFF_HID;
    float* h2    = S + OFF_H2;
    float* qd    = S + OFF_Q;
    float* kd    = S + OFF_K;
    float* vd    = S + OFF_V;
    float* vgd   = S + OFF_VG;
    float* outv  = S + OFF_OUTV;
    float* outg  = S + OFF_OUTG;
    float* hsrc  = S + OFF_HSRC;
    float* gsf   = S + OFF_GSF;

    const float scaling = 0.17677669529663687f;

    // g_src = (equ @ W_equ) * 16   (fp32: feeds final residual directly)
    gemm_f32(equ, MMDIM, W_equ, EE, nullptr, nullptr, 0.f, 16.f, g_src, EE, ROWS, EE, MMDIM, false);
    // g2p = g_src @ W_gproj  (N=32, fp32 kernel)
    gemm_f32(g_src, EE, W_gproj, 32, nullptr, nullptr, 0.f, 1.f, g2p, 32, ROWS, 32, EE, false);
    gram_kernel<<<NN, 128>>>(g2p, gram);
    // MLP (tf32)
    gemm_tf32(gram, 1024, W_g1, 512, b_g1, nullptr, 0.f, 1.f, hid, 512, NN, 512, 1024, true);
    gemm_tf32(hid, 512, W_g2, EE, b_g2, nullptr, 0.f, 1.f, h2, 512, NN, EE, 512, false);
    h2fill_kernel<<<(NN * EE + 255) / 256, 256>>>(h, h2);
    // q,k in fp32 (logit-critical); v in tf32
    gemm_f32(h2, 512, W_q, EE, b_q, nullptr, 0.f, scaling, qd, EE, NN, EE, 512, false);
    gemm_f32(h2, 512, W_k, EE, b_k, nullptr, 0.f, 1.f, kd, EE, NN, EE, 512, false);
    gemm_tf32(h2, 512, W_v, EE, b_v, nullptr, 0.f, 1.f, vd, EE, NN, EE, 512, false);
    // vg (tf32)
    gemm_tf32(g_src, EE, W_vg, EE, nullptr, nullptr, 0.f, 1.f, vgd, EE, ROWS, EE, EE, false);

    // attention
    attn_kernel<<<dim3(NN / AQ, HH), 256, ATTN_SMEM>>>(qd, kd, vd, vgd, outv, outg);

    // h_src = out_v @ W_ng + b_ng + 16h   (tf32)
    gemm_tf32(outv, EE, W_ng, EE, b_ng, h, 16.f, 1.f, hsrc, EE, NN, EE, EE, false);
    // g_src_final = out_g @ W_gout + g_src  (tf32)
    gemm_tf32(outg, EE, W_gout, EE, nullptr, g_src, 1.f, 1.f, gsf, EE, ROWS, EE, EE, false);
    // decoders in fp32 (final outputs)
    gemm_f32(gsf, EE, W_gdec, MMDIM, nullptr, nullptr, 0.f, 1.f, out, MMDIM, ROWS, MMDIM, EE, false);
    gemm_f32(hsrc, EE, W_hdec, EE, b_hdec, nullptr, 0.f, 1.f, out + ROWS * MMDIM, EE, NN, EE, EE, false);
}

// round 3
// speedup vs baseline: 3.1677x; 1.1563x over previous
#include <cuda_runtime.h>
#include <cuda_fp16.h>
#include <math.h>

#define NN 4096
#define NV 3
#define MMDIM 16
#define EE 256
#define HH 8
#define DD 32
#define ROWS (NN*NV)

__device__ float scratch[26607616];

#define OFF_GSRC   0u
#define OFF_G2P    3145728u
#define OFF_GRAM   3538944u
#define OFF_HID    7733248u
#define OFF_H2     9830400u
#define OFF_Q      11927552u
#define OFF_K      12976128u
#define OFF_V      14024704u
#define OFF_VG     15073280u
#define OFF_OUTV   18219008u
#define OFF_OUTG   19267584u
#define OFF_HSRC   22413312u
#define OFF_GSF    23461888u

// ---------------------------------------------------------------------------
// helpers
// ---------------------------------------------------------------------------
__device__ __forceinline__ float to_tf32(float x) {
    unsigned u;
    asm("cvt.rna.tf32.f32 %0, %1;" : "=r"(u) : "f"(x));
    return __uint_as_float(u);
}

__device__ __forceinline__ void mma_tf32(float c[4],
                                         float a0, float a1, float a2, float a3,
                                         float b0, float b1) {
    unsigned A0 = __float_as_uint(a0), A1 = __float_as_uint(a1);
    unsigned A2 = __float_as_uint(a2), A3 = __float_as_uint(a3);
    unsigned B0 = __float_as_uint(b0), B1 = __float_as_uint(b1);
    asm volatile(
        "mma.sync.aligned.m16n8k8.row.col.f32.tf32.tf32.f32 "
        "{%0,%1,%2,%3}, {%4,%5,%6,%7}, {%8,%9}, {%0,%1,%2,%3};"
        : "+f"(c[0]), "+f"(c[1]), "+f"(c[2]), "+f"(c[3])
        : "r"(A0), "r"(A1), "r"(A2), "r"(A3), "r"(B0), "r"(B1));
}

__device__ __forceinline__ void mma_f16(float c[4],
                                        unsigned a0, unsigned a1, unsigned a2, unsigned a3,
                                        unsigned b0, unsigned b1) {
    asm volatile(
        "mma.sync.aligned.m16n8k16.row.col.f32.f16.f16.f32 "
        "{%0,%1,%2,%3}, {%4,%5,%6,%7}, {%8,%9}, {%0,%1,%2,%3};"
        : "+f"(c[0]), "+f"(c[1]), "+f"(c[2]), "+f"(c[3])
        : "r"(a0), "r"(a1), "r"(a2), "r"(a3), "r"(b0), "r"(b1));
}

__device__ __forceinline__ unsigned h2pack(float a, float b) {
    __half2 h = __floats2half2_rn(a, b);
    return *(unsigned*)&h;
}

__device__ __forceinline__ void cp_async16(void* smem, const void* gmem) {
    unsigned s = (unsigned)__cvta_generic_to_shared(smem);
    asm volatile("cp.async.cg.shared.global [%0], [%1], 16;" :: "r"(s), "l"(gmem));
}
#define CP_COMMIT() asm volatile("cp.async.commit_group;")
#define CP_WAIT(n)  asm volatile("cp.async.wait_group %0;" :: "n"(n))

// ---------------------------------------------------------------------------
// fp32 SGEMM (small / odd-shaped GEMMs)
// ---------------------------------------------------------------------------
template<bool RELU>
__global__ __launch_bounds__(256)
void sgemm_kernel(const float* __restrict__ A, int lda,
                  const float* __restrict__ B, int ldb,
                  const float* __restrict__ bias,
                  const float* __restrict__ Res, float resScale,
                  float alpha,
                  float* __restrict__ C, int ldc,
                  int M, int Nd, int K)
{
    __shared__ float As[16 * 68];
    __shared__ float Bs[16 * 64];

    const int tid = threadIdx.x;
    const int tx  = tid & 15;
    const int ty  = tid >> 4;
    const int bm  = blockIdx.y * 64;
    const int bn  = blockIdx.x * 64;

    float acc[4][4] = {};

    for (int k0 = 0; k0 < K; k0 += 16) {
        #pragma unroll
        for (int i = 0; i < 4; i++) {
            int idx = tid + i * 256;
            int m_  = idx >> 4;
            int kk  = idx & 15;
            As[kk * 68 + m_] = A[(size_t)(bm + m_) * lda + k0 + kk];
        }
        #pragma unroll
        for (int i = 0; i < 4; i++) {
            int idx = tid + i * 256;
            int kk  = idx >> 6;
            int nn  = idx & 63;
            int gn  = bn + nn;
            Bs[kk * 64 + nn] = (gn < Nd) ? B[(size_t)(k0 + kk) * ldb + gn] : 0.f;
        }
        __syncthreads();

        #pragma unroll
        for (int kk = 0; kk < 16; kk++) {
            float4 a4 = *(const float4*)&As[kk * 68 + ty * 4];
            float4 b4 = *(const float4*)&Bs[kk * 64 + tx * 4];
            float a_[4] = {a4.x, a4.y, a4.z, a4.w};
            float b_[4] = {b4.x, b4.y, b4.z, b4.w};
            #pragma unroll
            for (int i = 0; i < 4; i++)
                #pragma unroll
                for (int j = 0; j < 4; j++)
                    acc[i][j] = fmaf(a_[i], b_[j], acc[i][j]);
        }
        __syncthreads();
    }

    #pragma unroll
    for (int i = 0; i < 4; i++) {
        int gm = bm + ty * 4 + i;
        #pragma unroll
        for (int j = 0; j < 4; j++) {
            int gn = bn + tx * 4 + j;
            if (gn < Nd) {
                float v = acc[i][j];
                if (bias) v += bias[gn];
                v *= alpha;
                if (Res) v = fmaf(resScale, Res[(size_t)gm * ldc + gn], v);
                if (RELU) v = fmaxf(v, 0.f);
                C[(size_t)gm * ldc + gn] = v;
            }
        }
    }
}

// ---------------------------------------------------------------------------
// TF32 GEMM, double-buffered cp.async, NPASS=1 (single) or 3 (tf32x3).
// Block 128x128, BK=16, 8 warps, warp tile 64x32. M%128==0, Nd%128==0, K%16==0.
// Raw fp32 staged in smem; tf32 conversion / hi-lo split at fragment read.
// ---------------------------------------------------------------------------
#define GA_STR 20
#define GB_STR 136

template<int NPASS, bool RELU>
__global__ __launch_bounds__(256)
void tf32_gemm(const float* __restrict__ A, int lda,
               const float* __restrict__ B, int ldb,
               const float* __restrict__ bias,
               const float* __restrict__ Res, float resScale, float alpha,
               float* __restrict__ C, int ldc,
               int M, int Nd, int K)
{
    __shared__ float As[2][128 * GA_STR];
    __shared__ float Bs[2][16 * GB_STR];

    const int tid  = threadIdx.x;
    const int lane = tid & 31;
    const int warp = tid >> 5;
    const int bm   = blockIdx.y * 128;
    const int bn   = blockIdx.x * 128;
    const int wM   = (warp >> 2) * 64;
    const int wN   = (warp & 3) * 32;
    const int lr   = lane >> 2;
    const int lc   = lane & 3;

    float acc[4][4][4];
    #pragma unroll
    for (int i = 0; i < 4; i++)
        #pragma unroll
        for (int j = 0; j < 4; j++)
            #pragma unroll
            for (int v = 0; v < 4; v++) acc[i][j][v] = 0.f;

    const int KT = K / 16;

    // stage 0
    {
        #pragma unroll
        for (int i = 0; i < 2; i++) {
            int idx = tid + i * 256;
            int row = idx >> 2, seg = idx & 3;
            cp_async16(&As[0][row * GA_STR + seg * 4], &A[(size_t)(bm + row) * lda + seg * 4]);
        }
        #pragma unroll
        for (int i = 0; i < 2; i++) {
            int idx = tid + i * 256;
            int row = idx >> 5, seg = idx & 31;
            cp_async16(&Bs[0][row * GB_STR + seg * 4], &B[(size_t)row * ldb + bn + seg * 4]);
        }
        CP_COMMIT();
    }

    for (int kt = 0; kt < KT; kt++) {
        if (kt + 1 < KT) {
            int k0 = (kt + 1) * 16;
            int nb = (kt + 1) & 1;
            #pragma unroll
            for (int i = 0; i < 2; i++) {
                int idx = tid + i * 256;
                int row = idx >> 2, seg = idx & 3;
                cp_async16(&As[nb][row * GA_STR + seg * 4],
                           &A[(size_t)(bm + row) * lda + k0 + seg * 4]);
            }
            #pragma unroll
            for (int i = 0; i < 2; i++) {
                int idx = tid + i * 256;
                int row = idx >> 5, seg = idx & 31;
                cp_async16(&Bs[nb][row * GB_STR + seg * 4],
                           &B[(size_t)(k0 + row) * ldb + bn + seg * 4]);
            }
            CP_COMMIT();
            CP_WAIT(1);
        } else {
            CP_WAIT(0);
        }
        __syncthreads();

        const float* Ac = As[kt & 1];
        const float* Bc = Bs[kt & 1];

        #pragma unroll
        for (int ks = 0; ks < 2; ks++) {
            float afh[4][4], afl[4][4];
            #pragma unroll
            for (int mt = 0; mt < 4; mt++) {
                int rb = wM + mt * 16 + lr;
                int c  = ks * 8 + lc;
                float x0 = Ac[rb * GA_STR + c];
                float x1 = Ac[(rb + 8) * GA_STR + c];
                float x2 = Ac[rb * GA_STR + c + 4];
                float x3 = Ac[(rb + 8) * GA_STR + c + 4];
                afh[mt][0] = to_tf32(x0); afh[mt][1] = to_tf32(x1);
                afh[mt][2] = to_tf32(x2); afh[mt][3] = to_tf32(x3);
                if (NPASS == 3) {
                    afl[mt][0] = to_tf32(x0 - afh[mt][0]);
                    afl[mt][1] = to_tf32(x1 - afh[mt][1]);
                    afl[mt][2] = to_tf32(x2 - afh[mt][2]);
                    afl[mt][3] = to_tf32(x3 - afh[mt][3]);
                }
            }
            float bfh[4][2], bfl[4][2];
            #pragma unroll
            for (int nt = 0; nt < 4; nt++) {
                int n = wN + nt * 8 + lr;
                float x0 = Bc[(ks * 8 + lc) * GB_STR + n];
                float x1 = Bc[(ks * 8 + 4 + lc) * GB_STR + n];
                bfh[nt][0] = to_tf32(x0);
                bfh[nt][1] = to_tf32(x1);
                if (NPASS == 3) {
                    bfl[nt][0] = to_tf32(x0 - bfh[nt][0]);
                    bfl[nt][1] = to_tf32(x1 - bfh[nt][1]);
                }
            }
            #pragma unroll
            for (int mt = 0; mt < 4; mt++)
                #pragma unroll
                for (int nt = 0; nt < 4; nt++) {
                    mma_tf32(acc[mt][nt], afh[mt][0], afh[mt][1], afh[mt][2], afh[mt][3],
                             bfh[nt][0], bfh[nt][1]);
                    if (NPASS == 3) {
                        mma_tf32(acc[mt][nt], afh[mt][0], afh[mt][1], afh[mt][2], afh[mt][3],
                                 bfl[nt][0], bfl[nt][1]);
                        mma_tf32(acc[mt][nt], afl[mt][0], afl[mt][1], afl[mt][2], afl[mt][3],
                                 bfh[nt][0], bfh[nt][1]);
                    }
                }
        }
        __syncthreads();
    }

    #pragma unroll
    for (int mt = 0; mt < 4; mt++) {
        #pragma unroll
        for (int nt = 0; nt < 4; nt++) {
            int col = bn + wN + nt * 8 + 2 * lc;
            #pragma unroll
            for (int half = 0; half < 2; half++) {
                int r = bm + wM + mt * 16 + lr + half * 8;
                float v0 = acc[mt][nt][half * 2 + 0];
                float v1 = acc[mt][nt][half * 2 + 1];
                if (bias) { v0 += bias[col]; v1 += bias[col + 1]; }
                v0 *= alpha; v1 *= alpha;
                if (Res) {
                    v0 = fmaf(resScale, Res[(size_t)r * ldc + col], v0);
                    v1 = fmaf(resScale, Res[(size_t)r * ldc + col + 1], v1);
                }
                if (RELU) { v0 = fmaxf(v0, 0.f); v1 = fmaxf(v1, 0.f); }
                *(float2*)&C[(size_t)r * ldc + col] = make_float2(v0, v1);
            }
        }
    }
}

// ---------------------------------------------------------------------------
// Gram + h2 fill
// ---------------------------------------------------------------------------
__global__ void gram_kernel(const float* __restrict__ g2p, float* __restrict__ gram)
{
    int node = blockIdx.x;
    __shared__ float s[96];
    int tid = threadIdx.x;
    if (tid < 96) s[tid] = g2p[(size_t)node * 96 + tid];
    __syncthreads();
    #pragma unroll
    for (int o = tid; o < 1024; o += 128) {
        int a = o >> 5, b = o & 31;
        gram[(size_t)node * 1024 + o] =
            s[a] * s[b] + s[32 + a] * s[32 + b] + s[64 + a] * s[64 + b];
    }
}

__global__ void h2fill_kernel(const float* __restrict__ h, float* __restrict__ h2)
{
    int idx = blockIdx.x * blockDim.x + threadIdx.x;
    if (idx < NN * EE) {
        int r = idx >> 8, c = idx & 255;
        h2[(size_t)r * 512 + 256 + c] = 16.f * h[idx];
    }
}

// ---------------------------------------------------------------------------
// Flash attention v2: tf32x3 S (register P), fp16 PV, cp.async pipeline.
// Block = 128 q rows x head; K tiles of 64 (two 32-key sub-steps).
// 8 warps, warp owns 16 q rows. Value dim 128 = v | vg0 | vg1 | vg2.
// ---------------------------------------------------------------------------
#define AQ 128
#define AK 64
#define QSTR 36
#define KSTR 36
#define VSTR 132
#define KS_SZ (AK*KSTR)

#define SM_QH 0
#define SM_QL (SM_QH + AQ*QSTR)
#define SM_KS (SM_QL + AQ*QSTR)
#define SM_VS (SM_KS + 2*KS_SZ)
#define ATTN_SMEM_FLOATS (SM_VS + AK*VSTR)
#define ATTN_SMEM (ATTN_SMEM_FLOATS * 4)

__global__ __launch_bounds__(256, 2)
void attn_kernel(const float* __restrict__ q,
                 const float* __restrict__ k,
                 const float* __restrict__ v,
                 const float* __restrict__ vg,
                 float* __restrict__ out_v,
                 float* __restrict__ out_g)
{
    extern __shared__ float sm[];
    float* Qh = sm + SM_QH;
    float* Ql = sm + SM_QL;
    float* Ks = sm + SM_KS;
    float* Vs = sm + SM_VS;

    const int head = blockIdx.y;
    const int qb   = blockIdx.x * AQ;
    const int tid  = threadIdx.x;
    const int lane = tid & 31;
    const int warp = tid >> 5;
    const int hof  = head * DD;
    const int lr   = lane >> 2;
    const int lc   = lane & 3;
    const int wRow = warp * 16;

    // prologue: issue K(0) loads
    #pragma unroll
    for (int i = 0; i < 2; i++) {
        int idx = tid + i * 256;
        int key = idx >> 3, seg = idx & 7;
        cp_async16(&Ks[key * KSTR + seg * 4], &k[(size_t)key * EE + hof + seg * 4]);
    }
    CP_COMMIT();

    // load Q tile, split hi/lo (synchronous)
    #pragma unroll
    for (int i = 0; i < 4; i++) {
        int idx = tid + i * 256;
        int row = idx >> 3, seg = idx & 7;
        float4 x = *(const float4*)&q[(size_t)(qb + row) * EE + hof + seg * 4];
        float4 hi, lo;
        hi.x = to_tf32(x.x); lo.x = to_tf32(x.x - hi.x);
        hi.y = to_tf32(x.y); lo.y = to_tf32(x.y - hi.y);
        hi.z = to_tf32(x.z); lo.z = to_tf32(x.z - hi.z);
        hi.w = to_tf32(x.w); lo.w = to_tf32(x.w - hi.w);
        *(float4*)&Qh[row * QSTR + seg * 4] = hi;
        *(float4*)&Ql[row * QSTR + seg * 4] = lo;
    }

    float O[16][4];
    #pragma unroll
    for (int nt = 0; nt < 16; nt++)
        #pragma unroll
        for (int j = 0; j < 4; j++) O[nt][j] = 0.f;
    float m0 = -1e30f, m1 = -1e30f, l0 = 0.f, l1 = 0.f;

    for (int t = 0; t < NN / AK; t++) {
        const int kb = t * AK;
        __syncthreads();   // protect Vs / K-alt buffer from prior readers

        // issue V(t)
        #pragma unroll
        for (int i = 0; i < 8; i++) {
            int idx = tid + i * 256;
            int key = idx >> 5, c4 = idx & 31;
            int chunk = c4 >> 3, w = c4 & 7;
            const float* src = (chunk == 0)
                ? &v[(size_t)(kb + key) * EE + hof + w * 4]
                : &vg[((size_t)(kb + key) * 3 + (chunk - 1)) * EE + hof + w * 4];
            cp_async16(&Vs[key * VSTR + c4 * 4], src);
        }
        CP_COMMIT();

        const bool hasNext = (t + 1 < NN / AK);
        if (hasNext) {
            float* Kd = Ks + ((t + 1) & 1) * KS_SZ;
            #pragma unroll
            for (int i = 0; i < 2; i++) {
                int idx = tid + i * 256;
                int key = idx >> 3, seg = idx & 7;
                cp_async16(&Kd[key * KSTR + seg * 4],
                           &k[(size_t)(kb + AK + key) * EE + hof + seg * 4]);
            }
            CP_COMMIT();
            CP_WAIT(2);   // K(t) complete
        } else {
            CP_WAIT(1);   // K(t) complete
        }
        __syncthreads();

        const float* Kc = Ks + (t & 1) * KS_SZ;

        #pragma unroll
        for (int half = 0; half < 2; half++) {
            // ---- S = Q K^T (tf32x3) for 32 keys ----
            float s[4][4];
            #pragma unroll
            for (int nt = 0; nt < 4; nt++)
                #pragma unroll
                for (int j = 0; j < 4; j++) s[nt][j] = 0.f;

            #pragma unroll
            for (int ks = 0; ks < 4; ks++) {
                int rb = wRow + lr, c = ks * 8 + lc;
                float ah0 = Qh[rb * QSTR + c],     ah1 = Qh[(rb + 8) * QSTR + c];
                float ah2 = Qh[rb * QSTR + c + 4], ah3 = Qh[(rb + 8) * QSTR + c + 4];
                float al0 = Ql[rb * QSTR + c],     al1 = Ql[(rb + 8) * QSTR + c];
                float al2 = Ql[rb * QSTR + c + 4], al3 = Ql[(rb + 8) * QSTR + c + 4];
                #pragma unroll
                for (int nt = 0; nt < 4; nt++) {
                    int key = half * 32 + nt * 8 + lr;
                    float x0 = Kc[key * KSTR + ks * 8 + lc];
                    float x1 = Kc[key * KSTR + ks * 8 + 4 + lc];
                    float bh0 = to_tf32(x0), bl0 = to_tf32(x0 - bh0);
                    float bh1 = to_tf32(x1), bl1 = to_tf32(x1 - bh1);
                    mma_tf32(s[nt], ah0, ah1, ah2, ah3, bh0, bh1);
                    mma_tf32(s[nt], ah0, ah1, ah2, ah3, bl0, bl1);
                    mma_tf32(s[nt], al0, al1, al2, al3, bh0, bh1);
                }
            }

            // ---- online softmax ----
            float mx0 = m0, mx1 = m1;
            #pragma unroll
            for (int nt = 0; nt < 4; nt++) {
                mx0 = fmaxf(mx0, fmaxf(s[nt][0], s[nt][1]));
                mx1 = fmaxf(mx1, fmaxf(s[nt][2], s[nt][3]));
            }
            mx0 = fmaxf(mx0, __shfl_xor_sync(0xffffffff, mx0, 1));
            mx0 = fmaxf(mx0, __shfl_xor_sync(0xffffffff, mx0, 2));
            mx1 = fmaxf(mx1, __shfl_xor_sync(0xffffffff, mx1, 1));
            mx1 = fmaxf(mx1, __shfl_xor_sync(0xffffffff, mx1, 2));

            float alpha0 = __expf(m0 - mx0);
            float alpha1 = __expf(m1 - mx1);
            float sum0 = 0.f, sum1 = 0.f;
            #pragma unroll
            for (int nt = 0; nt < 4; nt++) {
                s[nt][0] = __expf(s[nt][0] - mx0);
                s[nt][1] = __expf(s[nt][1] - mx0);
                s[nt][2] = __expf(s[nt][2] - mx1);
                s[nt][3] = __expf(s[nt][3] - mx1);
                sum0 += s[nt][0] + s[nt][1];
                sum1 += s[nt][2] + s[nt][3];
            }
            sum0 += __shfl_xor_sync(0xffffffff, sum0, 1);
            sum0 += __shfl_xor_sync(0xffffffff, sum0, 2);
            sum1 += __shfl_xor_sync(0xffffffff, sum1, 1);
            sum1 += __shfl_xor_sync(0xffffffff, sum1, 2);
            l0 = l0 * alpha0 + sum0;  m0 = mx0;
            l1 = l1 * alpha1 + sum1;  m1 = mx1;

            // pack P fragments (register-only; C-layout == A-layout pairing)
            unsigned pa[2][4];
            #pragma unroll
            for (int t16 = 0; t16 < 2; t16++) {
                pa[t16][0] = h2pack(s[2 * t16][0],     s[2 * t16][1]);
                pa[t16][1] = h2pack(s[2 * t16][2],     s[2 * t16][3]);
                pa[t16][2] = h2pack(s[2 * t16 + 1][0], s[2 * t16 + 1][1]);
                pa[t16][3] = h2pack(s[2 * t16 + 1][2], s[2 * t16 + 1][3]);
            }

            // rescale O
            #pragma unroll
            for (int nt = 0; nt < 16; nt++) {
                O[nt][0] *= alpha0; O[nt][1] *= alpha0;
                O[nt][2] *= alpha1; O[nt][3] *= alpha1;
            }

            // V must be resident before first PV
            if (half == 0) {
                if (hasNext) { CP_WAIT(1); } else { CP_WAIT(0); }
                __syncthreads();
            }

            // ---- PV (fp16 m16n8k16) ----
            #pragma unroll
            for (int t16 = 0; t16 < 2; t16++) {
                int kb16 = half * 32 + t16 * 16;
                #pragma unroll
                for (int nt = 0; nt < 16; nt++) {
                    int n = nt * 8 + lr;
                    float x0 = Vs[(kb16 + 2 * lc) * VSTR + n];
                    float x1 = Vs[(kb16 + 2 * lc + 1) * VSTR + n];
                    float x2 = Vs[(kb16 + 2 * lc + 8) * VSTR + n];
                    float x3 = Vs[(kb16 + 2 * lc + 9) * VSTR + n];
                    unsigned b0 = h2pack(x0, x1);
                    unsigned b1 = h2pack(x2, x3);
                    mma_f16(O[nt], pa[t16][0], pa[t16][1], pa[t16][2], pa[t16][3], b0, b1);
                }
            }
        }
    }

    // epilogue
    float linv0 = 1.f / l0;
    float linv1 = 1.f / l1;
    int r0 = qb + wRow + lr;
    int r1 = r0 + 8;
    #pragma unroll
    for (int nt = 0; nt < 16; nt++) {
        int c = nt * 8 + 2 * lc;
        #pragma unroll
        for (int b = 0; b < 2; b++) {
            int cc = c + b;
            float v0 = O[nt][b] * linv0;
            float v1 = O[nt][2 + b] * linv1;
            if (cc < 32) {
                out_v[(size_t)r0 * EE + hof + cc] = v0;
                out_v[(size_t)r1 * EE + hof + cc] = v1;
            } else {
                int ch = (cc - 32) >> 5;
                int d  = (cc - 32) & 31;
                out_g[((size_t)r0 * 3 + ch) * EE + hof + d] = v0;
                out_g[((size_t)r1 * 3 + ch) * EE + hof + d] = v1;
            }
        }
    }
}

// ---------------------------------------------------------------------------
// Host orchestration
// ---------------------------------------------------------------------------
static void gemm_f32(const float* A, int lda, const float* B, int ldb,
                     const float* bias, const float* Res, float resScale,
                     float alpha, float* C, int ldc, int M, int Nd, int K, bool relu)
{
    dim3 g((Nd + 63) / 64, M / 64), b(256);
    if (relu)
        sgemm_kernel<true><<<g, b>>>(A, lda, B, ldb, bias, Res, resScale, alpha, C, ldc, M, Nd, K);
    else
        sgemm_kernel<false><<<g, b>>>(A, lda, B, ldb, bias, Res, resScale, alpha, C, ldc, M, Nd, K);
}

template<int NPASS>
static void gemm_tf32(const float* A, int lda, const float* B, int ldb,
                      const float* bias, const float* Res, float resScale,
                      float alpha, float* C, int ldc, int M, int Nd, int K, bool relu)
{
    dim3 g(Nd / 128, M / 128), b(256);
    if (relu)
        tf32_gemm<NPASS, true><<<g, b>>>(A, lda, B, ldb, bias, Res, resScale, alpha, C, ldc, M, Nd, K);
    else
        tf32_gemm<NPASS, false><<<g, b>>>(A, lda, B, ldb, bias, Res, resScale, alpha, C, ldc, M, Nd, K);
}

extern "C" void kernel_launch(void* const* d_in, const int* in_sizes, int n_in,
                              void* d_out, int out_size)
{
    const float* equ    = (const float*)d_in[0];
    const float* h      = (const float*)d_in[1];
    const float* W_equ  = (const float*)d_in[4];
    const float* W_gproj= (const float*)d_in[5];
    const float* W_vg   = (const float*)d_in[6];
    const float* W_g1   = (const float*)d_in[7];
    const float* b_g1   = (const float*)d_in[8];
    const float* W_g2   = (const float*)d_in[9];
    const float* b_g2   = (const float*)d_in[10];
    const float* W_q    = (const float*)d_in[11];
    const float* b_q    = (const float*)d_in[12];
    const float* W_k    = (const float*)d_in[13];
    const float* b_k    = (const float*)d_in[14];
    const float* W_v    = (const float*)d_in[15];
    const float* b_v    = (const float*)d_in[16];
    const float* W_ng   = (const float*)d_in[17];
    const float* b_ng   = (const float*)d_in[18];
    const float* W_gout = (const float*)d_in[19];
    const float* W_gdec = (const float*)d_in[20];
    const float* W_hdec = (const float*)d_in[21];
    const float* b_hdec = (const float*)d_in[22];

    float* out = (float*)d_out;

    float* S = nullptr;
    cudaGetSymbolAddress((void**)&S, scratch);
    cudaFuncSetAttribute(attn_kernel, cudaFuncAttributeMaxDynamicSharedMemorySize, ATTN_SMEM);

    float* g_src = S + OFF_GSRC;
    float* g2p   = S + OFF_G2P;
    float* gram  = S + OFF_GRAM;
    float* hid   = S + OFF_HID;
    float* h2    = S + OFF_H2;
    float* qd    = S + OFF_Q;
    float* kd    = S + OFF_K;
    float* vd    = S + OFF_V;
    float* vgd   = S + OFF_VG;
    float* outv  = S + OFF_OUTV;
    float* outg  = S + OFF_OUTG;
    float* hsrc  = S + OFF_HSRC;
    float* gsf   = S + OFF_GSF;

    const float scaling = 0.17677669529663687f;

    // g_src = (equ @ W_equ) * 16   (fp32, K=16 memory-bound)
    gemm_f32(equ, MMDIM, W_equ, EE, nullptr, nullptr, 0.f, 16.f, g_src, EE, ROWS, EE, MMDIM, false);
    // g2p = g_src @ W_gproj (N=32)
    gemm_f32(g_src, EE, W_gproj, 32, nullptr, nullptr, 0.f, 1.f, g2p, 32, ROWS, 32, EE, false);
    gram_kernel<<<NN, 128>>>(g2p, gram);
    // MLP (tf32)
    gemm_tf32<1>(gram, 1024, W_g1, 512, b_g1, nullptr, 0.f, 1.f, hid, 512, NN, 512, 1024, true);
    gemm_tf32<1>(hid, 512, W_g2, EE, b_g2, nullptr, 0.f, 1.f, h2, 512, NN, EE, 512, false);
    h2fill_kernel<<<(NN * EE + 255) / 256, 256>>>(h, h2);
    // q,k tf32x3 (logit-critical); v tf32
    gemm_tf32<3>(h2, 512, W_q, EE, b_q, nullptr, 0.f, scaling, qd, EE, NN, EE, 512, false);
    gemm_tf32<3>(h2, 512, W_k, EE, b_k, nullptr, 0.f, 1.f, kd, EE, NN, EE, 512, false);
    gemm_tf32<1>(h2, 512, W_v, EE, b_v, nullptr, 0.f, 1.f, vd, EE, NN, EE, 512, false);
    // vg (tf32)
    gemm_tf32<1>(g_src, EE, W_vg, EE, nullptr, nullptr, 0.f, 1.f, vgd, EE, ROWS, EE, EE, false);

    // attention
    attn_kernel<<<dim3(NN / AQ, HH), 256, ATTN_SMEM>>>(qd, kd, vd, vgd, outv, outg);

    // h_src = out_v @ W_ng + b_ng + 16h (tf32)
    gemm_tf32<1>(outv, EE, W_ng, EE, b_ng, h, 16.f, 1.f, hsrc, EE, NN, EE, EE, false);
    // g_src_final = out_g @ W_gout + g_src (tf32)
    gemm_tf32<1>(outg, EE, W_gout, EE, nullptr, g_src, 1.f, 1.f, gsf, EE, ROWS, EE, EE, false);
    // decoders: gdec fp32 (N=16), hdec tf32x3 (final output, accurate)
    gemm_f32(gsf, EE, W_gdec, MMDIM, nullptr, nullptr, 0.f, 1.f, out, MMDIM, ROWS, MMDIM, EE, false);
    gemm_tf32<3>(hsrc, EE, W_hdec, EE, b_hdec, nullptr, 0.f, 1.f, out + ROWS * MMDIM, EE, NN, EE, EE, false);
}

// round 4
// speedup vs baseline: 3.7956x; 1.1982x over previous
#include <cuda_runtime.h>
#include <cuda_fp16.h>
#include <math.h>

#define NN 4096
#define NV 3
#define MMDIM 16
#define EE 256
#define HH 8
#define DD 32
#define ROWS (NN*NV)

__device__ float scratch[26607616];

#define OFF_GSRC   0u
#define OFF_G2P    3145728u
#define OFF_GRAM   3538944u
#define OFF_HID    7733248u
#define OFF_H2     9830400u
#define OFF_Q      11927552u
#define OFF_K      12976128u
#define OFF_V      14024704u
#define OFF_VG     15073280u
#define OFF_OUTV   18219008u
#define OFF_OUTG   19267584u
#define OFF_HSRC   22413312u
#define OFF_GSF    23461888u

// ---------------------------------------------------------------------------
// helpers
// ---------------------------------------------------------------------------
__device__ __forceinline__ float to_tf32(float x) {
    unsigned u;
    asm("cvt.rna.tf32.f32 %0, %1;" : "=r"(u) : "f"(x));
    return __uint_as_float(u);
}

__device__ __forceinline__ void mma_tf32(float c[4],
                                         float a0, float a1, float a2, float a3,
                                         float b0, float b1) {
    unsigned A0 = __float_as_uint(a0), A1 = __float_as_uint(a1);
    unsigned A2 = __float_as_uint(a2), A3 = __float_as_uint(a3);
    unsigned B0 = __float_as_uint(b0), B1 = __float_as_uint(b1);
    asm volatile(
        "mma.sync.aligned.m16n8k8.row.col.f32.tf32.tf32.f32 "
        "{%0,%1,%2,%3}, {%4,%5,%6,%7}, {%8,%9}, {%0,%1,%2,%3};"
        : "+f"(c[0]), "+f"(c[1]), "+f"(c[2]), "+f"(c[3])
        : "r"(A0), "r"(A1), "r"(A2), "r"(A3), "r"(B0), "r"(B1));
}

__device__ __forceinline__ void mma_f16(float c[4],
                                        unsigned a0, unsigned a1, unsigned a2, unsigned a3,
                                        unsigned b0, unsigned b1) {
    asm volatile(
        "mma.sync.aligned.m16n8k16.row.col.f32.f16.f16.f32 "
        "{%0,%1,%2,%3}, {%4,%5,%6,%7}, {%8,%9}, {%0,%1,%2,%3};"
        : "+f"(c[0]), "+f"(c[1]), "+f"(c[2]), "+f"(c[3])
        : "r"(a0), "r"(a1), "r"(a2), "r"(a3), "r"(b0), "r"(b1));
}

__device__ __forceinline__ unsigned h2pack(float a, float b) {
    __half2 h = __floats2half2_rn(a, b);
    return *(unsigned*)&h;
}

__device__ __forceinline__ void cp_async16(void* smem, const void* gmem) {
    unsigned s = (unsigned)__cvta_generic_to_shared(smem);
    asm volatile("cp.async.cg.shared.global [%0], [%1], 16;" :: "r"(s), "l"(gmem));
}
#define CP_COMMIT() asm volatile("cp.async.commit_group;")
#define CP_WAIT(n)  asm volatile("cp.async.wait_group %0;" :: "n"(n))

// ---------------------------------------------------------------------------
// fp32 SGEMM (small / odd-shaped GEMMs)
// ---------------------------------------------------------------------------
template<bool RELU>
__global__ __launch_bounds__(256)
void sgemm_kernel(const float* __restrict__ A, int lda,
                  const float* __restrict__ B, int ldb,
                  const float* __restrict__ bias,
                  const float* __restrict__ Res, float resScale,
                  float alpha,
                  float* __restrict__ C, int ldc,
                  int M, int Nd, int K)
{
    __shared__ float As[16 * 68];
    __shared__ float Bs[16 * 64];

    const int tid = threadIdx.x;
    const int tx  = tid & 15;
    const int ty  = tid >> 4;
    const int bm  = blockIdx.y * 64;
    const int bn  = blockIdx.x * 64;

    float acc[4][4] = {};

    for (int k0 = 0; k0 < K; k0 += 16) {
        #pragma unroll
        for (int i = 0; i < 4; i++) {
            int idx = tid + i * 256;
            int m_  = idx >> 4;
            int kk  = idx & 15;
            As[kk * 68 + m_] = A[(size_t)(bm + m_) * lda + k0 + kk];
        }
        #pragma unroll
        for (int i = 0; i < 4; i++) {
            int idx = tid + i * 256;
            int kk  = idx >> 6;
            int nn  = idx & 63;
            int gn  = bn + nn;
            Bs[kk * 64 + nn] = (gn < Nd) ? B[(size_t)(k0 + kk) * ldb + gn] : 0.f;
        }
        __syncthreads();

        #pragma unroll
        for (int kk = 0; kk < 16; kk++) {
            float4 a4 = *(const float4*)&As[kk * 68 + ty * 4];
            float4 b4 = *(const float4*)&Bs[kk * 64 + tx * 4];
            float a_[4] = {a4.x, a4.y, a4.z, a4.w};
            float b_[4] = {b4.x, b4.y, b4.z, b4.w};
            #pragma unroll
            for (int i = 0; i < 4; i++)
                #pragma unroll
                for (int j = 0; j < 4; j++)
                    acc[i][j] = fmaf(a_[i], b_[j], acc[i][j]);
        }
        __syncthreads();
    }

    #pragma unroll
    for (int i = 0; i < 4; i++) {
        int gm = bm + ty * 4 + i;
        #pragma unroll
        for (int j = 0; j < 4; j++) {
            int gn = bn + tx * 4 + j;
            if (gn < Nd) {
                float v = acc[i][j];
                if (bias) v += bias[gn];
                v *= alpha;
                if (Res) v = fmaf(resScale, Res[(size_t)gm * ldc + gn], v);
                if (RELU) v = fmaxf(v, 0.f);
                C[(size_t)gm * ldc + gn] = v;
            }
        }
    }
}

// ---------------------------------------------------------------------------
// TF32 GEMM, double-buffered cp.async, NPASS=1 or 3.
// Block 128x128, BK=16, 8 warps, warp tile 64x32.
// ---------------------------------------------------------------------------
#define GA_STR 20
#define GB_STR 136

template<int NPASS, bool RELU>
__global__ __launch_bounds__(256)
void tf32_gemm(const float* __restrict__ A, int lda,
               const float* __restrict__ B, int ldb,
               const float* __restrict__ bias,
               const float* __restrict__ Res, float resScale, float alpha,
               float* __restrict__ C, int ldc,
               int M, int Nd, int K)
{
    __shared__ float As[2][128 * GA_STR];
    __shared__ float Bs[2][16 * GB_STR];

    const int tid  = threadIdx.x;
    const int lane = tid & 31;
    const int warp = tid >> 5;
    const int bm   = blockIdx.y * 128;
    const int bn   = blockIdx.x * 128;
    const int wM   = (warp >> 2) * 64;
    const int wN   = (warp & 3) * 32;
    const int lr   = lane >> 2;
    const int lc   = lane & 3;

    float acc[4][4][4];
    #pragma unroll
    for (int i = 0; i < 4; i++)
        #pragma unroll
        for (int j = 0; j < 4; j++)
            #pragma unroll
            for (int v = 0; v < 4; v++) acc[i][j][v] = 0.f;

    const int KT = K / 16;

    {
        #pragma unroll
        for (int i = 0; i < 2; i++) {
            int idx = tid + i * 256;
            int row = idx >> 2, seg = idx & 3;
            cp_async16(&As[0][row * GA_STR + seg * 4], &A[(size_t)(bm + row) * lda + seg * 4]);
        }
        #pragma unroll
        for (int i = 0; i < 2; i++) {
            int idx = tid + i * 256;
            int row = idx >> 5, seg = idx & 31;
            cp_async16(&Bs[0][row * GB_STR + seg * 4], &B[(size_t)row * ldb + bn + seg * 4]);
        }
        CP_COMMIT();
    }

    for (int kt = 0; kt < KT; kt++) {
        if (kt + 1 < KT) {
            int k0 = (kt + 1) * 16;
            int nb = (kt + 1) & 1;
            #pragma unroll
            for (int i = 0; i < 2; i++) {
                int idx = tid + i * 256;
                int row = idx >> 2, seg = idx & 3;
                cp_async16(&As[nb][row * GA_STR + seg * 4],
                           &A[(size_t)(bm + row) * lda + k0 + seg * 4]);
            }
            #pragma unroll
            for (int i = 0; i < 2; i++) {
                int idx = tid + i * 256;
                int row = idx >> 5, seg = idx & 31;
                cp_async16(&Bs[nb][row * GB_STR + seg * 4],
                           &B[(size_t)(k0 + row) * ldb + bn + seg * 4]);
            }
            CP_COMMIT();
            CP_WAIT(1);
        } else {
            CP_WAIT(0);
        }
        __syncthreads();

        const float* Ac = As[kt & 1];
        const float* Bc = Bs[kt & 1];

        #pragma unroll
        for (int ks = 0; ks < 2; ks++) {
            float afh[4][4], afl[4][4];
            #pragma unroll
            for (int mt = 0; mt < 4; mt++) {
                int rb = wM + mt * 16 + lr;
                int c  = ks * 8 + lc;
                float x0 = Ac[rb * GA_STR + c];
                float x1 = Ac[(rb + 8) * GA_STR + c];
                float x2 = Ac[rb * GA_STR + c + 4];
                float x3 = Ac[(rb + 8) * GA_STR + c + 4];
                afh[mt][0] = to_tf32(x0); afh[mt][1] = to_tf32(x1);
                afh[mt][2] = to_tf32(x2); afh[mt][3] = to_tf32(x3);
                if (NPASS == 3) {
                    afl[mt][0] = to_tf32(x0 - afh[mt][0]);
                    afl[mt][1] = to_tf32(x1 - afh[mt][1]);
                    afl[mt][2] = to_tf32(x2 - afh[mt][2]);
                    afl[mt][3] = to_tf32(x3 - afh[mt][3]);
                }
            }
            float bfh[4][2], bfl[4][2];
            #pragma unroll
            for (int nt = 0; nt < 4; nt++) {
                int n = wN + nt * 8 + lr;
                float x0 = Bc[(ks * 8 + lc) * GB_STR + n];
                float x1 = Bc[(ks * 8 + 4 + lc) * GB_STR + n];
                bfh[nt][0] = to_tf32(x0);
                bfh[nt][1] = to_tf32(x1);
                if (NPASS == 3) {
                    bfl[nt][0] = to_tf32(x0 - bfh[nt][0]);
                    bfl[nt][1] = to_tf32(x1 - bfh[nt][1]);
                }
            }
            #pragma unroll
            for (int mt = 0; mt < 4; mt++)
                #pragma unroll
                for (int nt = 0; nt < 4; nt++) {
                    mma_tf32(acc[mt][nt], afh[mt][0], afh[mt][1], afh[mt][2], afh[mt][3],
                             bfh[nt][0], bfh[nt][1]);
                    if (NPASS == 3) {
                        mma_tf32(acc[mt][nt], afh[mt][0], afh[mt][1], afh[mt][2], afh[mt][3],
                                 bfl[nt][0], bfl[nt][1]);
                        mma_tf32(acc[mt][nt], afl[mt][0], afl[mt][1], afl[mt][2], afl[mt][3],
                                 bfh[nt][0], bfh[nt][1]);
                    }
                }
        }
        __syncthreads();
    }

    #pragma unroll
    for (int mt = 0; mt < 4; mt++) {
        #pragma unroll
        for (int nt = 0; nt < 4; nt++) {
            int col = bn + wN + nt * 8 + 2 * lc;
            #pragma unroll
            for (int half = 0; half < 2; half++) {
                int r = bm + wM + mt * 16 + lr + half * 8;
                float v0 = acc[mt][nt][half * 2 + 0];
                float v1 = acc[mt][nt][half * 2 + 1];
                if (bias) { v0 += bias[col]; v1 += bias[col + 1]; }
                v0 *= alpha; v1 *= alpha;
                if (Res) {
                    v0 = fmaf(resScale, Res[(size_t)r * ldc + col], v0);
                    v1 = fmaf(resScale, Res[(size_t)r * ldc + col + 1], v1);
                }
                if (RELU) { v0 = fmaxf(v0, 0.f); v1 = fmaxf(v1, 0.f); }
                *(float2*)&C[(size_t)r * ldc + col] = make_float2(v0, v1);
            }
        }
    }
}

// ---------------------------------------------------------------------------
// Fused QKV GEMM (tf32x3): A = h2 [4096,512]; B/bias/C selected per 256-col
// segment: seg 0 -> q (alpha=scaling), 1 -> k, 2 -> v. Grid (768/128, 4096/128).
// ---------------------------------------------------------------------------
__global__ __launch_bounds__(256)
void qkv_gemm(const float* __restrict__ A,
              const float* __restrict__ Wq, const float* __restrict__ bq,
              const float* __restrict__ Wk, const float* __restrict__ bk,
              const float* __restrict__ Wv, const float* __restrict__ bv,
              float* __restrict__ qd, float* __restrict__ kd, float* __restrict__ vd,
              float scaling)
{
    __shared__ float As[2][128 * GA_STR];
    __shared__ float Bs[2][16 * GB_STR];

    const int tid  = threadIdx.x;
    const int lane = tid & 31;
    const int warp = tid >> 5;
    const int bm   = blockIdx.y * 128;
    const int bnG  = blockIdx.x * 128;
    const int seg  = bnG >> 8;
    const int bn   = bnG & 255;
    const int lda  = 512, ldb = 256, ldc = 256;

    const float* B    = (seg == 0) ? Wq : (seg == 1) ? Wk : Wv;
    const float* bias = (seg == 0) ? bq : (seg == 1) ? bk : bv;
    float*       C    = (seg == 0) ? qd : (seg == 1) ? kd : vd;
    const float alpha = (seg == 0) ? scaling : 1.f;

    const int wM = (warp >> 2) * 64;
    const int wN = (warp & 3) * 32;
    const int lr = lane >> 2;
    const int lc = lane & 3;

    float acc[4][4][4];
    #pragma unroll
    for (int i = 0; i < 4; i++)
        #pragma unroll
        for (int j = 0; j < 4; j++)
            #pragma unroll
            for (int v = 0; v < 4; v++) acc[i][j][v] = 0.f;

    const int KT = 512 / 16;

    {
        #pragma unroll
        for (int i = 0; i < 2; i++) {
            int idx = tid + i * 256;
            int row = idx >> 2, s4 = idx & 3;
            cp_async16(&As[0][row * GA_STR + s4 * 4], &A[(size_t)(bm + row) * lda + s4 * 4]);
        }
        #pragma unroll
        for (int i = 0; i < 2; i++) {
            int idx = tid + i * 256;
            int row = idx >> 5, s4 = idx & 31;
            cp_async16(&Bs[0][row * GB_STR + s4 * 4], &B[(size_t)row * ldb + bn + s4 * 4]);
        }
        CP_COMMIT();
    }

    for (int kt = 0; kt < KT; kt++) {
        if (kt + 1 < KT) {
            int k0 = (kt + 1) * 16;
            int nb = (kt + 1) & 1;
            #pragma unroll
            for (int i = 0; i < 2; i++) {
                int idx = tid + i * 256;
                int row = idx >> 2, s4 = idx & 3;
                cp_async16(&As[nb][row * GA_STR + s4 * 4],
                           &A[(size_t)(bm + row) * lda + k0 + s4 * 4]);
            }
            #pragma unroll
            for (int i = 0; i < 2; i++) {
                int idx = tid + i * 256;
                int row = idx >> 5, s4 = idx & 31;
                cp_async16(&Bs[nb][row * GB_STR + s4 * 4],
                           &B[(size_t)(k0 + row) * ldb + bn + s4 * 4]);
            }
            CP_COMMIT();
            CP_WAIT(1);
        } else {
            CP_WAIT(0);
        }
        __syncthreads();

        const float* Ac = As[kt & 1];
        const float* Bc = Bs[kt & 1];

        #pragma unroll
        for (int ks = 0; ks < 2; ks++) {
            float afh[4][4], afl[4][4];
            #pragma unroll
            for (int mt = 0; mt < 4; mt++) {
                int rb = wM + mt * 16 + lr;
                int c  = ks * 8 + lc;
                float x0 = Ac[rb * GA_STR + c];
                float x1 = Ac[(rb + 8) * GA_STR + c];
                float x2 = Ac[rb * GA_STR + c + 4];
                float x3 = Ac[(rb + 8) * GA_STR + c + 4];
                afh[mt][0] = to_tf32(x0); afh[mt][1] = to_tf32(x1);
                afh[mt][2] = to_tf32(x2); afh[mt][3] = to_tf32(x3);
                afl[mt][0] = to_tf32(x0 - afh[mt][0]);
                afl[mt][1] = to_tf32(x1 - afh[mt][1]);
                afl[mt][2] = to_tf32(x2 - afh[mt][2]);
                afl[mt][3] = to_tf32(x3 - afh[mt][3]);
            }
            float bfh[4][2], bfl[4][2];
            #pragma unroll
            for (int nt = 0; nt < 4; nt++) {
                int n = wN + nt * 8 + lr;
                float x0 = Bc[(ks * 8 + lc) * GB_STR + n];
                float x1 = Bc[(ks * 8 + 4 + lc) * GB_STR + n];
                bfh[nt][0] = to_tf32(x0);
                bfh[nt][1] = to_tf32(x1);
                bfl[nt][0] = to_tf32(x0 - bfh[nt][0]);
                bfl[nt][1] = to_tf32(x1 - bfh[nt][1]);
            }
            #pragma unroll
            for (int mt = 0; mt < 4; mt++)
                #pragma unroll
                for (int nt = 0; nt < 4; nt++) {
                    mma_tf32(acc[mt][nt], afh[mt][0], afh[mt][1], afh[mt][2], afh[mt][3],
                             bfh[nt][0], bfh[nt][1]);
                    mma_tf32(acc[mt][nt], afh[mt][0], afh[mt][1], afh[mt][2], afh[mt][3],
                             bfl[nt][0], bfl[nt][1]);
                    mma_tf32(acc[mt][nt], afl[mt][0], afl[mt][1], afl[mt][2], afl[mt][3],
                             bfh[nt][0], bfh[nt][1]);
                }
        }
        __syncthreads();
    }

    #pragma unroll
    for (int mt = 0; mt < 4; mt++) {
        #pragma unroll
        for (int nt = 0; nt < 4; nt++) {
            int col = bn + wN + nt * 8 + 2 * lc;
            #pragma unroll
            for (int half = 0; half < 2; half++) {
                int r = bm + wM + mt * 16 + lr + half * 8;
                float v0 = acc[mt][nt][half * 2 + 0] + bias[col];
                float v1 = acc[mt][nt][half * 2 + 1] + bias[col + 1];
                v0 *= alpha; v1 *= alpha;
                *(float2*)&C[(size_t)r * ldc + col] = make_float2(v0, v1);
            }
        }
    }
}

// ---------------------------------------------------------------------------
// Gram + h2 fill
// ---------------------------------------------------------------------------
__global__ void gram_kernel(const float* __restrict__ g2p, float* __restrict__ gram)
{
    int node = blockIdx.x;
    __shared__ float s[96];
    int tid = threadIdx.x;
    if (tid < 96) s[tid] = g2p[(size_t)node * 96 + tid];
    __syncthreads();
    #pragma unroll
    for (int o = tid; o < 1024; o += 128) {
        int a = o >> 5, b = o & 31;
        gram[(size_t)node * 1024 + o] =
            s[a] * s[b] + s[32 + a] * s[32 + b] + s[64 + a] * s[64 + b];
    }
}

__global__ void h2fill_kernel(const float* __restrict__ h, float* __restrict__ h2)
{
    int idx = blockIdx.x * blockDim.x + threadIdx.x;
    if (idx < NN * EE) {
        int r = idx >> 8, c = idx & 255;
        h2[(size_t)r * 512 + 256 + c] = 16.f * h[idx];
    }
}

// ---------------------------------------------------------------------------
// Flash attention v3: fp16x3 S (packed half2 operands), fp16 PV.
// Per-tile cooperative conversion passes hoist all cvt out of MMA loops.
// Block = 128 q rows x head; K tiles of 64 (two 32-key halves).
// ---------------------------------------------------------------------------
#define AQ 128
#define AK 64
#define QP 20        // half2 row stride for Q/K packed tiles (16 + 4 pad)
#define KRSTR 36     // raw K float stride
#define VRSTR 132    // raw V float stride
#define VPSTR 136    // packed V half2 stride

// word offsets (1 word = 1 float = 1 half2)
#define SM_QHI  0
#define SM_QLO  (SM_QHI + AQ*QP)              // 2560
#define SM_KRAW (SM_QLO + AQ*QP)              // 5120 (2 buffers of 64*36)
#define SM_KHI  (SM_KRAW + 2*AK*KRSTR)        // 9728
#define SM_KLO  (SM_KHI + AK*QP)              // 11008
#define SM_VRAW (SM_KLO + AK*QP)              // 12288
#define SM_VP   (SM_VRAW + AK*VRSTR)          // 20736
#define ATTN_WORDS (SM_VP + 32*VPSTR)         // 25088
#define ATTN_SMEM (ATTN_WORDS * 4)

__global__ __launch_bounds__(256, 2)
void attn_kernel(const float* __restrict__ q,
                 const float* __restrict__ k,
                 const float* __restrict__ v,
                 const float* __restrict__ vg,
                 float* __restrict__ out_v,
                 float* __restrict__ out_g)
{
    extern __shared__ float sm[];
    unsigned* Qhi = (unsigned*)(sm + SM_QHI);   // [128][QP] half2
    unsigned* Qlo = (unsigned*)(sm + SM_QLO);
    float*    Kraw= sm + SM_KRAW;               // 2 x [64][KRSTR]
    unsigned* Khi = (unsigned*)(sm + SM_KHI);   // [64][QP] half2
    unsigned* Klo = (unsigned*)(sm + SM_KLO);
    float*    Vraw= sm + SM_VRAW;               // [64][VRSTR]
    unsigned* Vp  = (unsigned*)(sm + SM_VP);    // [32][VPSTR] half2 (k-pairs)

    const int head = blockIdx.y;
    const int qb   = blockIdx.x * AQ;
    const int tid  = threadIdx.x;
    const int lane = tid & 31;
    const int warp = tid >> 5;
    const int hof  = head * DD;
    const int lr   = lane >> 2;
    const int lc   = lane & 3;
    const int wRow = warp * 16;

    // prologue: issue K(0) raw loads
    #pragma unroll
    for (int i = 0; i < 2; i++) {
        int idx = tid + i * 256;
        int key = idx >> 3, seg = idx & 7;
        cp_async16(&Kraw[key * KRSTR + seg * 4], &k[(size_t)key * EE + hof + seg * 4]);
    }
    CP_COMMIT();

    // load Q, split hi/lo into packed half2
    #pragma unroll
    for (int i = 0; i < 4; i++) {
        int idx = tid + i * 256;
        int row = idx >> 3, seg = idx & 7;   // seg: group of 4 floats = 2 half2 (kp 2seg, 2seg+1)
        float4 x = *(const float4*)&q[(size_t)(qb + row) * EE + hof + seg * 4];
        float hx = __half2float(__float2half_rn(x.x));
        float hy = __half2float(__float2half_rn(x.y));
        float hz = __half2float(__float2half_rn(x.z));
        float hw = __half2float(__float2half_rn(x.w));
        Qhi[row * QP + 2 * seg + 0] = h2pack(hx, hy);
        Qhi[row * QP + 2 * seg + 1] = h2pack(hz, hw);
        Qlo[row * QP + 2 * seg + 0] = h2pack(x.x - hx, x.y - hy);
        Qlo[row * QP + 2 * seg + 1] = h2pack(x.z - hz, x.w - hw);
    }

    float O[16][4];
    #pragma unroll
    for (int nt = 0; nt < 16; nt++)
        #pragma unroll
        for (int j = 0; j < 4; j++) O[nt][j] = 0.f;
    float m0 = -1e30f, m1 = -1e30f, l0 = 0.f, l1 = 0.f;

    for (int t = 0; t < NN / AK; t++) {
        const int kb = t * AK;
        __syncthreads();   // prior readers of Vraw/Khi/Klo/Vp done

        // issue V(t) raw
        #pragma unroll
        for (int i = 0; i < 8; i++) {
            int idx = tid + i * 256;
            int key = idx >> 5, c4 = idx & 31;
            int chunk = c4 >> 3, w = c4 & 7;
            const float* src = (chunk == 0)
                ? &v[(size_t)(kb + key) * EE + hof + w * 4]
                : &vg[((size_t)(kb + key) * 3 + (chunk - 1)) * EE + hof + w * 4];
            cp_async16(&Vraw[key * VRSTR + c4 * 4], src);
        }
        CP_COMMIT();

        const bool hasNext = (t + 1 < NN / AK);
        if (hasNext) {
            float* Kd = Kraw + ((t + 1) & 1) * AK * KRSTR;
            #pragma unroll
            for (int i = 0; i < 2; i++) {
                int idx = tid + i * 256;
                int key = idx >> 3, seg = idx & 7;
                cp_async16(&Kd[key * KRSTR + seg * 4],
                           &k[(size_t)(kb + AK + key) * EE + hof + seg * 4]);
            }
            CP_COMMIT();
            CP_WAIT(2);   // K(t) done
        } else {
            CP_WAIT(1);
        }
        __syncthreads();

        // convert K(t): 1024 half2 pairs, 4 per thread
        {
            const float* Kc = Kraw + (t & 1) * AK * KRSTR;
            #pragma unroll
            for (int i = 0; i < 4; i++) {
                int idx = tid + i * 256;
                int key = idx >> 4, kp = idx & 15;
                float x0 = Kc[key * KRSTR + 2 * kp];
                float x1 = Kc[key * KRSTR + 2 * kp + 1];
                float h0 = __half2float(__float2half_rn(x0));
                float h1 = __half2float(__float2half_rn(x1));
                Khi[key * QP + kp] = h2pack(h0, h1);
                Klo[key * QP + kp] = h2pack(x0 - h0, x1 - h1);
            }
        }
        __syncthreads();

        #pragma unroll
        for (int half = 0; half < 2; half++) {
            // ---- S = Q K^T (fp16x3: hh + hl + lh) ----
            float s[4][4];
            #pragma unroll
            for (int nt = 0; nt < 4; nt++)
                #pragma unroll
                for (int j = 0; j < 4; j++) s[nt][j] = 0.f;

            #pragma unroll
            for (int ks = 0; ks < 2; ks++) {   // two k16 chunks cover 32 dims
                int rb = wRow + lr;
                int c  = ks * 8 + lc;
                unsigned ah0 = Qhi[rb * QP + c],       ah1 = Qhi[(rb + 8) * QP + c];
                unsigned ah2 = Qhi[rb * QP + c + 4],   ah3 = Qhi[(rb + 8) * QP + c + 4];
                unsigned al0 = Qlo[rb * QP + c],       al1 = Qlo[(rb + 8) * QP + c];
                unsigned al2 = Qlo[rb * QP + c + 4],   al3 = Qlo[(rb + 8) * QP + c + 4];
                #pragma unroll
                for (int nt = 0; nt < 4; nt++) {
                    int key = half * 32 + nt * 8 + lr;
                    unsigned bh0 = Khi[key * QP + c];
                    unsigned bh1 = Khi[key * QP + c + 4];
                    unsigned bl0 = Klo[key * QP + c];
                    unsigned bl1 = Klo[key * QP + c + 4];
                    mma_f16(s[nt], ah0, ah1, ah2, ah3, bh0, bh1);
                    mma_f16(s[nt], ah0, ah1, ah2, ah3, bl0, bl1);
                    mma_f16(s[nt], al0, al1, al2, al3, bh0, bh1);
                }
            }

            // ---- online softmax ----
            float mx0 = m0, mx1 = m1;
            #pragma unroll
            for (int nt = 0; nt < 4; nt++) {
                mx0 = fmaxf(mx0, fmaxf(s[nt][0], s[nt][1]));
                mx1 = fmaxf(mx1, fmaxf(s[nt][2], s[nt][3]));
            }
            mx0 = fmaxf(mx0, __shfl_xor_sync(0xffffffff, mx0, 1));
            mx0 = fmaxf(mx0, __shfl_xor_sync(0xffffffff, mx0, 2));
            mx1 = fmaxf(mx1, __shfl_xor_sync(0xffffffff, mx1, 1));
            mx1 = fmaxf(mx1, __shfl_xor_sync(0xffffffff, mx1, 2));

            float alpha0 = __expf(m0 - mx0);
            float alpha1 = __expf(m1 - mx1);
            float sum0 = 0.f, sum1 = 0.f;
            #pragma unroll
            for (int nt = 0; nt < 4; nt++) {
                s[nt][0] = __expf(s[nt][0] - mx0);
                s[nt][1] = __expf(s[nt][1] - mx0);
                s[nt][2] = __expf(s[nt][2] - mx1);
                s[nt][3] = __expf(s[nt][3] - mx1);
                sum0 += s[nt][0] + s[nt][1];
                sum1 += s[nt][2] + s[nt][3];
            }
            sum0 += __shfl_xor_sync(0xffffffff, sum0, 1);
            sum0 += __shfl_xor_sync(0xffffffff, sum0, 2);
            sum1 += __shfl_xor_sync(0xffffffff, sum1, 1);
            sum1 += __shfl_xor_sync(0xffffffff, sum1, 2);
            l0 = l0 * alpha0 + sum0;  m0 = mx0;
            l1 = l1 * alpha1 + sum1;  m1 = mx1;

            unsigned pa[2][4];
            #pragma unroll
            for (int t16 = 0; t16 < 2; t16++) {
                pa[t16][0] = h2pack(s[2 * t16][0],     s[2 * t16][1]);
                pa[t16][1] = h2pack(s[2 * t16][2],     s[2 * t16][3]);
                pa[t16][2] = h2pack(s[2 * t16 + 1][0], s[2 * t16 + 1][1]);
                pa[t16][3] = h2pack(s[2 * t16 + 1][2], s[2 * t16 + 1][3]);
            }

            #pragma unroll
            for (int nt = 0; nt < 16; nt++) {
                O[nt][0] *= alpha0; O[nt][1] *= alpha0;
                O[nt][2] *= alpha1; O[nt][3] *= alpha1;
            }

            // convert V once (after its cp.async completes)
            if (half == 0) {
                if (hasNext) { CP_WAIT(1); } else { CP_WAIT(0); }
                __syncthreads();
                #pragma unroll
                for (int i = 0; i < 16; i++) {
                    int idx = tid + i * 256;        // 4096 half2
                    int kp = idx >> 7, n = idx & 127;
                    float x0 = Vraw[(2 * kp) * VRSTR + n];
                    float x1 = Vraw[(2 * kp + 1) * VRSTR + n];
                    Vp[kp * VPSTR + n] = h2pack(x0, x1);
                }
                __syncthreads();
            }

            // ---- PV (fp16) ----
            #pragma unroll
            for (int t16 = 0; t16 < 2; t16++) {
                int kpb = half * 16 + t16 * 8;
                #pragma unroll
                for (int nt = 0; nt < 16; nt++) {
                    int n = nt * 8 + lr;
                    unsigned b0 = Vp[(kpb + lc) * VPSTR + n];
                    unsigned b1 = Vp[(kpb + 4 + lc) * VPSTR + n];
                    mma_f16(O[nt], pa[t16][0], pa[t16][1], pa[t16][2], pa[t16][3], b0, b1);
                }
            }
        }
    }

    // epilogue
    float linv0 = 1.f / l0;
    float linv1 = 1.f / l1;
    int r0 = qb + wRow + lr;
    int r1 = r0 + 8;
    #pragma unroll
    for (int nt = 0; nt < 16; nt++) {
        int c = nt * 8 + 2 * lc;
        #pragma unroll
        for (int b = 0; b < 2; b++) {
            int cc = c + b;
            float v0 = O[nt][b] * linv0;
            float v1 = O[nt][2 + b] * linv1;
            if (cc < 32) {
                out_v[(size_t)r0 * EE + hof + cc] = v0;
                out_v[(size_t)r1 * EE + hof + cc] = v1;
            } else {
                int ch = (cc - 32) >> 5;
                int d  = (cc - 32) & 31;
                out_g[((size_t)r0 * 3 + ch) * EE + hof + d] = v0;
                out_g[((size_t)r1 * 3 + ch) * EE + hof + d] = v1;
            }
        }
    }
}

// ---------------------------------------------------------------------------
// Host orchestration
// ---------------------------------------------------------------------------
static void gemm_f32(const float* A, int lda, const float* B, int ldb,
                     const float* bias, const float* Res, float resScale,
                     float alpha, float* C, int ldc, int M, int Nd, int K, bool relu)
{
    dim3 g((Nd + 63) / 64, M / 64), b(256);
    if (relu)
        sgemm_kernel<true><<<g, b>>>(A, lda, B, ldb, bias, Res, resScale, alpha, C, ldc, M, Nd, K);
    else
        sgemm_kernel<false><<<g, b>>>(A, lda, B, ldb, bias, Res, resScale, alpha, C, ldc, M, Nd, K);
}

template<int NPASS>
static void gemm_tf32(const float* A, int lda, const float* B, int ldb,
                      const float* bias, const float* Res, float resScale,
                      float alpha, float* C, int ldc, int M, int Nd, int K, bool relu)
{
    dim3 g(Nd / 128, M / 128), b(256);
    if (relu)
        tf32_gemm<NPASS, true><<<g, b>>>(A, lda, B, ldb, bias, Res, resScale, alpha, C, ldc, M, Nd, K);
    else
        tf32_gemm<NPASS, false><<<g, b>>>(A, lda, B, ldb, bias, Res, resScale, alpha, C, ldc, M, Nd, K);
}

extern "C" void kernel_launch(void* const* d_in, const int* in_sizes, int n_in,
                              void* d_out, int out_size)
{
    const float* equ    = (const float*)d_in[0];
    const float* h      = (const float*)d_in[1];
    const float* W_equ  = (const float*)d_in[4];
    const float* W_gproj= (const float*)d_in[5];
    const float* W_vg   = (const float*)d_in[6];
    const float* W_g1   = (const float*)d_in[7];
    const float* b_g1   = (const float*)d_in[8];
    const float* W_g2   = (const float*)d_in[9];
    const float* b_g2   = (const float*)d_in[10];
    const float* W_q    = (const float*)d_in[11];
    const float* b_q    = (const float*)d_in[12];
    const float* W_k    = (const float*)d_in[13];
    const float* b_k    = (const float*)d_in[14];
    const float* W_v    = (const float*)d_in[15];
    const float* b_v    = (const float*)d_in[16];
    const float* W_ng   = (const float*)d_in[17];
    const float* b_ng   = (const float*)d_in[18];
    const float* W_gout = (const float*)d_in[19];
    const float* W_gdec = (const float*)d_in[20];
    const float* W_hdec = (const float*)d_in[21];
    const float* b_hdec = (const float*)d_in[22];

    float* out = (float*)d_out;

    float* S = nullptr;
    cudaGetSymbolAddress((void**)&S, scratch);
    cudaFuncSetAttribute(attn_kernel, cudaFuncAttributeMaxDynamicSharedMemorySize, ATTN_SMEM);

    float* g_src = S + OFF_GSRC;
    float* g2p   = S + OFF_G2P;
    float* gram  = S + OFF_GRAM;
    float* hid   = S + OFF_HID;
    float* h2    = S + OFF_H2;
    float* qd    = S + OFF_Q;
    float* kd    = S + OFF_K;
    float* vd    = S + OFF_V;
    float* vgd   = S + OFF_VG;
    float* outv  = S + OFF_OUTV;
    float* outg  = S + OFF_OUTG;
    float* hsrc  = S + OFF_HSRC;
    float* gsf   = S + OFF_GSF;

    const float scaling = 0.17677669529663687f;

    gemm_f32(equ, MMDIM, W_equ, EE, nullptr, nullptr, 0.f, 16.f, g_src, EE, ROWS, EE, MMDIM, false);
    gemm_f32(g_src, EE, W_gproj, 32, nullptr, nullptr, 0.f, 1.f, g2p, 32, ROWS, 32, EE, false);
    gram_kernel<<<NN, 128>>>(g2p, gram);
    gemm_tf32<1>(gram, 1024, W_g1, 512, b_g1, nullptr, 0.f, 1.f, hid, 512, NN, 512, 1024, true);
    gemm_tf32<1>(hid, 512, W_g2, EE, b_g2, nullptr, 0.f, 1.f, h2, 512, NN, EE, 512, false);
    h2fill_kernel<<<(NN * EE + 255) / 256, 256>>>(h, h2);

    // fused q/k/v projections (tf32x3)
    qkv_gemm<<<dim3(6, 32), 256>>>(h2, W_q, b_q, W_k, b_k, W_v, b_v, qd, kd, vd, scaling);

    gemm_tf32<1>(g_src, EE, W_vg, EE, nullptr, nullptr, 0.f, 1.f, vgd, EE, ROWS, EE, EE, false);

    attn_kernel<<<dim3(NN / AQ, HH), 256, ATTN_SMEM>>>(qd, kd, vd, vgd, outv, outg);

    gemm_tf32<1>(outv, EE, W_ng, EE, b_ng, h, 16.f, 1.f, hsrc, EE, NN, EE, EE, false);
    gemm_tf32<1>(outg, EE, W_gout, EE, nullptr, g_src, 1.f, 1.f, gsf, EE, ROWS, EE, EE, false);
    gemm_f32(gsf, EE, W_gdec, MMDIM, nullptr, nullptr, 0.f, 1.f, out, MMDIM, ROWS, MMDIM, EE, false);
    gemm_tf32<3>(hsrc, EE, W_hdec, EE, b_hdec, nullptr, 0.f, 1.f, out + ROWS * MMDIM, EE, NN, EE, EE, false);
}

// round 5
// speedup vs baseline: 4.7299x; 1.2461x over previous
#include <cuda_runtime.h>
#include <cuda_fp16.h>
#include <math.h>

#define NN 4096
#define NV 3
#define MMDIM 16
#define EE 256
#define HH 8
#define DD 32
#define ROWS (NN*NV)

__device__ float scratch[26607616];

// word offsets (1 word = 4 bytes)
#define OFF_GSRC    0u          // f32 [12288,256]
#define OFF_GSRC_H  3145728u    // h16 [12288,256]
#define OFF_G2P     4718592u    // f32 [12288,32]
#define OFF_GRAM_H  5111808u    // h16 [4096,1024]
#define OFF_HID_H   7208960u    // h16 [4096,512]
#define OFF_H2HI    8257536u    // h16 [4096,512]
#define OFF_H2LO    9306112u
#define OFF_QHI     10354688u   // h16 [4096,256]
#define OFF_QLO     10878976u
#define OFF_KHI     11403264u
#define OFF_KLO     11927552u
#define OFF_VH      12451840u   // h16 [4096,256]
#define OFF_VGH     12976128u   // h16 [12288,256]
#define OFF_OUTV    14548992u   // h16 [4096,256]
#define OFF_OUTG    15073280u   // h16 [12288,256]
#define OFF_HSRCHI  16646144u   // h16 [4096,256]
#define OFF_HSRCLO  17170432u
#define OFF_GSF     17694720u   // f32 [12288,256]
#define OFF_WG1P    20840448u   // packed half2 [512][512]
#define OFF_WG2P    21102592u   // [256][256]
#define OFF_WQHI    21168128u
#define OFF_WQLO    21233664u
#define OFF_WKHI    21299200u
#define OFF_WKLO    21364736u
#define OFF_WVP     21430272u
#define OFF_WVGP    21495808u   // [128][256]
#define OFF_WNGP    21528576u
#define OFF_WGOUTP  21561344u
#define OFF_WHDHI   21594112u
#define OFF_WHDLO   21626880u

// ---------------------------------------------------------------------------
// helpers
// ---------------------------------------------------------------------------
__device__ __forceinline__ void mma_f16(float c[4],
                                        unsigned a0, unsigned a1, unsigned a2, unsigned a3,
                                        unsigned b0, unsigned b1) {
    asm volatile(
        "mma.sync.aligned.m16n8k16.row.col.f32.f16.f16.f32 "
        "{%0,%1,%2,%3}, {%4,%5,%6,%7}, {%8,%9}, {%0,%1,%2,%3};"
        : "+f"(c[0]), "+f"(c[1]), "+f"(c[2]), "+f"(c[3])
        : "r"(a0), "r"(a1), "r"(a2), "r"(a3), "r"(b0), "r"(b1));
}

__device__ __forceinline__ unsigned h2pack(float a, float b) {
    __half2 h = __floats2half2_rn(a, b);
    return *(unsigned*)&h;
}

__device__ __forceinline__ void cp_async16(void* smem, const void* gmem) {
    unsigned s = (unsigned)__cvta_generic_to_shared(smem);
    asm volatile("cp.async.cg.shared.global [%0], [%1], 16;" :: "r"(s), "l"(gmem));
}
#define CP_COMMIT() asm volatile("cp.async.commit_group;")
#define CP_WAIT(n)  asm volatile("cp.async.wait_group %0;" :: "n"(n))

// ---------------------------------------------------------------------------
// fp32 SGEMM (small / odd-shaped GEMMs) with optional half copy of output
// ---------------------------------------------------------------------------
__global__ __launch_bounds__(256)
void sgemm_kernel(const float* __restrict__ A, int lda,
                  const float* __restrict__ B, int ldb,
                  const float* __restrict__ bias,
                  float alpha,
                  float* __restrict__ C, __half* __restrict__ Ch, int ldc,
                  int M, int Nd, int K)
{
    __shared__ float As[16 * 68];
    __shared__ float Bs[16 * 64];

    const int tid = threadIdx.x;
    const int tx  = tid & 15;
    const int ty  = tid >> 4;
    const int bm  = blockIdx.y * 64;
    const int bn  = blockIdx.x * 64;

    float acc[4][4] = {};

    for (int k0 = 0; k0 < K; k0 += 16) {
        #pragma unroll
        for (int i = 0; i < 4; i++) {
            int idx = tid + i * 256;
            int m_  = idx >> 4;
            int kk  = idx & 15;
            As[kk * 68 + m_] = A[(size_t)(bm + m_) * lda + k0 + kk];
        }
        #pragma unroll
        for (int i = 0; i < 4; i++) {
            int idx = tid + i * 256;
            int kk  = idx >> 6;
            int nn  = idx & 63;
            int gn  = bn + nn;
            Bs[kk * 64 + nn] = (gn < Nd) ? B[(size_t)(k0 + kk) * ldb + gn] : 0.f;
        }
        __syncthreads();

        #pragma unroll
        for (int kk = 0; kk < 16; kk++) {
            float4 a4 = *(const float4*)&As[kk * 68 + ty * 4];
            float4 b4 = *(const float4*)&Bs[kk * 64 + tx * 4];
            float a_[4] = {a4.x, a4.y, a4.z, a4.w};
            float b_[4] = {b4.x, b4.y, b4.z, b4.w};
            #pragma unroll
            for (int i = 0; i < 4; i++)
                #pragma unroll
                for (int j = 0; j < 4; j++)
                    acc[i][j] = fmaf(a_[i], b_[j], acc[i][j]);
        }
        __syncthreads();
    }

    #pragma unroll
    for (int i = 0; i < 4; i++) {
        int gm = bm + ty * 4 + i;
        #pragma unroll
        for (int j = 0; j < 4; j++) {
            int gn = bn + tx * 4 + j;
            if (gn < Nd) {
                float v = acc[i][j];
                if (bias) v += bias[gn];
                v *= alpha;
                C[(size_t)gm * ldc + gn] = v;
                if (Ch) Ch[(size_t)gm * ldc + gn] = __float2half_rn(v);
            }
        }
    }
}

// ---------------------------------------------------------------------------
// Weight pre-pack: W[K,N] f32 -> packed half2 [K/2][N]: elem(kp,n) = (W[2kp][n], W[2kp+1][n])
// hi always; lo residual optional (x3 GEMMs). One kernel for all weights.
// ---------------------------------------------------------------------------
__device__ __forceinline__ void pack_one(const float* __restrict__ W, int N, int i,
                                         unsigned* __restrict__ H, unsigned* __restrict__ L)
{
    int kp = i / N, n = i - kp * N;
    float x0 = W[(size_t)(2 * kp) * N + n];
    float x1 = W[(size_t)(2 * kp + 1) * N + n];
    __half h0 = __float2half_rn(x0), h1 = __float2half_rn(x1);
    __half2 hh = __halves2half2(h0, h1);
    H[i] = *(unsigned*)&hh;
    if (L) {
        __half2 ll = __floats2half2_rn(x0 - __half2float(h0), x1 - __half2float(h1));
        L[i] = *(unsigned*)&ll;
    }
}

__global__ void pack_weights(const float* Wg1, const float* Wg2, const float* Wq,
                             const float* Wk, const float* Wv, const float* Wvg,
                             const float* Wng, const float* Wgout, const float* Whd,
                             unsigned* Pg1, unsigned* Pg2,
                             unsigned* Pqh, unsigned* Pql,
                             unsigned* Pkh, unsigned* Pkl,
                             unsigned* Pv, unsigned* Pvg, unsigned* Png,
                             unsigned* Pgout, unsigned* Phdh, unsigned* Phdl)
{
    int idx = blockIdx.x * 256 + threadIdx.x;
    if (idx < 262144) { pack_one(Wg1, 512, idx, Pg1, nullptr); return; }
    idx -= 262144;
    if (idx < 65536) { pack_one(Wg2, 256, idx, Pg2, nullptr); return; }
    idx -= 65536;
    if (idx < 65536) { pack_one(Wq, 256, idx, Pqh, Pql); return; }
    idx -= 65536;
    if (idx < 65536) { pack_one(Wk, 256, idx, Pkh, Pkl); return; }
    idx -= 65536;
    if (idx < 65536) { pack_one(Wv, 256, idx, Pv, nullptr); return; }
    idx -= 65536;
    if (idx < 32768) { pack_one(Wvg, 256, idx, Pvg, nullptr); return; }
    idx -= 32768;
    if (idx < 32768) { pack_one(Wng, 256, idx, Png, nullptr); return; }
    idx -= 32768;
    if (idx < 32768) { pack_one(Wgout, 256, idx, Pgout, nullptr); return; }
    idx -= 32768;
    if (idx < 32768) { pack_one(Whd, 256, idx, Phdh, Phdl); return; }
}

// ---------------------------------------------------------------------------
// FP16 GEMM (m16n8k16), double-buffered cp.async, NPASS = 1 or 3 (hi/lo split).
// Block 128x128, BK=32, 8 warps, warp tile 64x32.
// A: half row-major [M,K] (+Al for x3). B: packed half2 [K/2][N] (+Bl).
// Epilogue (runtime): bias, fp32 residual, alpha, relu; write fp32 OR half OR hi/lo split.
// ---------------------------------------------------------------------------
#define HA_STR 20
#define HB_STR 136

__device__ __forceinline__ void epi_store(float v0, float v1,
                                          float* outF, __half* outH, __half* outL,
                                          size_t off)
{
    if (outF) {
        *(float2*)&outF[off] = make_float2(v0, v1);
    } else if (outL) {
        __half h0 = __float2half_rn(v0), h1 = __float2half_rn(v1);
        __half2 hh = __halves2half2(h0, h1);
        ((__half2*)outH)[off >> 1] = hh;
        ((__half2*)outL)[off >> 1] =
            __floats2half2_rn(v0 - __half2float(h0), v1 - __half2float(h1));
    } else {
        ((__half2*)outH)[off >> 1] = __floats2half2_rn(v0, v1);
    }
}

template<int NPASS, bool RELU>
__global__ __launch_bounds__(256)
void hgemm(const __half* __restrict__ A, const __half* __restrict__ Al, int lda,
           const unsigned* __restrict__ Bp, const unsigned* __restrict__ Bl, int ldbw,
           const float* __restrict__ bias,
           const float* __restrict__ Res, int ldres, float resScale, float alpha,
           float* __restrict__ outF, __half* __restrict__ outH, __half* __restrict__ outL,
           int ldc, int K)
{
    extern __shared__ unsigned smw[];
    unsigned* As  = smw;                        // [2][128*HA_STR]
    unsigned* Bs  = smw + 2 * 128 * HA_STR;     // [2][16*HB_STR]
    unsigned* Als = Bs + 2 * 16 * HB_STR;       // x3 only
    unsigned* Bls = Als + 2 * 128 * HA_STR;

    const int tid  = threadIdx.x;
    const int lane = tid & 31;
    const int warp = tid >> 5;
    const int bm   = blockIdx.y * 128;
    const int bn   = blockIdx.x * 128;
    const int wM   = (warp >> 2) * 64;
    const int wN   = (warp & 3) * 32;
    const int lr   = lane >> 2;
    const int lc   = lane & 3;

    float acc[4][4][4] = {};

    const int KT = K / 32;

    #define STAGE_A(SRC, DST, K0) { \
        _Pragma("unroll") \
        for (int i = 0; i < 2; i++) { \
            int idx = tid + i * 256; \
            int row = idx >> 2, seg = idx & 3; \
            cp_async16(&(DST)[row * HA_STR + seg * 4], \
                       &(SRC)[(size_t)(bm + row) * lda + (K0) + seg * 8]); \
        } }
    #define STAGE_B(SRC, DST, K0) { \
        _Pragma("unroll") \
        for (int i = 0; i < 2; i++) { \
            int idx = tid + i * 256; \
            int kp = idx >> 5, s = idx & 31; \
            cp_async16(&(DST)[kp * HB_STR + s * 4], \
                       &(SRC)[(size_t)(((K0) >> 1) + kp) * ldbw + bn + s * 4]); \
        } }

    STAGE_A(A, As, 0);
    if (NPASS == 3) STAGE_A(Al, Als, 0);
    STAGE_B(Bp, Bs, 0);
    if (NPASS == 3) STAGE_B(Bl, Bls, 0);
    CP_COMMIT();

    for (int kt = 0; kt < KT; kt++) {
        if (kt + 1 < KT) {
            int nb = (kt + 1) & 1, k0 = (kt + 1) * 32;
            STAGE_A(A, As + nb * 128 * HA_STR, k0);
            if (NPASS == 3) STAGE_A(Al, Als + nb * 128 * HA_STR, k0);
            STAGE_B(Bp, Bs + nb * 16 * HB_STR, k0);
            if (NPASS == 3) STAGE_B(Bl, Bls + nb * 16 * HB_STR, k0);
            CP_COMMIT();
            CP_WAIT(1);
        } else {
            CP_WAIT(0);
        }
        __syncthreads();

        const unsigned* Ac  = As  + (kt & 1) * 128 * HA_STR;
        const unsigned* Bc  = Bs  + (kt & 1) * 16 * HB_STR;
        const unsigned* Alc = Als + (kt & 1) * 128 * HA_STR;
        const unsigned* Blc = Bls + (kt & 1) * 16 * HB_STR;

        #pragma unroll
        for (int ks = 0; ks < 2; ks++) {
            unsigned ah[4][4], al[4][4];
            #pragma unroll
            for (int mt = 0; mt < 4; mt++) {
                int rb = wM + mt * 16 + lr;
                int c  = ks * 8 + lc;
                ah[mt][0] = Ac[rb * HA_STR + c];
                ah[mt][1] = Ac[(rb + 8) * HA_STR + c];
                ah[mt][2] = Ac[rb * HA_STR + c + 4];
                ah[mt][3] = Ac[(rb + 8) * HA_STR + c + 4];
                if (NPASS == 3) {
                    al[mt][0] = Alc[rb * HA_STR + c];
                    al[mt][1] = Alc[(rb + 8) * HA_STR + c];
                    al[mt][2] = Alc[rb * HA_STR + c + 4];
                    al[mt][3] = Alc[(rb + 8) * HA_STR + c + 4];
                }
            }
            unsigned bh[4][2], bl[4][2];
            #pragma unroll
            for (int nt = 0; nt < 4; nt++) {
                int n  = wN + nt * 8 + lr;
                int kp = ks * 8 + lc;
                bh[nt][0] = Bc[kp * HB_STR + n];
                bh[nt][1] = Bc[(kp + 4) * HB_STR + n];
                if (NPASS == 3) {
                    bl[nt][0] = Blc[kp * HB_STR + n];
                    bl[nt][1] = Blc[(kp + 4) * HB_STR + n];
                }
            }
            #pragma unroll
            for (int mt = 0; mt < 4; mt++)
                #pragma unroll
                for (int nt = 0; nt < 4; nt++) {
                    mma_f16(acc[mt][nt], ah[mt][0], ah[mt][1], ah[mt][2], ah[mt][3],
                            bh[nt][0], bh[nt][1]);
                    if (NPASS == 3) {
                        mma_f16(acc[mt][nt], ah[mt][0], ah[mt][1], ah[mt][2], ah[mt][3],
                                bl[nt][0], bl[nt][1]);
                        mma_f16(acc[mt][nt], al[mt][0], al[mt][1], al[mt][2], al[mt][3],
                                bh[nt][0], bh[nt][1]);
                    }
                }
        }
        __syncthreads();
    }

    #pragma unroll
    for (int mt = 0; mt < 4; mt++) {
        #pragma unroll
        for (int nt = 0; nt < 4; nt++) {
            int col = bn + wN + nt * 8 + 2 * lc;
            #pragma unroll
            for (int half = 0; half < 2; half++) {
                int r = bm + wM + mt * 16 + lr + half * 8;
                float v0 = acc[mt][nt][half * 2 + 0];
                float v1 = acc[mt][nt][half * 2 + 1];
                if (bias) { v0 += bias[col]; v1 += bias[col + 1]; }
                v0 *= alpha; v1 *= alpha;
                if (Res) {
                    v0 = fmaf(resScale, Res[(size_t)r * ldres + col], v0);
                    v1 = fmaf(resScale, Res[(size_t)r * ldres + col + 1], v1);
                }
                if (RELU) { v0 = fmaxf(v0, 0.f); v1 = fmaxf(v1, 0.f); }
                epi_store(v0, v1, outF, outH, outL, (size_t)r * ldc + col);
            }
        }
    }
    #undef STAGE_A
    #undef STAGE_B
}

// ---------------------------------------------------------------------------
// Fused QKV (fp16, q/k x3 + split outputs, v x1 half output). blockIdx.z = seg.
// A = h2hi/h2lo [4096,512]. Grid (2, 32, 3).
// ---------------------------------------------------------------------------
__global__ __launch_bounds__(256)
void qkv_hgemm(const __half* __restrict__ A, const __half* __restrict__ Al,
               const unsigned* __restrict__ Pqh, const unsigned* __restrict__ Pql,
               const unsigned* __restrict__ Pkh, const unsigned* __restrict__ Pkl,
               const unsigned* __restrict__ Pv,
               const float* __restrict__ bq, const float* __restrict__ bk,
               const float* __restrict__ bv,
               __half* qh, __half* ql, __half* kh, __half* kl, __half* vh,
               float scaling)
{
    extern __shared__ unsigned smw[];
    unsigned* As  = smw;
    unsigned* Bs  = smw + 2 * 128 * HA_STR;
    unsigned* Als = Bs + 2 * 16 * HB_STR;
    unsigned* Bls = Als + 2 * 128 * HA_STR;

    const int seg = blockIdx.z;
    const bool x3 = (seg < 2);
    const unsigned* Bp = (seg == 0) ? Pqh : (seg == 1) ? Pkh : Pv;
    const unsigned* Bl = (seg == 0) ? Pql : (seg == 1) ? Pkl : nullptr;
    const float* bias  = (seg == 0) ? bq : (seg == 1) ? bk : bv;
    __half* outH = (seg == 0) ? qh : (seg == 1) ? kh : vh;
    __half* outL = (seg == 0) ? ql : (seg == 1) ? kl : nullptr;
    const float alpha = (seg == 0) ? scaling : 1.f;
    const int lda = 512, ldbw = 256, ldc = 256, K = 512;

    const int tid  = threadIdx.x;
    const int lane = tid & 31;
    const int warp = tid >> 5;
    const int bm   = blockIdx.y * 128;
    const int bn   = blockIdx.x * 128;
    const int wM   = (warp >> 2) * 64;
    const int wN   = (warp & 3) * 32;
    const int lr   = lane >> 2;
    const int lc   = lane & 3;

    float acc[4][4][4] = {};

    #define QSTAGE_A(SRC, DST, K0) { \
        _Pragma("unroll") \
        for (int i = 0; i < 2; i++) { \
            int idx = tid + i * 256; \
            int row = idx >> 2, sg = idx & 3; \
            cp_async16(&(DST)[row * HA_STR + sg * 4], \
                       &(SRC)[(size_t)(bm + row) * lda + (K0) + sg * 8]); \
        } }
    #define QSTAGE_B(SRC, DST, K0) { \
        _Pragma("unroll") \
        for (int i = 0; i < 2; i++) { \
            int idx = tid + i * 256; \
            int kp = idx >> 5, s = idx & 31; \
            cp_async16(&(DST)[kp * HB_STR + s * 4], \
                       &(SRC)[(size_t)(((K0) >> 1) + kp) * ldbw + bn + s * 4]); \
        } }

    QSTAGE_A(A, As, 0);
    if (x3) QSTAGE_A(Al, Als, 0);
    QSTAGE_B(Bp, Bs, 0);
    if (x3) QSTAGE_B(Bl, Bls, 0);
    CP_COMMIT();

    const int KT = K / 32;
    for (int kt = 0; kt < KT; kt++) {
        if (kt + 1 < KT) {
            int nb = (kt + 1) & 1, k0 = (kt + 1) * 32;
            QSTAGE_A(A, As + nb * 128 * HA_STR, k0);
            if (x3) QSTAGE_A(Al, Als + nb * 128 * HA_STR, k0);
            QSTAGE_B(Bp, Bs + nb * 16 * HB_STR, k0);
            if (x3) QSTAGE_B(Bl, Bls + nb * 16 * HB_STR, k0);
            CP_COMMIT();
            CP_WAIT(1);
        } else {
            CP_WAIT(0);
        }
        __syncthreads();

        const unsigned* Ac  = As  + (kt & 1) * 128 * HA_STR;
        const unsigned* Bc  = Bs  + (kt & 1) * 16 * HB_STR;
        const unsigned* Alc = Als + (kt & 1) * 128 * HA_STR;
        const unsigned* Blc = Bls + (kt & 1) * 16 * HB_STR;

        #pragma unroll
        for (int ks = 0; ks < 2; ks++) {
            unsigned ah[4][4], al[4][4];
            #pragma unroll
            for (int mt = 0; mt < 4; mt++) {
                int rb = wM + mt * 16 + lr;
                int c  = ks * 8 + lc;
                ah[mt][0] = Ac[rb * HA_STR + c];
                ah[mt][1] = Ac[(rb + 8) * HA_STR + c];
                ah[mt][2] = Ac[rb * HA_STR + c + 4];
                ah[mt][3] = Ac[(rb + 8) * HA_STR + c + 4];
                if (x3) {
                    al[mt][0] = Alc[rb * HA_STR + c];
                    al[mt][1] = Alc[(rb + 8) * HA_STR + c];
                    al[mt][2] = Alc[rb * HA_STR + c + 4];
                    al[mt][3] = Alc[(rb + 8) * HA_STR + c + 4];
                }
            }
            unsigned bh[4][2], bl[4][2];
            #pragma unroll
            for (int nt = 0; nt < 4; nt++) {
                int n  = wN + nt * 8 + lr;
                int kp = ks * 8 + lc;
                bh[nt][0] = Bc[kp * HB_STR + n];
                bh[nt][1] = Bc[(kp + 4) * HB_STR + n];
                if (x3) {
                    bl[nt][0] = Blc[kp * HB_STR + n];
                    bl[nt][1] = Blc[(kp + 4) * HB_STR + n];
                }
            }
            #pragma unroll
            for (int mt = 0; mt < 4; mt++)
                #pragma unroll
                for (int nt = 0; nt < 4; nt++) {
                    mma_f16(acc[mt][nt], ah[mt][0], ah[mt][1], ah[mt][2], ah[mt][3],
                            bh[nt][0], bh[nt][1]);
                    if (x3) {
                        mma_f16(acc[mt][nt], ah[mt][0], ah[mt][1], ah[mt][2], ah[mt][3],
                                bl[nt][0], bl[nt][1]);
                        mma_f16(acc[mt][nt], al[mt][0], al[mt][1], al[mt][2], al[mt][3],
                                bh[nt][0], bh[nt][1]);
                    }
                }
        }
        __syncthreads();
    }

    #pragma unroll
    for (int mt = 0; mt < 4; mt++) {
        #pragma unroll
        for (int nt = 0; nt < 4; nt++) {
            int col = bn + wN + nt * 8 + 2 * lc;
            #pragma unroll
            for (int half = 0; half < 2; half++) {
                int r = bm + wM + mt * 16 + lr + half * 8;
                float v0 = (acc[mt][nt][half * 2 + 0] + bias[col]) * alpha;
                float v1 = (acc[mt][nt][half * 2 + 1] + bias[col + 1]) * alpha;
                epi_store(v0, v1, nullptr, outH, outL, (size_t)r * ldc + col);
            }
        }
    }
    #undef QSTAGE_A
    #undef QSTAGE_B
}

// ---------------------------------------------------------------------------
// Gram (half out) + h2 fill (split halves)
// ---------------------------------------------------------------------------
__global__ void gram_kernel(const float* __restrict__ g2p, __half* __restrict__ gram)
{
    int node = blockIdx.x;
    __shared__ float s[96];
    int tid = threadIdx.x;
    if (tid < 96) s[tid] = g2p[(size_t)node * 96 + tid];
    __syncthreads();
    #pragma unroll
    for (int o = tid; o < 1024; o += 128) {
        int a = o >> 5, b = o & 31;
        gram[(size_t)node * 1024 + o] = __float2half_rn(
            s[a] * s[b] + s[32 + a] * s[32 + b] + s[64 + a] * s[64 + b]);
    }
}

__global__ void h2fill_kernel(const float* __restrict__ h,
                              __half* __restrict__ h2hi, __half* __restrict__ h2lo)
{
    int idx = blockIdx.x * blockDim.x + threadIdx.x;
    if (idx < NN * EE) {
        int r = idx >> 8, c = idx & 255;
        float v = 16.f * h[idx];
        __half hi = __float2half_rn(v);
        size_t o = (size_t)r * 512 + 256 + c;
        h2hi[o] = hi;
        h2lo[o] = __float2half_rn(v - __half2float(hi));
    }
}

// ---------------------------------------------------------------------------
// Flash attention v4: pre-split packed q/k from gmem (cp.async direct),
// half v/vg, fp16x3 S, fp16 PV, half outputs.
// ---------------------------------------------------------------------------
#define AQ 128
#define AK 64
#define QP 20
#define VRW 68      // V raw word stride (64 data + 4 pad) -> half stride 136
#define VPSTR 136

#define ATTN_WORDS (2560*4 + 4352*2)
#define ATTN_SMEM  (ATTN_WORDS * 4)

__global__ __launch_bounds__(256, 2)
void attn_kernel(const unsigned* __restrict__ qhiW, const unsigned* __restrict__ qloW,
                 const unsigned* __restrict__ khiW, const unsigned* __restrict__ kloW,
                 const unsigned* __restrict__ vW, const unsigned* __restrict__ vgW,
                 __half* __restrict__ outv, __half* __restrict__ outg)
{
    extern __shared__ unsigned smw[];
    unsigned* Qhi  = smw;                 // [128][QP]
    unsigned* Qlo  = Qhi + 2560;
    unsigned* Khi  = Qlo + 2560;          // 2 x [64][QP]
    unsigned* Klo  = Khi + 2560;
    unsigned* VrawW = Klo + 2560;         // [64][VRW]
    unsigned* Vp   = VrawW + 4352;        // [32][VPSTR]

    const int head = blockIdx.y;
    const int qb   = blockIdx.x * AQ;
    const int tid  = threadIdx.x;
    const int lane = tid & 31;
    const int warp = tid >> 5;
    const int hofw = head * 16;           // word offset of head slice (32 halves)
    const int hof  = head * DD;
    const int lr   = lane >> 2;
    const int lc   = lane & 3;
    const int wRow = warp * 16;

    // prologue: K(0) + Q in one cp.async group
    {
        int key = tid >> 2, seg = tid & 3;
        cp_async16(&Khi[key * QP + seg * 4], &khiW[(size_t)key * 128 + hofw + seg * 4]);
        cp_async16(&Klo[key * QP + seg * 4], &kloW[(size_t)key * 128 + hofw + seg * 4]);
    }
    #pragma unroll
    for (int i = 0; i < 2; i++) {
        int idx = tid + i * 256;
        int row = idx >> 2, seg = idx & 3;
        cp_async16(&Qhi[row * QP + seg * 4], &qhiW[(size_t)(qb + row) * 128 + hofw + seg * 4]);
        cp_async16(&Qlo[row * QP + seg * 4], &qloW[(size_t)(qb + row) * 128 + hofw + seg * 4]);
    }
    CP_COMMIT();

    float O[16][4] = {};
    float m0 = -1e30f, m1 = -1e30f, l0 = 0.f, l1 = 0.f;

    for (int t = 0; t < NN / AK; t++) {
        const int kb = t * AK;
        __syncthreads();   // VrawW/Vp and K-alt buffer reuse safe

        // issue V(t): 64 keys x 16 x 16B
        #pragma unroll
        for (int i = 0; i < 4; i++) {
            int idx = tid + i * 256;
            int key = idx >> 4;
            int cs  = idx & 15;
            int chunk = cs >> 2, seg = cs & 3;
            const unsigned* src = (chunk == 0)
                ? &vW[(size_t)(kb + key) * 128 + hofw + seg * 4]
                : &vgW[((size_t)(kb + key) * 3 + (chunk - 1)) * 128 + hofw + seg * 4];
            cp_async16(&VrawW[key * VRW + chunk * 16 + seg * 4], src);
        }
        CP_COMMIT();

        const bool hasNext = (t + 1 < NN / AK);
        if (hasNext) {
            unsigned* Kdh = Khi + ((t + 1) & 1) * 1280;
            unsigned* Kdl = Klo + ((t + 1) & 1) * 1280;
            int key = tid >> 2, seg = tid & 3;
            cp_async16(&Kdh[key * QP + seg * 4],
                       &khiW[(size_t)(kb + AK + key) * 128 + hofw + seg * 4]);
            cp_async16(&Kdl[key * QP + seg * 4],
                       &kloW[(size_t)(kb + AK + key) * 128 + hofw + seg * 4]);
            CP_COMMIT();
            CP_WAIT(2);   // K(t) (+Q at t=0) done
        } else {
            CP_WAIT(1);
        }
        __syncthreads();

        const unsigned* Kh = Khi + (t & 1) * 1280;
        const unsigned* Kl = Klo + (t & 1) * 1280;

        #pragma unroll
        for (int half = 0; half < 2; half++) {
            // ---- S = Q K^T (fp16x3) ----
            float s[4][4] = {};
            #pragma unroll
            for (int ks = 0; ks < 2; ks++) {
                int rb = wRow + lr;
                int c  = ks * 8 + lc;
                unsigned ah0 = Qhi[rb * QP + c],     ah1 = Qhi[(rb + 8) * QP + c];
                unsigned ah2 = Qhi[rb * QP + c + 4], ah3 = Qhi[(rb + 8) * QP + c + 4];
                unsigned al0 = Qlo[rb * QP + c],     al1 = Qlo[(rb + 8) * QP + c];
                unsigned al2 = Qlo[rb * QP + c + 4], al3 = Qlo[(rb + 8) * QP + c + 4];
                #pragma unroll
                for (int nt = 0; nt < 4; nt++) {
                    int key = half * 32 + nt * 8 + lr;
                    unsigned bh0 = Kh[key * QP + c];
                    unsigned bh1 = Kh[key * QP + c + 4];
                    unsigned bl0 = Kl[key * QP + c];
                    unsigned bl1 = Kl[key * QP + c + 4];
                    mma_f16(s[nt], ah0, ah1, ah2, ah3, bh0, bh1);
                    mma_f16(s[nt], ah0, ah1, ah2, ah3, bl0, bl1);
                    mma_f16(s[nt], al0, al1, al2, al3, bh0, bh1);
                }
            }

            // ---- online softmax ----
            float mx0 = m0, mx1 = m1;
            #pragma unroll
            for (int nt = 0; nt < 4; nt++) {
                mx0 = fmaxf(mx0, fmaxf(s[nt][0], s[nt][1]));
                mx1 = fmaxf(mx1, fmaxf(s[nt][2], s[nt][3]));
            }
            mx0 = fmaxf(mx0, __shfl_xor_sync(0xffffffff, mx0, 1));
            mx0 = fmaxf(mx0, __shfl_xor_sync(0xffffffff, mx0, 2));
            mx1 = fmaxf(mx1, __shfl_xor_sync(0xffffffff, mx1, 1));
            mx1 = fmaxf(mx1, __shfl_xor_sync(0xffffffff, mx1, 2));

            float alpha0 = __expf(m0 - mx0);
            float alpha1 = __expf(m1 - mx1);
            float sum0 = 0.f, sum1 = 0.f;
            #pragma unroll
            for (int nt = 0; nt < 4; nt++) {
                s[nt][0] = __expf(s[nt][0] - mx0);
                s[nt][1] = __expf(s[nt][1] - mx0);
                s[nt][2] = __expf(s[nt][2] - mx1);
                s[nt][3] = __expf(s[nt][3] - mx1);
                sum0 += s[nt][0] + s[nt][1];
                sum1 += s[nt][2] + s[nt][3];
            }
            sum0 += __shfl_xor_sync(0xffffffff, sum0, 1);
            sum0 += __shfl_xor_sync(0xffffffff, sum0, 2);
            sum1 += __shfl_xor_sync(0xffffffff, sum1, 1);
            sum1 += __shfl_xor_sync(0xffffffff, sum1, 2);
            l0 = l0 * alpha0 + sum0;  m0 = mx0;
            l1 = l1 * alpha1 + sum1;  m1 = mx1;

            unsigned pa[2][4];
            #pragma unroll
            for (int t16 = 0; t16 < 2; t16++) {
                pa[t16][0] = h2pack(s[2 * t16][0],     s[2 * t16][1]);
                pa[t16][1] = h2pack(s[2 * t16][2],     s[2 * t16][3]);
                pa[t16][2] = h2pack(s[2 * t16 + 1][0], s[2 * t16 + 1][1]);
                pa[t16][3] = h2pack(s[2 * t16 + 1][2], s[2 * t16 + 1][3]);
            }

            #pragma unroll
            for (int nt = 0; nt < 16; nt++) {
                O[nt][0] *= alpha0; O[nt][1] *= alpha0;
                O[nt][2] *= alpha1; O[nt][3] *= alpha1;
            }

            // V arrival + pack (once per tile)
            if (half == 0) {
                if (hasNext) { CP_WAIT(1); } else { CP_WAIT(0); }
                __syncthreads();
                const __half* VH = (const __half*)VrawW;
                #pragma unroll
                for (int i = 0; i < 16; i++) {
                    int idx = tid + i * 256;
                    int kp = idx >> 7, n = idx & 127;
                    __half2 hh = __halves2half2(VH[(2 * kp) * 136 + n],
                                                VH[(2 * kp + 1) * 136 + n]);
                    Vp[kp * VPSTR + n] = *(unsigned*)&hh;
                }
                __syncthreads();
            }

            // ---- PV (fp16) ----
            #pragma unroll
            for (int t16 = 0; t16 < 2; t16++) {
                int kpb = half * 16 + t16 * 8;
                #pragma unroll
                for (int nt = 0; nt < 16; nt++) {
                    int n = nt * 8 + lr;
                    unsigned b0 = Vp[(kpb + lc) * VPSTR + n];
                    unsigned b1 = Vp[(kpb + 4 + lc) * VPSTR + n];
                    mma_f16(O[nt], pa[t16][0], pa[t16][1], pa[t16][2], pa[t16][3], b0, b1);
                }
            }
        }
    }

    // epilogue: half2 writes
    float linv0 = 1.f / l0;
    float linv1 = 1.f / l1;
    int r0 = qb + wRow + lr;
    int r1 = r0 + 8;
    unsigned* outvW = (unsigned*)outv;
    unsigned* outgW = (unsigned*)outg;
    #pragma unroll
    for (int nt = 0; nt < 16; nt++) {
        int c = nt * 8 + 2 * lc;
        unsigned w0 = h2pack(O[nt][0] * linv0, O[nt][1] * linv0);
        unsigned w1 = h2pack(O[nt][2] * linv1, O[nt][3] * linv1);
        if (c < 32) {
            outvW[(size_t)r0 * 128 + (hof + c) / 2] = w0;
            outvW[(size_t)r1 * 128 + (hof + c) / 2] = w1;
        } else {
            int ch = (c - 32) >> 5;
            int d  = (c - 32) & 31;
            outgW[((size_t)r0 * 3 + ch) * 128 + (hof + d) / 2] = w0;
            outgW[((size_t)r1 * 3 + ch) * 128 + (hof + d) / 2] = w1;
        }
    }
}

// ---------------------------------------------------------------------------
// Host orchestration
// ---------------------------------------------------------------------------
extern "C" void kernel_launch(void* const* d_in, const int* in_sizes, int n_in,
                              void* d_out, int out_size)
{
    const float* equ    = (const float*)d_in[0];
    const float* h      = (const float*)d_in[1];
    const float* W_equ  = (const float*)d_in[4];
    const float* W_gproj= (const float*)d_in[5];
    const float* W_vg   = (const float*)d_in[6];
    const float* W_g1   = (const float*)d_in[7];
    const float* b_g1   = (const float*)d_in[8];
    const float* W_g2   = (const float*)d_in[9];
    const float* b_g2   = (const float*)d_in[10];
    const float* W_q    = (const float*)d_in[11];
    const float* b_q    = (const float*)d_in[12];
    const float* W_k    = (const float*)d_in[13];
    const float* b_k    = (const float*)d_in[14];
    const float* W_v    = (const float*)d_in[15];
    const float* b_v    = (const float*)d_in[16];
    const float* W_ng   = (const float*)d_in[17];
    const float* b_ng   = (const float*)d_in[18];
    const float* W_gout = (const float*)d_in[19];
    const float* W_gdec = (const float*)d_in[20];
    const float* W_hdec = (const float*)d_in[21];
    const float* b_hdec = (const float*)d_in[22];

    float* out = (float*)d_out;

    float* S = nullptr;
    cudaGetSymbolAddress((void**)&S, scratch);

    const int SM1 = (2 * 128 * HA_STR + 2 * 16 * HB_STR) * 4;       // 37888
    const int SM3 = SM1 * 2;                                         // 75776
    cudaFuncSetAttribute(hgemm<1, true>,  cudaFuncAttributeMaxDynamicSharedMemorySize, SM1);
    cudaFuncSetAttribute(hgemm<1, false>, cudaFuncAttributeMaxDynamicSharedMemorySize, SM1);
    cudaFuncSetAttribute(hgemm<3, false>, cudaFuncAttributeMaxDynamicSharedMemorySize, SM3);
    cudaFuncSetAttribute(qkv_hgemm, cudaFuncAttributeMaxDynamicSharedMemorySize, SM3);
    cudaFuncSetAttribute(attn_kernel, cudaFuncAttributeMaxDynamicSharedMemorySize, ATTN_SMEM);

    float*  gsrc   = S + OFF_GSRC;
    __half* gsrc_h = (__half*)(S + OFF_GSRC_H);
    float*  g2p    = S + OFF_G2P;
    __half* gram_h = (__half*)(S + OFF_GRAM_H);
    __half* hid_h  = (__half*)(S + OFF_HID_H);
    __half* h2hi   = (__half*)(S + OFF_H2HI);
    __half* h2lo   = (__half*)(S + OFF_H2LO);
    __half* qhi    = (__half*)(S + OFF_QHI);
    __half* qlo    = (__half*)(S + OFF_QLO);
    __half* khi    = (__half*)(S + OFF_KHI);
    __half* klo    = (__half*)(S + OFF_KLO);
    __half* vh     = (__half*)(S + OFF_VH);
    __half* vgh    = (__half*)(S + OFF_VGH);
    __half* outv_h = (__half*)(S + OFF_OUTV);
    __half* outg_h = (__half*)(S + OFF_OUTG);
    __half* hsrchi = (__half*)(S + OFF_HSRCHI);
    __half* hsrclo = (__half*)(S + OFF_HSRCLO);
    float*  gsf    = S + OFF_GSF;
    unsigned* Pg1  = (unsigned*)(S + OFF_WG1P);
    unsigned* Pg2  = (unsigned*)(S + OFF_WG2P);
    unsigned* Pqh  = (unsigned*)(S + OFF_WQHI);
    unsigned* Pql  = (unsigned*)(S + OFF_WQLO);
    unsigned* Pkh  = (unsigned*)(S + OFF_WKHI);
    unsigned* Pkl  = (unsigned*)(S + OFF_WKLO);
    unsigned* Pv   = (unsigned*)(S + OFF_WVP);
    unsigned* Pvg  = (unsigned*)(S + OFF_WVGP);
    unsigned* Png  = (unsigned*)(S + OFF_WNGP);
    unsigned* Pgout= (unsigned*)(S + OFF_WGOUTP);
    unsigned* Phdh = (unsigned*)(S + OFF_WHDHI);
    unsigned* Phdl = (unsigned*)(S + OFF_WHDLO);

    const float scaling = 0.17677669529663687f;

    // weight packing
    pack_weights<<<2560, 256>>>(W_g1, W_g2, W_q, W_k, W_v, W_vg, W_ng, W_gout, W_hdec,
                                Pg1, Pg2, Pqh, Pql, Pkh, Pkl, Pv, Pvg, Png, Pgout, Phdh, Phdl);

    // g_src = (equ @ W_equ) * 16 (fp32 + half copy)
    sgemm_kernel<<<dim3(4, ROWS / 64), 256>>>(equ, MMDIM, W_equ, EE, nullptr, 16.f,
                                              gsrc, gsrc_h, EE, ROWS, EE, MMDIM);
    // g2p = g_src @ W_gproj
    sgemm_kernel<<<dim3(1, ROWS / 64), 256>>>(gsrc, EE, W_gproj, 32, nullptr, 1.f,
                                              g2p, nullptr, 32, ROWS, 32, EE);
    gram_kernel<<<NN, 128>>>(g2p, gram_h);

    // MLP
    hgemm<1, true><<<dim3(4, 32), 256, SM1>>>(gram_h, nullptr, 1024, Pg1, nullptr, 512,
                                              b_g1, nullptr, 0, 0.f, 1.f,
                                              nullptr, hid_h, nullptr, 512, 1024);
    hgemm<1, false><<<dim3(2, 32), 256, SM1>>>(hid_h, nullptr, 512, Pg2, nullptr, 256,
                                               b_g2, nullptr, 0, 0.f, 1.f,
                                               nullptr, h2hi, h2lo, 512, 512);
    h2fill_kernel<<<(NN * EE + 255) / 256, 256>>>(h, h2hi, h2lo);

    // fused q/k/v projections
    qkv_hgemm<<<dim3(2, 32, 3), 256, SM3>>>(h2hi, h2lo, Pqh, Pql, Pkh, Pkl, Pv,
                                            b_q, b_k, b_v, qhi, qlo, khi, klo, vh, scaling);

    // vg = g_src @ W_vg
    hgemm<1, false><<<dim3(2, 96), 256, SM1>>>(gsrc_h, nullptr, 256, Pvg, nullptr, 256,
                                               nullptr, nullptr, 0, 0.f, 1.f,
                                               nullptr, vgh, nullptr, 256, 256);

    // attention
    attn_kernel<<<dim3(NN / AQ, HH), 256, ATTN_SMEM>>>(
        (const unsigned*)qhi, (const unsigned*)qlo,
        (const unsigned*)khi, (const unsigned*)klo,
        (const unsigned*)vh, (const unsigned*)vgh, outv_h, outg_h);

    // hsrc = outv @ W_ng + b_ng + 16h  (split out)
    hgemm<1, false><<<dim3(2, 32), 256, SM1>>>(outv_h, nullptr, 256, Png, nullptr, 256,
                                               b_ng, h, 256, 16.f, 1.f,
                                               nullptr, hsrchi, hsrclo, 256, 256);
    // gsf = outg @ W_gout + g_src  (fp32 out)
    hgemm<1, false><<<dim3(2, 96), 256, SM1>>>(outg_h, nullptr, 256, Pgout, nullptr, 256,
                                               nullptr, gsrc, 256, 1.f, 1.f,
                                               gsf, nullptr, nullptr, 256, 256);
    // equ_out = gsf @ W_gdec (fp32)
    sgemm_kernel<<<dim3(1, ROWS / 64), 256>>>(gsf, EE, W_gdec, MMDIM, nullptr, 1.f,
                                              out, nullptr, MMDIM, ROWS, MMDIM, EE);
    // h_out = hsrc @ W_hdec + b_hdec (fp16x3)
    hgemm<3, false><<<dim3(2, 32), 256, SM3>>>(hsrchi, hsrclo, 256, Phdh, Phdl, 256,
                                               b_hdec, nullptr, 0, 0.f, 1.f,
                                               out + (size_t)ROWS * MMDIM, nullptr, nullptr,
                                               256, 256);
}

// round 6
// speedup vs baseline: 6.1444x; 1.2991x over previous
#include <cuda_runtime.h>
#include <cuda_fp16.h>
#include <math.h>

#define NN 4096
#define NV 3
#define MMDIM 16
#define EE 256
#define HH 8
#define DD 32
#define ROWS (NN*NV)

__device__ float scratch[26607616];

// word offsets
#define OFF_GRAM    0u          // h16 [4096,1024]
#define OFF_HID     2097152u    // h16 [4096,512]
#define OFF_H2HI    3145728u    // h16 [4096,512]
#define OFF_H2LO    4194304u
#define OFF_QHI     5242880u    // h16 [4096,256]
#define OFF_QLO     5767168u
#define OFF_KHI     6291456u
#define OFF_KLO     6815744u
#define OFF_VH      7340032u
#define OFF_VGH     7864320u    // h16 [12288,256]
#define OFF_VPAIR   9437184u    // half2 [2048][8][128]
#define OFF_OUTV    11534336u   // h16 [4096,256]
#define OFF_OUTG    12058624u   // h16 [12288,256]
#define OFF_HPRE    13631488u   // f32 [4096,256]
#define OFF_PG1     14680064u
#define OFF_PG2     14942208u
#define OFF_PQH     15007744u
#define OFF_PQL     15073280u
#define OFF_PKH     15138816u
#define OFF_PKL     15204352u
#define OFF_PV      15269888u
#define OFF_PHDH    15335424u
#define OFF_PHDL    15368192u
#define OFF_W3P     15400960u
#define OFF_WG      15433728u   // f32 [16][32]
#define OFF_W1      15434240u   // f32 [16][16]
#define OFF_WVG2    15434496u   // f32 [16][256]
#define OFF_W2F     15438592u   // f32 [256][16]
#define OFF_BIAS2   15442688u   // f32 [256]

// ---------------------------------------------------------------------------
// helpers
// ---------------------------------------------------------------------------
__device__ __forceinline__ void mma_f16(float c[4],
                                        unsigned a0, unsigned a1, unsigned a2, unsigned a3,
                                        unsigned b0, unsigned b1) {
    asm volatile(
        "mma.sync.aligned.m16n8k16.row.col.f32.f16.f16.f32 "
        "{%0,%1,%2,%3}, {%4,%5,%6,%7}, {%8,%9}, {%0,%1,%2,%3};"
        : "+f"(c[0]), "+f"(c[1]), "+f"(c[2]), "+f"(c[3])
        : "r"(a0), "r"(a1), "r"(a2), "r"(a3), "r"(b0), "r"(b1));
}

__device__ __forceinline__ unsigned h2pack(float a, float b) {
    __half2 h = __floats2half2_rn(a, b);
    return *(unsigned*)&h;
}

__device__ __forceinline__ void cp_async16(void* smem, const void* gmem) {
    unsigned s = (unsigned)__cvta_generic_to_shared(smem);
    asm volatile("cp.async.cg.shared.global [%0], [%1], 16;" :: "r"(s), "l"(gmem));
}
#define CP_COMMIT() asm volatile("cp.async.commit_group;")
#define CP_WAIT(n)  asm volatile("cp.async.wait_group %0;" :: "n"(n))

// ---------------------------------------------------------------------------
// Weight packing (half2 kp-pairs)
// ---------------------------------------------------------------------------
__device__ __forceinline__ void pack_one(const float* __restrict__ W, int N, int i,
                                         unsigned* __restrict__ H, unsigned* __restrict__ L)
{
    int kp = i / N, n = i - kp * N;
    float x0 = W[(size_t)(2 * kp) * N + n];
    float x1 = W[(size_t)(2 * kp + 1) * N + n];
    __half h0 = __float2half_rn(x0), h1 = __float2half_rn(x1);
    __half2 hh = __halves2half2(h0, h1);
    H[i] = *(unsigned*)&hh;
    if (L) {
        __half2 ll = __floats2half2_rn(x0 - __half2float(h0), x1 - __half2float(h1));
        L[i] = *(unsigned*)&ll;
    }
}

__global__ void pack_weights(const float* Wg1, const float* Wg2, const float* Wq,
                             const float* Wk, const float* Wv, const float* Whd,
                             unsigned* Pg1, unsigned* Pg2,
                             unsigned* Pqh, unsigned* Pql,
                             unsigned* Pkh, unsigned* Pkl,
                             unsigned* Pv, unsigned* Phdh, unsigned* Phdl)
{
    int idx = blockIdx.x * 256 + threadIdx.x;
    if (idx < 262144) { pack_one(Wg1, 512, idx, Pg1, nullptr); return; }
    idx -= 262144;
    if (idx < 65536) { pack_one(Wg2, 256, idx, Pg2, nullptr); return; }
    idx -= 65536;
    if (idx < 65536) { pack_one(Wq, 256, idx, Pqh, Pql); return; }
    idx -= 65536;
    if (idx < 65536) { pack_one(Wk, 256, idx, Pkh, Pkl); return; }
    idx -= 65536;
    if (idx < 65536) { pack_one(Wv, 256, idx, Pv, nullptr); return; }
    idx -= 65536;
    if (idx < 32768) { pack_one(Whd, 256, idx, Phdh, Phdl); return; }
}

// ---------------------------------------------------------------------------
// Prep: small weight combinations (fp32)
// Wg = 16*W_equ@W_gproj [16,32]; W1 = 16*W_equ@W_gdec [16,16];
// Wvg2 = 16*W_equ@W_vg [16,256]; W2f = W_gout@W_gdec [256,16]
// ---------------------------------------------------------------------------
__global__ void prep_small(const float* __restrict__ We, const float* __restrict__ Wgp,
                           const float* __restrict__ Wgd, const float* __restrict__ Wvg,
                           const float* __restrict__ Wgo,
                           float* Wg, float* W1, float* Wvg2, float* W2f)
{
    int idx = blockIdx.x * 256 + threadIdx.x;
    if (idx < 512) {
        int m = idx >> 5, n = idx & 31;
        float a = 0;
        for (int e = 0; e < 256; e++) a += We[m * 256 + e] * Wgp[e * 32 + n];
        Wg[idx] = 16.f * a; return;
    }
    idx -= 512;
    if (idx < 256) {
        int m = idx >> 4, j = idx & 15;
        float a = 0;
        for (int e = 0; e < 256; e++) a += We[m * 256 + e] * Wgd[e * 16 + j];
        W1[idx] = 16.f * a; return;
    }
    idx -= 256;
    if (idx < 4096) {
        int m = idx >> 8, c = idx & 255;
        float a = 0;
        for (int e = 0; e < 256; e++) a += We[m * 256 + e] * Wvg[e * 256 + c];
        Wvg2[idx] = 16.f * a; return;
    }
    idx -= 4096;
    if (idx < 4096) {
        int k = idx >> 4, j = idx & 15;
        float a = 0;
        for (int e = 0; e < 256; e++) a += Wgo[k * 256 + e] * Wgd[e * 16 + j];
        W2f[idx] = a;
    }
}

// W3p = pack(W_ng @ W_hdec) [128][256] half2; bias2 = b_ng@W_hdec + b_hdec
__global__ void prep_w3(const float* __restrict__ Wng, const float* __restrict__ Whd,
                        const float* __restrict__ bng, const float* __restrict__ bhd,
                        unsigned* W3p, float* bias2)
{
    int idx = blockIdx.x * 256 + threadIdx.x;
    if (idx < 32768) {
        int kp = idx >> 8, n = idx & 255;
        float a0 = 0, a1 = 0;
        for (int e = 0; e < 256; e++) {
            float w = Whd[e * 256 + n];
            a0 += Wng[(2 * kp) * 256 + e] * w;
            a1 += Wng[(2 * kp + 1) * 256 + e] * w;
        }
        __half2 h = __floats2half2_rn(a0, a1);
        W3p[idx] = *(unsigned*)&h;
        return;
    }
    idx -= 32768;
    if (idx < 256) {
        float a = bhd[idx];
        for (int k = 0; k < 256; k++) a += bng[k] * Whd[k * 256 + idx];
        bias2[idx] = a;
    }
}

// ---------------------------------------------------------------------------
// Fused g2p + gram: per node, g2[i][a] = equ[node,i,:]@Wg[:,a]; gram from g2.
// ---------------------------------------------------------------------------
__global__ __launch_bounds__(128)
void g2p_gram(const float* __restrict__ equ, const float* __restrict__ Wg,
              __half* __restrict__ gram)
{
    __shared__ float wgs[512];
    __shared__ float es[48];
    __shared__ float g2s[96];
    int t = threadIdx.x;
    int node = blockIdx.x;
    #pragma unroll
    for (int i = 0; i < 4; i++) wgs[t + i * 128] = Wg[t + i * 128];
    if (t < 48) es[t] = equ[(size_t)node * 48 + t];
    __syncthreads();
    if (t < 96) {
        int i = t >> 5, a = t & 31;
        float acc = 0;
        #pragma unroll
        for (int k = 0; k < 16; k++) acc += es[i * 16 + k] * wgs[k * 32 + a];
        g2s[t] = acc;
    }
    __syncthreads();
    #pragma unroll
    for (int o = t; o < 1024; o += 128) {
        int a = o >> 5, b = o & 31;
        gram[(size_t)node * 1024 + o] = __float2half_rn(
            g2s[a] * g2s[b] + g2s[32 + a] * g2s[32 + b] + g2s[64 + a] * g2s[64 + b]);
    }
}

// vg = equ @ Wvg2 (K=16), half out [12288,256]
__global__ __launch_bounds__(256)
void vg_small(const float* __restrict__ equ, const float* __restrict__ Wvg2,
              __half* __restrict__ vgh)
{
    __shared__ float ws[16 * 256];
    __shared__ float es[64 * 16];
    int tid = threadIdx.x;
    #pragma unroll
    for (int i = 0; i < 16; i++) ws[tid + i * 256] = Wvg2[tid + i * 256];
    int r0 = blockIdx.x * 64;
    #pragma unroll
    for (int i = 0; i < 4; i++) {
        int idx = tid + i * 256;
        es[idx] = equ[(size_t)r0 * 16 + idx];
    }
    __syncthreads();
    for (int r = 0; r < 64; r++) {
        float acc = 0;
        #pragma unroll
        for (int k = 0; k < 16; k++) acc += es[r * 16 + k] * ws[k * 256 + tid];
        vgh[(size_t)(r0 + r) * 256 + tid] = __float2half_rn(acc);
    }
}

// h2 right half = 16h split hi/lo
__global__ void h2fill_kernel(const float* __restrict__ h,
                              __half* __restrict__ h2hi, __half* __restrict__ h2lo)
{
    int idx = blockIdx.x * blockDim.x + threadIdx.x;
    if (idx < NN * EE) {
        int r = idx >> 8, c = idx & 255;
        float v = 16.f * h[idx];
        __half hi = __float2half_rn(v);
        size_t o = (size_t)r * 512 + 256 + c;
        h2hi[o] = hi;
        h2lo[o] = __float2half_rn(v - __half2float(hi));
    }
}

// V pair repack: vpair[pair][head][n] half2 = (V[2p][f], V[2p+1][f]),
// f = head*32 + (n<32 ? n from v : vg[ch]) per attention feature layout.
__global__ void vpair_kernel(const __half* __restrict__ vh, const __half* __restrict__ vgh,
                             unsigned* __restrict__ vp)
{
    int idx = blockIdx.x * 256 + threadIdx.x;   // 2,097,152 words
    int pair = idx >> 10;
    int rem  = idx & 1023;
    int head = rem >> 7;
    int n    = rem & 127;
    int k0 = pair * 2;
    __half h0, h1;
    if (n < 32) {
        h0 = vh[(size_t)k0 * 256 + head * 32 + n];
        h1 = vh[(size_t)(k0 + 1) * 256 + head * 32 + n];
    } else {
        int ch = (n - 32) >> 5, d = (n - 32) & 31;
        h0 = vgh[((size_t)k0 * 3 + ch) * 256 + head * 32 + d];
        h1 = vgh[((size_t)(k0 + 1) * 3 + ch) * 256 + head * 32 + d];
    }
    __half2 hh = __halves2half2(h0, h1);
    vp[idx] = *(unsigned*)&hh;
}

// equ_out = equ@W1 + outg@W2f  (N=16 fused)
__global__ __launch_bounds__(256)
void equ_out_kernel(const float* __restrict__ equ, const __half* __restrict__ outg,
                    const float* __restrict__ W1, const float* __restrict__ W2,
                    float* __restrict__ out)
{
    __shared__ float w1s[256];
    __shared__ float w2s[4096];
    int tid = threadIdx.x;
    w1s[tid] = W1[tid];
    #pragma unroll
    for (int i = 0; i < 16; i++) w2s[tid + i * 256] = W2[tid + i * 256];
    __syncthreads();
    int lane = tid & 31, warp = tid >> 5;
    int row = blockIdx.x * 16 + warp * 2 + (lane >> 4);
    int j = lane & 15;
    float acc = 0;
    const float* er = equ + (size_t)row * 16;
    #pragma unroll
    for (int k = 0; k < 16; k++) acc += er[k] * w1s[k * 16 + j];
    const __half2* og = (const __half2*)(outg + (size_t)row * 256);
    #pragma unroll 8
    for (int kp = 0; kp < 128; kp++) {
        float2 v = __half22float2(og[kp]);
        acc += v.x * w2s[(2 * kp) * 16 + j] + v.y * w2s[(2 * kp + 1) * 16 + j];
    }
    out[(size_t)row * 16 + j] = acc;
}

// ---------------------------------------------------------------------------
// FP16 GEMM (m16n8k16), double-buffered cp.async, NPASS = 1 or 3.
// ---------------------------------------------------------------------------
#define HA_STR 20
#define HB_STR 136

__device__ __forceinline__ void epi_store(float v0, float v1,
                                          float* outF, __half* outH, __half* outL,
                                          size_t off)
{
    if (outF) {
        *(float2*)&outF[off] = make_float2(v0, v1);
    } else if (outL) {
        __half h0 = __float2half_rn(v0), h1 = __float2half_rn(v1);
        __half2 hh = __halves2half2(h0, h1);
        ((__half2*)outH)[off >> 1] = hh;
        ((__half2*)outL)[off >> 1] =
            __floats2half2_rn(v0 - __half2float(h0), v1 - __half2float(h1));
    } else {
        ((__half2*)outH)[off >> 1] = __floats2half2_rn(v0, v1);
    }
}

template<int NPASS, bool RELU>
__global__ __launch_bounds__(256)
void hgemm(const __half* __restrict__ A, const __half* __restrict__ Al, int lda,
           const unsigned* __restrict__ Bp, const unsigned* __restrict__ Bl, int ldbw,
           const float* __restrict__ bias,
           const float* __restrict__ Res, int ldres, float resScale, float alpha,
           float* __restrict__ outF, __half* __restrict__ outH, __half* __restrict__ outL,
           int ldc, int K)
{
    extern __shared__ unsigned smw[];
    unsigned* As  = smw;
    unsigned* Bs  = smw + 2 * 128 * HA_STR;
    unsigned* Als = Bs + 2 * 16 * HB_STR;
    unsigned* Bls = Als + 2 * 128 * HA_STR;

    const int tid  = threadIdx.x;
    const int lane = tid & 31;
    const int warp = tid >> 5;
    const int bm   = blockIdx.y * 128;
    const int bn   = blockIdx.x * 128;
    const int wM   = (warp >> 2) * 64;
    const int wN   = (warp & 3) * 32;
    const int lr   = lane >> 2;
    const int lc   = lane & 3;

    float acc[4][4][4] = {};
    const int KT = K / 32;

    #define STAGE_A(SRC, DST, K0) { \
        _Pragma("unroll") \
        for (int i = 0; i < 2; i++) { \
            int idx = tid + i * 256; \
            int row = idx >> 2, seg = idx & 3; \
            cp_async16(&(DST)[row * HA_STR + seg * 4], \
                       &(SRC)[(size_t)(bm + row) * lda + (K0) + seg * 8]); \
        } }
    #define STAGE_B(SRC, DST, K0) { \
        _Pragma("unroll") \
        for (int i = 0; i < 2; i++) { \
            int idx = tid + i * 256; \
            int kp = idx >> 5, s = idx & 31; \
            cp_async16(&(DST)[kp * HB_STR + s * 4], \
                       &(SRC)[(size_t)(((K0) >> 1) + kp) * ldbw + bn + s * 4]); \
        } }

    STAGE_A(A, As, 0);
    if (NPASS == 3) STAGE_A(Al, Als, 0);
    STAGE_B(Bp, Bs, 0);
    if (NPASS == 3) STAGE_B(Bl, Bls, 0);
    CP_COMMIT();

    for (int kt = 0; kt < KT; kt++) {
        if (kt + 1 < KT) {
            int nb = (kt + 1) & 1, k0 = (kt + 1) * 32;
            STAGE_A(A, As + nb * 128 * HA_STR, k0);
            if (NPASS == 3) STAGE_A(Al, Als + nb * 128 * HA_STR, k0);
            STAGE_B(Bp, Bs + nb * 16 * HB_STR, k0);
            if (NPASS == 3) STAGE_B(Bl, Bls + nb * 16 * HB_STR, k0);
            CP_COMMIT();
            CP_WAIT(1);
        } else {
            CP_WAIT(0);
        }
        __syncthreads();

        const unsigned* Ac  = As  + (kt & 1) * 128 * HA_STR;
        const unsigned* Bc  = Bs  + (kt & 1) * 16 * HB_STR;
        const unsigned* Alc = Als + (kt & 1) * 128 * HA_STR;
        const unsigned* Blc = Bls + (kt & 1) * 16 * HB_STR;

        #pragma unroll
        for (int ks = 0; ks < 2; ks++) {
            unsigned ah[4][4], al[4][4];
            #pragma unroll
            for (int mt = 0; mt < 4; mt++) {
                int rb = wM + mt * 16 + lr;
                int c  = ks * 8 + lc;
                ah[mt][0] = Ac[rb * HA_STR + c];
                ah[mt][1] = Ac[(rb + 8) * HA_STR + c];
                ah[mt][2] = Ac[rb * HA_STR + c + 4];
                ah[mt][3] = Ac[(rb + 8) * HA_STR + c + 4];
                if (NPASS == 3) {
                    al[mt][0] = Alc[rb * HA_STR + c];
                    al[mt][1] = Alc[(rb + 8) * HA_STR + c];
                    al[mt][2] = Alc[rb * HA_STR + c + 4];
                    al[mt][3] = Alc[(rb + 8) * HA_STR + c + 4];
                }
            }
            unsigned bh[4][2], bl[4][2];
            #pragma unroll
            for (int nt = 0; nt < 4; nt++) {
                int n  = wN + nt * 8 + lr;
                int kp = ks * 8 + lc;
                bh[nt][0] = Bc[kp * HB_STR + n];
                bh[nt][1] = Bc[(kp + 4) * HB_STR + n];
                if (NPASS == 3) {
                    bl[nt][0] = Blc[kp * HB_STR + n];
                    bl[nt][1] = Blc[(kp + 4) * HB_STR + n];
                }
            }
            #pragma unroll
            for (int mt = 0; mt < 4; mt++)
                #pragma unroll
                for (int nt = 0; nt < 4; nt++) {
                    mma_f16(acc[mt][nt], ah[mt][0], ah[mt][1], ah[mt][2], ah[mt][3],
                            bh[nt][0], bh[nt][1]);
                    if (NPASS == 3) {
                        mma_f16(acc[mt][nt], ah[mt][0], ah[mt][1], ah[mt][2], ah[mt][3],
                                bl[nt][0], bl[nt][1]);
                        mma_f16(acc[mt][nt], al[mt][0], al[mt][1], al[mt][2], al[mt][3],
                                bh[nt][0], bh[nt][1]);
                    }
                }
        }
        __syncthreads();
    }

    #pragma unroll
    for (int mt = 0; mt < 4; mt++) {
        #pragma unroll
        for (int nt = 0; nt < 4; nt++) {
            int col = bn + wN + nt * 8 + 2 * lc;
            #pragma unroll
            for (int half = 0; half < 2; half++) {
                int r = bm + wM + mt * 16 + lr + half * 8;
                float v0 = acc[mt][nt][half * 2 + 0];
                float v1 = acc[mt][nt][half * 2 + 1];
                if (bias) { v0 += bias[col]; v1 += bias[col + 1]; }
                v0 *= alpha; v1 *= alpha;
                if (Res) {
                    v0 = fmaf(resScale, Res[(size_t)r * ldres + col], v0);
                    v1 = fmaf(resScale, Res[(size_t)r * ldres + col + 1], v1);
                }
                if (RELU) { v0 = fmaxf(v0, 0.f); v1 = fmaxf(v1, 0.f); }
                epi_store(v0, v1, outF, outH, outL, (size_t)r * ldc + col);
            }
        }
    }
    #undef STAGE_A
    #undef STAGE_B
}

// ---------------------------------------------------------------------------
// Fused QKV (q/k x3 split-out, v x1). blockIdx.z = seg.
// ---------------------------------------------------------------------------
__global__ __launch_bounds__(256)
void qkv_hgemm(const __half* __restrict__ A, const __half* __restrict__ Al,
               const unsigned* __restrict__ Pqh, const unsigned* __restrict__ Pql,
               const unsigned* __restrict__ Pkh, const unsigned* __restrict__ Pkl,
               const unsigned* __restrict__ Pv,
               const float* __restrict__ bq, const float* __restrict__ bk,
               const float* __restrict__ bv,
               __half* qh, __half* ql, __half* kh, __half* kl, __half* vh,
               float scaling)
{
    extern __shared__ unsigned smw[];
    unsigned* As  = smw;
    unsigned* Bs  = smw + 2 * 128 * HA_STR;
    unsigned* Als = Bs + 2 * 16 * HB_STR;
    unsigned* Bls = Als + 2 * 128 * HA_STR;

    const int seg = blockIdx.z;
    const bool x3 = (seg < 2);
    const unsigned* Bp = (seg == 0) ? Pqh : (seg == 1) ? Pkh : Pv;
    const unsigned* Bl = (seg == 0) ? Pql : (seg == 1) ? Pkl : nullptr;
    const float* bias  = (seg == 0) ? bq : (seg == 1) ? bk : bv;
    __half* outH = (seg == 0) ? qh : (seg == 1) ? kh : vh;
    __half* outL = (seg == 0) ? ql : (seg == 1) ? kl : nullptr;
    const float alpha = (seg == 0) ? scaling : 1.f;
    const int lda = 512, ldbw = 256, ldc = 256, K = 512;

    const int tid  = threadIdx.x;
    const int lane = tid & 31;
    const int warp = tid >> 5;
    const int bm   = blockIdx.y * 128;
    const int bn   = blockIdx.x * 128;
    const int wM   = (warp >> 2) * 64;
    const int wN   = (warp & 3) * 32;
    const int lr   = lane >> 2;
    const int lc   = lane & 3;

    float acc[4][4][4] = {};

    #define QSTAGE_A(SRC, DST, K0) { \
        _Pragma("unroll") \
        for (int i = 0; i < 2; i++) { \
            int idx = tid + i * 256; \
            int row = idx >> 2, sg = idx & 3; \
            cp_async16(&(DST)[row * HA_STR + sg * 4], \
                       &(SRC)[(size_t)(bm + row) * lda + (K0) + sg * 8]); \
        } }
    #define QSTAGE_B(SRC, DST, K0) { \
        _Pragma("unroll") \
        for (int i = 0; i < 2; i++) { \
            int idx = tid + i * 256; \
            int kp = idx >> 5, s = idx & 31; \
            cp_async16(&(DST)[kp * HB_STR + s * 4], \
                       &(SRC)[(size_t)(((K0) >> 1) + kp) * ldbw + bn + s * 4]); \
        } }

    QSTAGE_A(A, As, 0);
    if (x3) QSTAGE_A(Al, Als, 0);
    QSTAGE_B(Bp, Bs, 0);
    if (x3) QSTAGE_B(Bl, Bls, 0);
    CP_COMMIT();

    const int KT = K / 32;
    for (int kt = 0; kt < KT; kt++) {
        if (kt + 1 < KT) {
            int nb = (kt + 1) & 1, k0 = (kt + 1) * 32;
            QSTAGE_A(A, As + nb * 128 * HA_STR, k0);
            if (x3) QSTAGE_A(Al, Als + nb * 128 * HA_STR, k0);
            QSTAGE_B(Bp, Bs + nb * 16 * HB_STR, k0);
            if (x3) QSTAGE_B(Bl, Bls + nb * 16 * HB_STR, k0);
            CP_COMMIT();
            CP_WAIT(1);
        } else {
            CP_WAIT(0);
        }
        __syncthreads();

        const unsigned* Ac  = As  + (kt & 1) * 128 * HA_STR;
        const unsigned* Bc  = Bs  + (kt & 1) * 16 * HB_STR;
        const unsigned* Alc = Als + (kt & 1) * 128 * HA_STR;
        const unsigned* Blc = Bls + (kt & 1) * 16 * HB_STR;

        #pragma unroll
        for (int ks = 0; ks < 2; ks++) {
            unsigned ah[4][4], al[4][4];
            #pragma unroll
            for (int mt = 0; mt < 4; mt++) {
                int rb = wM + mt * 16 + lr;
                int c  = ks * 8 + lc;
                ah[mt][0] = Ac[rb * HA_STR + c];
                ah[mt][1] = Ac[(rb + 8) * HA_STR + c];
                ah[mt][2] = Ac[rb * HA_STR + c + 4];
                ah[mt][3] = Ac[(rb + 8) * HA_STR + c + 4];
                if (x3) {
                    al[mt][0] = Alc[rb * HA_STR + c];
                    al[mt][1] = Alc[(rb + 8) * HA_STR + c];
                    al[mt][2] = Alc[rb * HA_STR + c + 4];
                    al[mt][3] = Alc[(rb + 8) * HA_STR + c + 4];
                }
            }
            unsigned bh[4][2], bl[4][2];
            #pragma unroll
            for (int nt = 0; nt < 4; nt++) {
                int n  = wN + nt * 8 + lr;
                int kp = ks * 8 + lc;
                bh[nt][0] = Bc[kp * HB_STR + n];
                bh[nt][1] = Bc[(kp + 4) * HB_STR + n];
                if (x3) {
                    bl[nt][0] = Blc[kp * HB_STR + n];
                    bl[nt][1] = Blc[(kp + 4) * HB_STR + n];
                }
            }
            #pragma unroll
            for (int mt = 0; mt < 4; mt++)
                #pragma unroll
                for (int nt = 0; nt < 4; nt++) {
                    mma_f16(acc[mt][nt], ah[mt][0], ah[mt][1], ah[mt][2], ah[mt][3],
                            bh[nt][0], bh[nt][1]);
                    if (x3) {
                        mma_f16(acc[mt][nt], ah[mt][0], ah[mt][1], ah[mt][2], ah[mt][3],
                                bl[nt][0], bl[nt][1]);
                        mma_f16(acc[mt][nt], al[mt][0], al[mt][1], al[mt][2], al[mt][3],
                                bh[nt][0], bh[nt][1]);
                    }
                }
        }
        __syncthreads();
    }

    #pragma unroll
    for (int mt = 0; mt < 4; mt++) {
        #pragma unroll
        for (int nt = 0; nt < 4; nt++) {
            int col = bn + wN + nt * 8 + 2 * lc;
            #pragma unroll
            for (int half = 0; half < 2; half++) {
                int r = bm + wM + mt * 16 + lr + half * 8;
                float v0 = (acc[mt][nt][half * 2 + 0] + bias[col]) * alpha;
                float v1 = (acc[mt][nt][half * 2 + 1] + bias[col + 1]) * alpha;
                epi_store(v0, v1, nullptr, outH, outL, (size_t)r * ldc + col);
            }
        }
    }
    #undef QSTAGE_A
    #undef QSTAGE_B
}

// ---------------------------------------------------------------------------
// Flash attention v5: pre-split q/k, pre-paired V (direct cp.async to MMA layout).
// ---------------------------------------------------------------------------
#define AQ 128
#define AK 64
#define QP 20
#define VPSTR 136

#define ATTN_WORDS (2560*4 + 4352)
#define ATTN_SMEM  (ATTN_WORDS * 4)

__global__ __launch_bounds__(256, 2)
void attn_kernel(const unsigned* __restrict__ qhiW, const unsigned* __restrict__ qloW,
                 const unsigned* __restrict__ khiW, const unsigned* __restrict__ kloW,
                 const unsigned* __restrict__ vpW,
                 __half* __restrict__ outv, __half* __restrict__ outg)
{
    extern __shared__ unsigned smw[];
    unsigned* Qhi = smw;                  // [128][QP]
    unsigned* Qlo = Qhi + 2560;
    unsigned* Khi = Qlo + 2560;           // 2 x [64][QP]
    unsigned* Klo = Khi + 2560;
    unsigned* Vp  = Klo + 2560;           // [32][VPSTR]

    const int head = blockIdx.y;
    const int qb   = blockIdx.x * AQ;
    const int tid  = threadIdx.x;
    const int lane = tid & 31;
    const int warp = tid >> 5;
    const int hofw = head * 16;
    const int hof  = head * DD;
    const int lr   = lane >> 2;
    const int lc   = lane & 3;
    const int wRow = warp * 16;

    // prologue: K(0) + Q
    {
        int key = tid >> 2, seg = tid & 3;
        cp_async16(&Khi[key * QP + seg * 4], &khiW[(size_t)key * 128 + hofw + seg * 4]);
        cp_async16(&Klo[key * QP + seg * 4], &kloW[(size_t)key * 128 + hofw + seg * 4]);
    }
    #pragma unroll
    for (int i = 0; i < 2; i++) {
        int idx = tid + i * 256;
        int row = idx >> 2, seg = idx & 3;
        cp_async16(&Qhi[row * QP + seg * 4], &qhiW[(size_t)(qb + row) * 128 + hofw + seg * 4]);
        cp_async16(&Qlo[row * QP + seg * 4], &qloW[(size_t)(qb + row) * 128 + hofw + seg * 4]);
    }
    CP_COMMIT();

    float O[16][4] = {};
    float m0 = -1e30f, m1 = -1e30f, l0 = 0.f, l1 = 0.f;

    for (int t = 0; t < NN / AK; t++) {
        const int kb = t * AK;
        __syncthreads();   // prior readers of Vp / K-alt done

        // issue V(t): 32 pairs x 128 half2, already MMA-ready
        {
            const int p0 = kb >> 1;
            #pragma unroll
            for (int i = 0; i < 4; i++) {
                int idx = tid + i * 256;
                int pr = idx >> 5, s = idx & 31;
                cp_async16(&Vp[pr * VPSTR + s * 4],
                           &vpW[((size_t)(p0 + pr)) * 1024 + head * 128 + s * 4]);
            }
        }
        CP_COMMIT();

        const bool hasNext = (t + 1 < NN / AK);
        if (hasNext) {
            unsigned* Kdh = Khi + ((t + 1) & 1) * 1280;
            unsigned* Kdl = Klo + ((t + 1) & 1) * 1280;
            int key = tid >> 2, seg = tid & 3;
            cp_async16(&Kdh[key * QP + seg * 4],
                       &khiW[(size_t)(kb + AK + key) * 128 + hofw + seg * 4]);
            cp_async16(&Kdl[key * QP + seg * 4],
                       &kloW[(size_t)(kb + AK + key) * 128 + hofw + seg * 4]);
            CP_COMMIT();
            CP_WAIT(2);   // K(t) done
        } else {
            CP_WAIT(1);
        }
        __syncthreads();

        const unsigned* Kh = Khi + (t & 1) * 1280;
        const unsigned* Kl = Klo + (t & 1) * 1280;

        #pragma unroll
        for (int half = 0; half < 2; half++) {
            // ---- S = Q K^T (fp16x3) ----
            float s[4][4] = {};
            #pragma unroll
            for (int ks = 0; ks < 2; ks++) {
                int rb = wRow + lr;
                int c  = ks * 8 + lc;
                unsigned ah0 = Qhi[rb * QP + c],     ah1 = Qhi[(rb + 8) * QP + c];
                unsigned ah2 = Qhi[rb * QP + c + 4], ah3 = Qhi[(rb + 8) * QP + c + 4];
                unsigned al0 = Qlo[rb * QP + c],     al1 = Qlo[(rb + 8) * QP + c];
                unsigned al2 = Qlo[rb * QP + c + 4], al3 = Qlo[(rb + 8) * QP + c + 4];
                #pragma unroll
                for (int nt = 0; nt < 4; nt++) {
                    int key = half * 32 + nt * 8 + lr;
                    unsigned bh0 = Kh[key * QP + c];
                    unsigned bh1 = Kh[key * QP + c + 4];
                    unsigned bl0 = Kl[key * QP + c];
                    unsigned bl1 = Kl[key * QP + c + 4];
                    mma_f16(s[nt], ah0, ah1, ah2, ah3, bh0, bh1);
                    mma_f16(s[nt], ah0, ah1, ah2, ah3, bl0, bl1);
                    mma_f16(s[nt], al0, al1, al2, al3, bh0, bh1);
                }
            }

            // ---- online softmax ----
            float mx0 = m0, mx1 = m1;
            #pragma unroll
            for (int nt = 0; nt < 4; nt++) {
                mx0 = fmaxf(mx0, fmaxf(s[nt][0], s[nt][1]));
                mx1 = fmaxf(mx1, fmaxf(s[nt][2], s[nt][3]));
            }
            mx0 = fmaxf(mx0, __shfl_xor_sync(0xffffffff, mx0, 1));
            mx0 = fmaxf(mx0, __shfl_xor_sync(0xffffffff, mx0, 2));
            mx1 = fmaxf(mx1, __shfl_xor_sync(0xffffffff, mx1, 1));
            mx1 = fmaxf(mx1, __shfl_xor_sync(0xffffffff, mx1, 2));

            float alpha0 = __expf(m0 - mx0);
            float alpha1 = __expf(m1 - mx1);
            float sum0 = 0.f, sum1 = 0.f;
            #pragma unroll
            for (int nt = 0; nt < 4; nt++) {
                s[nt][0] = __expf(s[nt][0] - mx0);
                s[nt][1] = __expf(s[nt][1] - mx0);
                s[nt][2] = __expf(s[nt][2] - mx1);
                s[nt][3] = __expf(s[nt][3] - mx1);
                sum0 += s[nt][0] + s[nt][1];
                sum1 += s[nt][2] + s[nt][3];
            }
            sum0 += __shfl_xor_sync(0xffffffff, sum0, 1);
            sum0 += __shfl_xor_sync(0xffffffff, sum0, 2);
            sum1 += __shfl_xor_sync(0xffffffff, sum1, 1);
            sum1 += __shfl_xor_sync(0xffffffff, sum1, 2);
            l0 = l0 * alpha0 + sum0;  m0 = mx0;
            l1 = l1 * alpha1 + sum1;  m1 = mx1;

            unsigned pa[2][4];
            #pragma unroll
            for (int t16 = 0; t16 < 2; t16++) {
                pa[t16][0] = h2pack(s[2 * t16][0],     s[2 * t16][1]);
                pa[t16][1] = h2pack(s[2 * t16][2],     s[2 * t16][3]);
                pa[t16][2] = h2pack(s[2 * t16 + 1][0], s[2 * t16 + 1][1]);
                pa[t16][3] = h2pack(s[2 * t16 + 1][2], s[2 * t16 + 1][3]);
            }

            #pragma unroll
            for (int nt = 0; nt < 16; nt++) {
                O[nt][0] *= alpha0; O[nt][1] *= alpha0;
                O[nt][2] *= alpha1; O[nt][3] *= alpha1;
            }

            // V arrival
            if (half == 0) {
                if (hasNext) { CP_WAIT(1); } else { CP_WAIT(0); }
                __syncthreads();
            }

            // ---- PV ----
            #pragma unroll
            for (int t16 = 0; t16 < 2; t16++) {
                int kpb = half * 16 + t16 * 8;
                #pragma unroll
                for (int nt = 0; nt < 16; nt++) {
                    int n = nt * 8 + lr;
                    unsigned b0 = Vp[(kpb + lc) * VPSTR + n];
                    unsigned b1 = Vp[(kpb + 4 + lc) * VPSTR + n];
                    mma_f16(O[nt], pa[t16][0], pa[t16][1], pa[t16][2], pa[t16][3], b0, b1);
                }
            }
        }
    }

    // epilogue
    float linv0 = 1.f / l0;
    float linv1 = 1.f / l1;
    int r0 = qb + wRow + lr;
    int r1 = r0 + 8;
    unsigned* outvW = (unsigned*)outv;
    unsigned* outgW = (unsigned*)outg;
    #pragma unroll
    for (int nt = 0; nt < 16; nt++) {
        int c = nt * 8 + 2 * lc;
        unsigned w0 = h2pack(O[nt][0] * linv0, O[nt][1] * linv0);
        unsigned w1 = h2pack(O[nt][2] * linv1, O[nt][3] * linv1);
        if (c < 32) {
            outvW[(size_t)r0 * 128 + (hof + c) / 2] = w0;
            outvW[(size_t)r1 * 128 + (hof + c) / 2] = w1;
        } else {
            int ch = (c - 32) >> 5;
            int d  = (c - 32) & 31;
            outgW[((size_t)r0 * 3 + ch) * 128 + (hof + d) / 2] = w0;
            outgW[((size_t)r1 * 3 + ch) * 128 + (hof + d) / 2] = w1;
        }
    }
}

// ---------------------------------------------------------------------------
// Host orchestration (multi-stream fork/join, capture-safe)
// ---------------------------------------------------------------------------
extern "C" void kernel_launch(void* const* d_in, const int* in_sizes, int n_in,
                              void* d_out, int out_size)
{
    const float* equ    = (const float*)d_in[0];
    const float* h      = (const float*)d_in[1];
    const float* W_equ  = (const float*)d_in[4];
    const float* W_gproj= (const float*)d_in[5];
    const float* W_vg   = (const float*)d_in[6];
    const float* W_g1   = (const float*)d_in[7];
    const float* b_g1   = (const float*)d_in[8];
    const float* W_g2   = (const float*)d_in[9];
    const float* b_g2   = (const float*)d_in[10];
    const float* W_q    = (const float*)d_in[11];
    const float* b_q    = (const float*)d_in[12];
    const float* W_k    = (const float*)d_in[13];
    const float* b_k    = (const float*)d_in[14];
    const float* W_v    = (const float*)d_in[15];
    const float* b_v    = (const float*)d_in[16];
    const float* W_ng   = (const float*)d_in[17];
    const float* b_ng   = (const float*)d_in[18];
    const float* W_gout = (const float*)d_in[19];
    const float* W_gdec = (const float*)d_in[20];
    const float* W_hdec = (const float*)d_in[21];
    const float* b_hdec = (const float*)d_in[22];

    float* out = (float*)d_out;

    static cudaStream_t s1 = nullptr, s2 = nullptr;
    static cudaEvent_t evRoot, evPrep, evPack, evH2, evVg, evAttn, evS1, evHout;
    if (!s1) {
        cudaStreamCreateWithFlags(&s1, cudaStreamNonBlocking);
        cudaStreamCreateWithFlags(&s2, cudaStreamNonBlocking);
        cudaEventCreateWithFlags(&evRoot, cudaEventDisableTiming);
        cudaEventCreateWithFlags(&evPrep, cudaEventDisableTiming);
        cudaEventCreateWithFlags(&evPack, cudaEventDisableTiming);
        cudaEventCreateWithFlags(&evH2, cudaEventDisableTiming);
        cudaEventCreateWithFlags(&evVg, cudaEventDisableTiming);
        cudaEventCreateWithFlags(&evAttn, cudaEventDisableTiming);
        cudaEventCreateWithFlags(&evS1, cudaEventDisableTiming);
        cudaEventCreateWithFlags(&evHout, cudaEventDisableTiming);
    }

    float* S = nullptr;
    cudaGetSymbolAddress((void**)&S, scratch);

    const int SM1 = (2 * 128 * HA_STR + 2 * 16 * HB_STR) * 4;
    const int SM3 = SM1 * 2;
    cudaFuncSetAttribute(hgemm<1, true>,  cudaFuncAttributeMaxDynamicSharedMemorySize, SM1);
    cudaFuncSetAttribute(hgemm<1, false>, cudaFuncAttributeMaxDynamicSharedMemorySize, SM1);
    cudaFuncSetAttribute(hgemm<3, false>, cudaFuncAttributeMaxDynamicSharedMemorySize, SM3);
    cudaFuncSetAttribute(qkv_hgemm, cudaFuncAttributeMaxDynamicSharedMemorySize, SM3);
    cudaFuncSetAttribute(attn_kernel, cudaFuncAttributeMaxDynamicSharedMemorySize, ATTN_SMEM);

    __half* gram_h = (__half*)(S + OFF_GRAM);
    __half* hid_h  = (__half*)(S + OFF_HID);
    __half* h2hi   = (__half*)(S + OFF_H2HI);
    __half* h2lo   = (__half*)(S + OFF_H2LO);
    __half* qhi    = (__half*)(S + OFF_QHI);
    __half* qlo    = (__half*)(S + OFF_QLO);
    __half* khi    = (__half*)(S + OFF_KHI);
    __half* klo    = (__half*)(S + OFF_KLO);
    __half* vh     = (__half*)(S + OFF_VH);
    __half* vgh    = (__half*)(S + OFF_VGH);
    unsigned* vpair= (unsigned*)(S + OFF_VPAIR);
    __half* outv_h = (__half*)(S + OFF_OUTV);
    __half* outg_h = (__half*)(S + OFF_OUTG);
    float*  hpre   = S + OFF_HPRE;
    unsigned* Pg1  = (unsigned*)(S + OFF_PG1);
    unsigned* Pg2  = (unsigned*)(S + OFF_PG2);
    unsigned* Pqh  = (unsigned*)(S + OFF_PQH);
    unsigned* Pql  = (unsigned*)(S + OFF_PQL);
    unsigned* Pkh  = (unsigned*)(S + OFF_PKH);
    unsigned* Pkl  = (unsigned*)(S + OFF_PKL);
    unsigned* Pv   = (unsigned*)(S + OFF_PV);
    unsigned* Phdh = (unsigned*)(S + OFF_PHDH);
    unsigned* Phdl = (unsigned*)(S + OFF_PHDL);
    unsigned* W3p  = (unsigned*)(S + OFF_W3P);
    float* Wg      = S + OFF_WG;
    float* W1      = S + OFF_W1;
    float* Wvg2    = S + OFF_WVG2;
    float* W2f     = S + OFF_W2F;
    float* bias2   = S + OFF_BIAS2;

    const float scaling = 0.17677669529663687f;

    // ---- fork ----
    cudaEventRecord(evRoot, 0);
    cudaStreamWaitEvent(s1, evRoot, 0);
    cudaStreamWaitEvent(s2, evRoot, 0);

    // s2: h2fill early (only needs h)
    h2fill_kernel<<<(NN * EE + 255) / 256, 256, 0, s2>>>(h, h2hi, h2lo);
    cudaEventRecord(evH2, s2);

    // s1: weight packing + W3/bias2 + hpre
    pack_weights<<<2176, 256, 0, s1>>>(W_g1, W_g2, W_q, W_k, W_v, W_hdec,
                                       Pg1, Pg2, Pqh, Pql, Pkh, Pkl, Pv, Phdh, Phdl);
    cudaEventRecord(evPack, s1);
    prep_w3<<<129, 256, 0, s1>>>(W_ng, W_hdec, b_ng, b_hdec, W3p, bias2);
    cudaStreamWaitEvent(s1, evH2, 0);
    // hpre = 16h@W_hdec + bias2 (fp16x3, A = right half of h2)
    hgemm<3, false><<<dim3(2, 32), 256, SM3, s1>>>(h2hi + 256, h2lo + 256, 512,
                                                   Phdh, Phdl, 256,
                                                   bias2, nullptr, 0, 0.f, 1.f,
                                                   hpre, nullptr, nullptr, 256, 256);
    cudaEventRecord(evS1, s1);

    // main: prep combos
    prep_small<<<35, 256>>>(W_equ, W_gproj, W_gdec, W_vg, W_gout, Wg, W1, Wvg2, W2f);
    cudaEventRecord(evPrep, 0);

    // s2: vg = equ @ Wvg2
    cudaStreamWaitEvent(s2, evPrep, 0);
    vg_small<<<192, 256, 0, s2>>>(equ, Wvg2, vgh);
    cudaEventRecord(evVg, s2);

    // main: gram -> MLP -> qkv -> vpair -> attention
    g2p_gram<<<NN, 128>>>(equ, Wg, gram_h);
    cudaStreamWaitEvent(0, evPack, 0);
    hgemm<1, true><<<dim3(4, 32), 256, SM1>>>(gram_h, nullptr, 1024, Pg1, nullptr, 512,
                                              b_g1, nullptr, 0, 0.f, 1.f,
                                              nullptr, hid_h, nullptr, 512, 1024);
    hgemm<1, false><<<dim3(2, 32), 256, SM1>>>(hid_h, nullptr, 512, Pg2, nullptr, 256,
                                               b_g2, nullptr, 0, 0.f, 1.f,
                                               nullptr, h2hi, h2lo, 512, 512);
    cudaStreamWaitEvent(0, evH2, 0);
    qkv_hgemm<<<dim3(2, 32, 3), 256, SM3>>>(h2hi, h2lo, Pqh, Pql, Pkh, Pkl, Pv,
                                            b_q, b_k, b_v, qhi, qlo, khi, klo, vh, scaling);
    cudaStreamWaitEvent(0, evVg, 0);
    vpair_kernel<<<8192, 256>>>(vh, vgh, vpair);
    attn_kernel<<<dim3(NN / AQ, HH), 256, ATTN_SMEM>>>(
        (const unsigned*)qhi, (const unsigned*)qlo,
        (const unsigned*)khi, (const unsigned*)klo,
        vpair, outv_h, outg_h);
    cudaEventRecord(evAttn, 0);

    // s2: h_out = outv@W3 + hpre
    cudaStreamWaitEvent(s2, evAttn, 0);
    cudaStreamWaitEvent(s2, evS1, 0);
    hgemm<1, false><<<dim3(2, 32), 256, SM1, s2>>>(outv_h, nullptr, 256, W3p, nullptr, 256,
                                                   nullptr, hpre, 256, 1.f, 1.f,
                                                   out + (size_t)ROWS * MMDIM,
                                                   nullptr, nullptr, 256, 256);
    cudaEventRecord(evHout, s2);

    // main: equ_out = equ@W1 + outg@W2f
    equ_out_kernel<<<768, 256>>>(equ, outg_h, W1, W2f, out);

    // ---- join ----
    cudaStreamWaitEvent(0, evHout, 0);
}

// round 7
// speedup vs baseline: 6.2087x; 1.0105x over previous
#include <cuda_runtime.h>
#include <cuda_fp16.h>
#include <math.h>

#define NN 4096
#define NV 3
#define MMDIM 16
#define EE 256
#define HH 8
#define DD 32
#define ROWS (NN*NV)

__device__ float scratch[26607616];

// word offsets
#define OFF_GRAM    0u          // h16 [4096,1024]
#define OFF_HID     2097152u    // h16 [4096,512]
#define OFF_H2HI    3145728u    // h16 [4096,512]
#define OFF_H2LO    4194304u
#define OFF_QHI     5242880u    // h16 [4096,256]
#define OFF_QLO     5767168u
#define OFF_KHI     6291456u
#define OFF_KLO     6815744u
#define OFF_VPAIR   9437184u    // half2 [2048][8][128]
#define OFF_OUTV    11534336u   // h16 [4096,256]
#define OFF_OUTG    12058624u   // h16 [12288,256]
#define OFF_HPRE    13631488u   // f32 [4096,256]
#define OFF_PG1     14680064u
#define OFF_PG2     14942208u
#define OFF_PQH     15007744u
#define OFF_PQL     15073280u
#define OFF_PKH     15138816u
#define OFF_PKL     15204352u
#define OFF_PV      15269888u
#define OFF_PHDH    15335424u
#define OFF_PHDL    15368192u
#define OFF_W3P     15400960u
#define OFF_WG      15433728u
#define OFF_W1      15434240u
#define OFF_WVG2    15434496u
#define OFF_W2F     15438592u
#define OFF_BIAS2   15442688u

// ---------------------------------------------------------------------------
// helpers
// ---------------------------------------------------------------------------
__device__ __forceinline__ void mma_f16(float c[4],
                                        unsigned a0, unsigned a1, unsigned a2, unsigned a3,
                                        unsigned b0, unsigned b1) {
    asm volatile(
        "mma.sync.aligned.m16n8k16.row.col.f32.f16.f16.f32 "
        "{%0,%1,%2,%3}, {%4,%5,%6,%7}, {%8,%9}, {%0,%1,%2,%3};"
        : "+f"(c[0]), "+f"(c[1]), "+f"(c[2]), "+f"(c[3])
        : "r"(a0), "r"(a1), "r"(a2), "r"(a3), "r"(b0), "r"(b1));
}

__device__ __forceinline__ unsigned h2pack(float a, float b) {
    __half2 h = __floats2half2_rn(a, b);
    return *(unsigned*)&h;
}

__device__ __forceinline__ void cp_async16(void* smem, const void* gmem) {
    unsigned s = (unsigned)__cvta_generic_to_shared(smem);
    asm volatile("cp.async.cg.shared.global [%0], [%1], 16;" :: "r"(s), "l"(gmem));
}
#define CP_COMMIT() asm volatile("cp.async.commit_group;")
#define CP_WAIT(n)  asm volatile("cp.async.wait_group %0;" :: "n"(n))

// ---------------------------------------------------------------------------
// Weight packing (half2 kp-pairs)
// ---------------------------------------------------------------------------
__device__ __forceinline__ void pack_one(const float* __restrict__ W, int N, int i,
                                         unsigned* __restrict__ H, unsigned* __restrict__ L)
{
    int kp = i / N, n = i - kp * N;
    float x0 = W[(size_t)(2 * kp) * N + n];
    float x1 = W[(size_t)(2 * kp + 1) * N + n];
    __half h0 = __float2half_rn(x0), h1 = __float2half_rn(x1);
    __half2 hh = __halves2half2(h0, h1);
    H[i] = *(unsigned*)&hh;
    if (L) {
        __half2 ll = __floats2half2_rn(x0 - __half2float(h0), x1 - __half2float(h1));
        L[i] = *(unsigned*)&ll;
    }
}

__global__ void pack_weights(const float* Wg1, const float* Wg2, const float* Wq,
                             const float* Wk, const float* Wv, const float* Whd,
                             unsigned* Pg1, unsigned* Pg2,
                             unsigned* Pqh, unsigned* Pql,
                             unsigned* Pkh, unsigned* Pkl,
                             unsigned* Pv, unsigned* Phdh, unsigned* Phdl)
{
    int idx = blockIdx.x * 256 + threadIdx.x;
    if (idx < 262144) { pack_one(Wg1, 512, idx, Pg1, nullptr); return; }
    idx -= 262144;
    if (idx < 65536) { pack_one(Wg2, 256, idx, Pg2, nullptr); return; }
    idx -= 65536;
    if (idx < 65536) { pack_one(Wq, 256, idx, Pqh, Pql); return; }
    idx -= 65536;
    if (idx < 65536) { pack_one(Wk, 256, idx, Pkh, Pkl); return; }
    idx -= 65536;
    if (idx < 65536) { pack_one(Wv, 256, idx, Pv, nullptr); return; }
    idx -= 65536;
    if (idx < 32768) { pack_one(Whd, 256, idx, Phdh, Phdl); return; }
}

// ---------------------------------------------------------------------------
// Prep: small weight combinations (fp32)
// ---------------------------------------------------------------------------
__global__ void prep_small(const float* __restrict__ We, const float* __restrict__ Wgp,
                           const float* __restrict__ Wgd, const float* __restrict__ Wvg,
                           const float* __restrict__ Wgo,
                           float* Wg, float* W1, float* Wvg2, float* W2f)
{
    int idx = blockIdx.x * 256 + threadIdx.x;
    if (idx < 512) {
        int m = idx >> 5, n = idx & 31;
        float a = 0;
        for (int e = 0; e < 256; e++) a += We[m * 256 + e] * Wgp[e * 32 + n];
        Wg[idx] = 16.f * a; return;
    }
    idx -= 512;
    if (idx < 256) {
        int m = idx >> 4, j = idx & 15;
        float a = 0;
        for (int e = 0; e < 256; e++) a += We[m * 256 + e] * Wgd[e * 16 + j];
        W1[idx] = 16.f * a; return;
    }
    idx -= 256;
    if (idx < 4096) {
        int m = idx >> 8, c = idx & 255;
        float a = 0;
        for (int e = 0; e < 256; e++) a += We[m * 256 + e] * Wvg[e * 256 + c];
        Wvg2[idx] = 16.f * a; return;
    }
    idx -= 4096;
    if (idx < 4096) {
        int k = idx >> 4, j = idx & 15;
        float a = 0;
        for (int e = 0; e < 256; e++) a += Wgo[k * 256 + e] * Wgd[e * 16 + j];
        W2f[idx] = a;
    }
}

// W3p = pack(W_ng @ W_hdec); bias2 = b_ng@W_hdec + b_hdec
__global__ void prep_w3(const float* __restrict__ Wng, const float* __restrict__ Whd,
                        const float* __restrict__ bng, const float* __restrict__ bhd,
                        unsigned* W3p, float* bias2)
{
    int idx = blockIdx.x * 256 + threadIdx.x;
    if (idx < 32768) {
        int kp = idx >> 8, n = idx & 255;
        float a0 = 0, a1 = 0;
        for (int e = 0; e < 256; e++) {
            float w = Whd[e * 256 + n];
            a0 += Wng[(2 * kp) * 256 + e] * w;
            a1 += Wng[(2 * kp + 1) * 256 + e] * w;
        }
        __half2 h = __floats2half2_rn(a0, a1);
        W3p[idx] = *(unsigned*)&h;
        return;
    }
    idx -= 32768;
    if (idx < 256) {
        float a = bhd[idx];
        for (int k = 0; k < 256; k++) a += bng[k] * Whd[k * 256 + idx];
        bias2[idx] = a;
    }
}

// ---------------------------------------------------------------------------
// Fused g2p + gram
// ---------------------------------------------------------------------------
__global__ __launch_bounds__(128)
void g2p_gram(const float* __restrict__ equ, const float* __restrict__ Wg,
              __half* __restrict__ gram)
{
    __shared__ float wgs[512];
    __shared__ float es[48];
    __shared__ float g2s[96];
    int t = threadIdx.x;
    int node = blockIdx.x;
    #pragma unroll
    for (int i = 0; i < 4; i++) wgs[t + i * 128] = Wg[t + i * 128];
    if (t < 48) es[t] = equ[(size_t)node * 48 + t];
    __syncthreads();
    if (t < 96) {
        int i = t >> 5, a = t & 31;
        float acc = 0;
        #pragma unroll
        for (int k = 0; k < 16; k++) acc += es[i * 16 + k] * wgs[k * 32 + a];
        g2s[t] = acc;
    }
    __syncthreads();
    #pragma unroll
    for (int o = t; o < 1024; o += 128) {
        int a = o >> 5, b = o & 31;
        gram[(size_t)node * 1024 + o] = __float2half_rn(
            g2s[a] * g2s[b] + g2s[32 + a] * g2s[32 + b] + g2s[64 + a] * g2s[64 + b]);
    }
}

// vg = equ @ Wvg2 (K=16), written directly into paired attention layout.
// row r = node*3+ch, col tid = head*32+d -> vpair half index
// ((node>>1)*1024 + head*128 + 32 + ch*32 + d)*2 + (node&1)
__global__ __launch_bounds__(256)
void vg_small(const float* __restrict__ equ, const float* __restrict__ Wvg2,
              __half* __restrict__ vpH)
{
    __shared__ float ws[16 * 256];
    __shared__ float es[64 * 16];
    int tid = threadIdx.x;
    #pragma unroll
    for (int i = 0; i < 16; i++) ws[tid + i * 256] = Wvg2[tid + i * 256];
    int r0 = blockIdx.x * 64;
    #pragma unroll
    for (int i = 0; i < 4; i++) {
        int idx = tid + i * 256;
        es[idx] = equ[(size_t)r0 * 16 + idx];
    }
    __syncthreads();
    const int head = tid >> 5, d = tid & 31;
    for (int r = 0; r < 64; r++) {
        float acc = 0;
        #pragma unroll
        for (int k = 0; k < 16; k++) acc += es[r * 16 + k] * ws[k * 256 + tid];
        int gr = r0 + r;
        int node = gr / 3;
        int ch = gr - 3 * node;
        size_t w = ((size_t)(node >> 1) * 1024 + head * 128 + 32 + ch * 32 + d) * 2 + (node & 1);
        vpH[w] = __float2half_rn(acc);
    }
}

// h2 right half = 16h split hi/lo
__global__ void h2fill_kernel(const float* __restrict__ h,
                              __half* __restrict__ h2hi, __half* __restrict__ h2lo)
{
    int idx = blockIdx.x * blockDim.x + threadIdx.x;
    if (idx < NN * EE) {
        int r = idx >> 8, c = idx & 255;
        float v = 16.f * h[idx];
        __half hi = __float2half_rn(v);
        size_t o = (size_t)r * 512 + 256 + c;
        h2hi[o] = hi;
        h2lo[o] = __float2half_rn(v - __half2float(hi));
    }
}

// equ_out = equ@W1 + outg@W2f  (N=16 fused)
__global__ __launch_bounds__(256)
void equ_out_kernel(const float* __restrict__ equ, const __half* __restrict__ outg,
                    const float* __restrict__ W1, const float* __restrict__ W2,
                    float* __restrict__ out)
{
    __shared__ float w1s[256];
    __shared__ float w2s[4096];
    int tid = threadIdx.x;
    w1s[tid] = W1[tid];
    #pragma unroll
    for (int i = 0; i < 16; i++) w2s[tid + i * 256] = W2[tid + i * 256];
    __syncthreads();
    int lane = tid & 31, warp = tid >> 5;
    int row = blockIdx.x * 16 + warp * 2 + (lane >> 4);
    int j = lane & 15;
    float acc = 0;
    const float* er = equ + (size_t)row * 16;
    #pragma unroll
    for (int k = 0; k < 16; k++) acc += er[k] * w1s[k * 16 + j];
    const __half2* og = (const __half2*)(outg + (size_t)row * 256);
    #pragma unroll 8
    for (int kp = 0; kp < 128; kp++) {
        float2 v = __half22float2(og[kp]);
        acc += v.x * w2s[(2 * kp) * 16 + j] + v.y * w2s[(2 * kp + 1) * 16 + j];
    }
    out[(size_t)row * 16 + j] = acc;
}

// ---------------------------------------------------------------------------
// FP16 GEMM (m16n8k16), 3-stage cp.async pipeline, NPASS = 1 or 3.
// ---------------------------------------------------------------------------
#define HA_STR 20
#define HB_STR 136
#define ASZ (128*HA_STR)
#define BSZ (16*HB_STR)

__device__ __forceinline__ void epi_store(float v0, float v1,
                                          float* outF, __half* outH, __half* outL,
                                          size_t off)
{
    if (outF) {
        *(float2*)&outF[off] = make_float2(v0, v1);
    } else if (outL) {
        __half h0 = __float2half_rn(v0), h1 = __float2half_rn(v1);
        __half2 hh = __halves2half2(h0, h1);
        ((__half2*)outH)[off >> 1] = hh;
        ((__half2*)outL)[off >> 1] =
            __floats2half2_rn(v0 - __half2float(h0), v1 - __half2float(h1));
    } else {
        ((__half2*)outH)[off >> 1] = __floats2half2_rn(v0, v1);
    }
}

#define STAGE_A_G(SRC, DST, K0) { \
    _Pragma("unroll") \
    for (int i = 0; i < 2; i++) { \
        int idx = tid + i * 256; \
        int row = idx >> 2, seg = idx & 3; \
        cp_async16(&(DST)[row * HA_STR + seg * 4], \
                   &(SRC)[(size_t)(bm + row) * lda + (K0) + seg * 8]); \
    } }
#define STAGE_B_G(SRC, DST, K0) { \
    _Pragma("unroll") \
    for (int i = 0; i < 2; i++) { \
        int idx = tid + i * 256; \
        int kp = idx >> 5, s = idx & 31; \
        cp_async16(&(DST)[kp * HB_STR + s * 4], \
                   &(SRC)[(size_t)(((K0) >> 1) + kp) * ldbw + bn + s * 4]); \
    } }

template<int NPASS, bool RELU>
__global__ __launch_bounds__(256)
void hgemm(const __half* __restrict__ A, const __half* __restrict__ Al, int lda,
           const unsigned* __restrict__ Bp, const unsigned* __restrict__ Bl, int ldbw,
           const float* __restrict__ bias,
           const float* __restrict__ Res, int ldres, float resScale, float alpha,
           float* __restrict__ outF, __half* __restrict__ outH, __half* __restrict__ outL,
           int ldc, int K)
{
    extern __shared__ unsigned smw[];
    unsigned* As  = smw;                 // 3 stages
    unsigned* Bs  = smw + 3 * ASZ;
    unsigned* Als = Bs + 3 * BSZ;
    unsigned* Bls = Als + 3 * ASZ;

    const int tid  = threadIdx.x;
    const int lane = tid & 31;
    const int warp = tid >> 5;
    const int bm   = blockIdx.y * 128;
    const int bn   = blockIdx.x * 128;
    const int wM   = (warp >> 2) * 64;
    const int wN   = (warp & 3) * 32;
    const int lr   = lane >> 2;
    const int lc   = lane & 3;

    float acc[4][4][4] = {};
    const int KT = K / 32;   // assume >= 3

    // prologue: stages 0, 1
    STAGE_A_G(A, As, 0);
    if (NPASS == 3) STAGE_A_G(Al, Als, 0);
    STAGE_B_G(Bp, Bs, 0);
    if (NPASS == 3) STAGE_B_G(Bl, Bls, 0);
    CP_COMMIT();
    STAGE_A_G(A, As + ASZ, 32);
    if (NPASS == 3) STAGE_A_G(Al, Als + ASZ, 32);
    STAGE_B_G(Bp, Bs + BSZ, 32);
    if (NPASS == 3) STAGE_B_G(Bl, Bls + BSZ, 32);
    CP_COMMIT();

    int scur = 0;
    for (int kt = 0; kt < KT; kt++) {
        if (kt + 2 < KT) {
            int s2 = scur + 2; if (s2 >= 3) s2 -= 3;
            int k0 = (kt + 2) * 32;
            STAGE_A_G(A, As + s2 * ASZ, k0);
            if (NPASS == 3) STAGE_A_G(Al, Als + s2 * ASZ, k0);
            STAGE_B_G(Bp, Bs + s2 * BSZ, k0);
            if (NPASS == 3) STAGE_B_G(Bl, Bls + s2 * BSZ, k0);
            CP_COMMIT();
            CP_WAIT(2);
        } else if (kt + 1 < KT) {
            CP_WAIT(1);
        } else {
            CP_WAIT(0);
        }
        __syncthreads();

        const unsigned* Ac  = As  + scur * ASZ;
        const unsigned* Bc  = Bs  + scur * BSZ;
        const unsigned* Alc = Als + scur * ASZ;
        const unsigned* Blc = Bls + scur * BSZ;

        #pragma unroll
        for (int ks = 0; ks < 2; ks++) {
            unsigned ah[4][4], al[4][4];
            #pragma unroll
            for (int mt = 0; mt < 4; mt++) {
                int rb = wM + mt * 16 + lr;
                int c  = ks * 8 + lc;
                ah[mt][0] = Ac[rb * HA_STR + c];
                ah[mt][1] = Ac[(rb + 8) * HA_STR + c];
                ah[mt][2] = Ac[rb * HA_STR + c + 4];
                ah[mt][3] = Ac[(rb + 8) * HA_STR + c + 4];
                if (NPASS == 3) {
                    al[mt][0] = Alc[rb * HA_STR + c];
                    al[mt][1] = Alc[(rb + 8) * HA_STR + c];
                    al[mt][2] = Alc[rb * HA_STR + c + 4];
                    al[mt][3] = Alc[(rb + 8) * HA_STR + c + 4];
                }
            }
            unsigned bh[4][2], bl[4][2];
            #pragma unroll
            for (int nt = 0; nt < 4; nt++) {
                int n  = wN + nt * 8 + lr;
                int kp = ks * 8 + lc;
                bh[nt][0] = Bc[kp * HB_STR + n];
                bh[nt][1] = Bc[(kp + 4) * HB_STR + n];
                if (NPASS == 3) {
                    bl[nt][0] = Blc[kp * HB_STR + n];
                    bl[nt][1] = Blc[(kp + 4) * HB_STR + n];
                }
            }
            #pragma unroll
            for (int mt = 0; mt < 4; mt++)
                #pragma unroll
                for (int nt = 0; nt < 4; nt++) {
                    mma_f16(acc[mt][nt], ah[mt][0], ah[mt][1], ah[mt][2], ah[mt][3],
                            bh[nt][0], bh[nt][1]);
                    if (NPASS == 3) {
                        mma_f16(acc[mt][nt], ah[mt][0], ah[mt][1], ah[mt][2], ah[mt][3],
                                bl[nt][0], bl[nt][1]);
                        mma_f16(acc[mt][nt], al[mt][0], al[mt][1], al[mt][2], al[mt][3],
                                bh[nt][0], bh[nt][1]);
                    }
                }
        }
        __syncthreads();
        scur = scur + 1; if (scur == 3) scur = 0;
    }

    #pragma unroll
    for (int mt = 0; mt < 4; mt++) {
        #pragma unroll
        for (int nt = 0; nt < 4; nt++) {
            int col = bn + wN + nt * 8 + 2 * lc;
            #pragma unroll
            for (int half = 0; half < 2; half++) {
                int r = bm + wM + mt * 16 + lr + half * 8;
                float v0 = acc[mt][nt][half * 2 + 0];
                float v1 = acc[mt][nt][half * 2 + 1];
                if (bias) { v0 += bias[col]; v1 += bias[col + 1]; }
                v0 *= alpha; v1 *= alpha;
                if (Res) {
                    v0 = fmaf(resScale, Res[(size_t)r * ldres + col], v0);
                    v1 = fmaf(resScale, Res[(size_t)r * ldres + col + 1], v1);
                }
                if (RELU) { v0 = fmaxf(v0, 0.f); v1 = fmaxf(v1, 0.f); }
                epi_store(v0, v1, outF, outH, outL, (size_t)r * ldc + col);
            }
        }
    }
}

// ---------------------------------------------------------------------------
// Fused QKV (q/k x3 split-out; v x1 written directly into vpair layout).
// ---------------------------------------------------------------------------
__global__ __launch_bounds__(256)
void qkv_hgemm(const __half* __restrict__ A, const __half* __restrict__ Al,
               const unsigned* __restrict__ Pqh, const unsigned* __restrict__ Pql,
               const unsigned* __restrict__ Pkh, const unsigned* __restrict__ Pkl,
               const unsigned* __restrict__ Pv,
               const float* __restrict__ bq, const float* __restrict__ bk,
               const float* __restrict__ bv,
               __half* qh, __half* ql, __half* kh, __half* kl,
               __half* __restrict__ vpH,
               float scaling)
{
    extern __shared__ unsigned smw[];
    unsigned* As  = smw;
    unsigned* Bs  = smw + 3 * ASZ;
    unsigned* Als = Bs + 3 * BSZ;
    unsigned* Bls = Als + 3 * ASZ;

    const int seg = blockIdx.z;
    const bool x3 = (seg < 2);
    const unsigned* Bp = (seg == 0) ? Pqh : (seg == 1) ? Pkh : Pv;
    const unsigned* Bl = (seg == 0) ? Pql : (seg == 1) ? Pkl : nullptr;
    const float* bias  = (seg == 0) ? bq : (seg == 1) ? bk : bv;
    __half* outH = (seg == 0) ? qh : kh;
    __half* outL = (seg == 0) ? ql : kl;
    const float alpha = (seg == 0) ? scaling : 1.f;
    const int lda = 512, ldbw = 256, ldc = 256, K = 512;

    const int tid  = threadIdx.x;
    const int lane = tid & 31;
    const int warp = tid >> 5;
    const int bm   = blockIdx.y * 128;
    const int bn   = blockIdx.x * 128;
    const int wM   = (warp >> 2) * 64;
    const int wN   = (warp & 3) * 32;
    const int lr   = lane >> 2;
    const int lc   = lane & 3;

    float acc[4][4][4] = {};
    const int KT = K / 32;   // 16

    STAGE_A_G(A, As, 0);
    if (x3) STAGE_A_G(Al, Als, 0);
    STAGE_B_G(Bp, Bs, 0);
    if (x3) STAGE_B_G(Bl, Bls, 0);
    CP_COMMIT();
    STAGE_A_G(A, As + ASZ, 32);
    if (x3) STAGE_A_G(Al, Als + ASZ, 32);
    STAGE_B_G(Bp, Bs + BSZ, 32);
    if (x3) STAGE_B_G(Bl, Bls + BSZ, 32);
    CP_COMMIT();

    int scur = 0;
    for (int kt = 0; kt < KT; kt++) {
        if (kt + 2 < KT) {
            int s2 = scur + 2; if (s2 >= 3) s2 -= 3;
            int k0 = (kt + 2) * 32;
            STAGE_A_G(A, As + s2 * ASZ, k0);
            if (x3) STAGE_A_G(Al, Als + s2 * ASZ, k0);
            STAGE_B_G(Bp, Bs + s2 * BSZ, k0);
            if (x3) STAGE_B_G(Bl, Bls + s2 * BSZ, k0);
            CP_COMMIT();
            CP_WAIT(2);
        } else if (kt + 1 < KT) {
            CP_WAIT(1);
        } else {
            CP_WAIT(0);
        }
        __syncthreads();

        const unsigned* Ac  = As  + scur * ASZ;
        const unsigned* Bc  = Bs  + scur * BSZ;
        const unsigned* Alc = Als + scur * ASZ;
        const unsigned* Blc = Bls + scur * BSZ;

        #pragma unroll
        for (int ks = 0; ks < 2; ks++) {
            unsigned ah[4][4], al[4][4];
            #pragma unroll
            for (int mt = 0; mt < 4; mt++) {
                int rb = wM + mt * 16 + lr;
                int c  = ks * 8 + lc;
                ah[mt][0] = Ac[rb * HA_STR + c];
                ah[mt][1] = Ac[(rb + 8) * HA_STR + c];
                ah[mt][2] = Ac[rb * HA_STR + c + 4];
                ah[mt][3] = Ac[(rb + 8) * HA_STR + c + 4];
                if (x3) {
                    al[mt][0] = Alc[rb * HA_STR + c];
                    al[mt][1] = Alc[(rb + 8) * HA_STR + c];
                    al[mt][2] = Alc[rb * HA_STR + c + 4];
                    al[mt][3] = Alc[(rb + 8) * HA_STR + c + 4];
                }
            }
            unsigned bh[4][2], bl[4][2];
            #pragma unroll
            for (int nt = 0; nt < 4; nt++) {
                int n  = wN + nt * 8 + lr;
                int kp = ks * 8 + lc;
                bh[nt][0] = Bc[kp * HB_STR + n];
                bh[nt][1] = Bc[(kp + 4) * HB_STR + n];
                if (x3) {
                    bl[nt][0] = Blc[kp * HB_STR + n];
                    bl[nt][1] = Blc[(kp + 4) * HB_STR + n];
                }
            }
            #pragma unroll
            for (int mt = 0; mt < 4; mt++)
                #pragma unroll
                for (int nt = 0; nt < 4; nt++) {
                    mma_f16(acc[mt][nt], ah[mt][0], ah[mt][1], ah[mt][2], ah[mt][3],
                            bh[nt][0], bh[nt][1]);
                    if (x3) {
                        mma_f16(acc[mt][nt], ah[mt][0], ah[mt][1], ah[mt][2], ah[mt][3],
                                bl[nt][0], bl[nt][1]);
                        mma_f16(acc[mt][nt], al[mt][0], al[mt][1], al[mt][2], al[mt][3],
                                bh[nt][0], bh[nt][1]);
                    }
                }
        }
        __syncthreads();
        scur = scur + 1; if (scur == 3) scur = 0;
    }

    #pragma unroll
    for (int mt = 0; mt < 4; mt++) {
        #pragma unroll
        for (int nt = 0; nt < 4; nt++) {
            int col = bn + wN + nt * 8 + 2 * lc;
            #pragma unroll
            for (int half = 0; half < 2; half++) {
                int r = bm + wM + mt * 16 + lr + half * 8;
                float v0 = (acc[mt][nt][half * 2 + 0] + bias[col]) * alpha;
                float v1 = (acc[mt][nt][half * 2 + 1] + bias[col + 1]) * alpha;
                if (seg == 2) {
                    // direct paired-V store: key=r, head=col>>5, d=col&31
                    int head = col >> 5, d = col & 31;
                    size_t w = ((size_t)(r >> 1) * 1024 + head * 128 + d) * 2 + (r & 1);
                    vpH[w]     = __float2half_rn(v0);
                    vpH[w + 2] = __float2half_rn(v1);
                } else {
                    epi_store(v0, v1, nullptr, outH, outL, (size_t)r * ldc + col);
                }
            }
        }
    }
}

// ---------------------------------------------------------------------------
// Flash attention v6: K triple-buffer, V double-buffer, 2 syncs/tile.
// ---------------------------------------------------------------------------
#define AQ 128
#define AK 64
#define QP 20
#define VPSTR 136
#define KBUF 1280
#define VBUF 4352

#define ATTN_WORDS (2560*2 + 3*KBUF*2 + 2*VBUF)   // 21504
#define ATTN_SMEM  (ATTN_WORDS * 4)

__global__ __launch_bounds__(256, 2)
void attn_kernel(const unsigned* __restrict__ qhiW, const unsigned* __restrict__ qloW,
                 const unsigned* __restrict__ khiW, const unsigned* __restrict__ kloW,
                 const unsigned* __restrict__ vpW,
                 __half* __restrict__ outv, __half* __restrict__ outg)
{
    extern __shared__ unsigned smw[];
    unsigned* Qhi  = smw;                    // [128][QP]
    unsigned* Qlo  = Qhi + 2560;
    unsigned* Khi3 = Qlo + 2560;             // 3 x [64][QP]
    unsigned* Klo3 = Khi3 + 3 * KBUF;
    unsigned* Vp2  = Klo3 + 3 * KBUF;        // 2 x [32][VPSTR]

    const int head = blockIdx.y;
    const int qb   = blockIdx.x * AQ;
    const int tid  = threadIdx.x;
    const int lane = tid & 31;
    const int warp = tid >> 5;
    const int hofw = head * 16;
    const int hof  = head * DD;
    const int lr   = lane >> 2;
    const int lc   = lane & 3;
    const int wRow = warp * 16;

    // prologue: K(0) into buf0 + Q (one group)
    {
        int key = tid >> 2, seg = tid & 3;
        cp_async16(&Khi3[key * QP + seg * 4], &khiW[(size_t)key * 128 + hofw + seg * 4]);
        cp_async16(&Klo3[key * QP + seg * 4], &kloW[(size_t)key * 128 + hofw + seg * 4]);
    }
    #pragma unroll
    for (int i = 0; i < 2; i++) {
        int idx = tid + i * 256;
        int row = idx >> 2, seg = idx & 3;
        cp_async16(&Qhi[row * QP + seg * 4], &qhiW[(size_t)(qb + row) * 128 + hofw + seg * 4]);
        cp_async16(&Qlo[row * QP + seg * 4], &qloW[(size_t)(qb + row) * 128 + hofw + seg * 4]);
    }
    CP_COMMIT();

    float O[16][4] = {};
    float m0 = -1e30f, m1 = -1e30f, l0 = 0.f, l1 = 0.f;

    int kcur = 0;
    for (int t = 0; t < NN / AK; t++) {
        const int kb = t * AK;

        // issue V(t) into Vp2[t&1]
        {
            unsigned* Vd = Vp2 + (t & 1) * VBUF;
            const int p0 = kb >> 1;
            #pragma unroll
            for (int i = 0; i < 4; i++) {
                int idx = tid + i * 256;
                int pr = idx >> 5, s = idx & 31;
                cp_async16(&Vd[pr * VPSTR + s * 4],
                           &vpW[((size_t)(p0 + pr)) * 1024 + head * 128 + s * 4]);
            }
        }
        CP_COMMIT();

        const bool hasNext = (t + 1 < NN / AK);
        int knext = kcur + 1; if (knext == 3) knext = 0;
        if (hasNext) {
            unsigned* Kdh = Khi3 + knext * KBUF;
            unsigned* Kdl = Klo3 + knext * KBUF;
            int key = tid >> 2, seg = tid & 3;
            cp_async16(&Kdh[key * QP + seg * 4],
                       &khiW[(size_t)(kb + AK + key) * 128 + hofw + seg * 4]);
            cp_async16(&Kdl[key * QP + seg * 4],
                       &kloW[(size_t)(kb + AK + key) * 128 + hofw + seg * 4]);
            CP_COMMIT();
            CP_WAIT(2);   // K(t) (and Q at t=0) complete
        } else {
            CP_WAIT(1);
        }
        __syncthreads();

        const unsigned* Kh = Khi3 + kcur * KBUF;
        const unsigned* Kl = Klo3 + kcur * KBUF;
        const unsigned* Vp = Vp2 + (t & 1) * VBUF;

        #pragma unroll
        for (int half = 0; half < 2; half++) {
            // ---- S = Q K^T (fp16x3) ----
            float s[4][4] = {};
            #pragma unroll
            for (int ks = 0; ks < 2; ks++) {
                int rb = wRow + lr;
                int c  = ks * 8 + lc;
                unsigned ah0 = Qhi[rb * QP + c],     ah1 = Qhi[(rb + 8) * QP + c];
                unsigned ah2 = Qhi[rb * QP + c + 4], ah3 = Qhi[(rb + 8) * QP + c + 4];
                unsigned al0 = Qlo[rb * QP + c],     al1 = Qlo[(rb + 8) * QP + c];
                unsigned al2 = Qlo[rb * QP + c + 4], al3 = Qlo[(rb + 8) * QP + c + 4];
                #pragma unroll
                for (int nt = 0; nt < 4; nt++) {
                    int key = half * 32 + nt * 8 + lr;
                    unsigned bh0 = Kh[key * QP + c];
                    unsigned bh1 = Kh[key * QP + c + 4];
                    unsigned bl0 = Kl[key * QP + c];
                    unsigned bl1 = Kl[key * QP + c + 4];
                    mma_f16(s[nt], ah0, ah1, ah2, ah3, bh0, bh1);
                    mma_f16(s[nt], ah0, ah1, ah2, ah3, bl0, bl1);
                    mma_f16(s[nt], al0, al1, al2, al3, bh0, bh1);
                }
            }

            // ---- online softmax ----
            float mx0 = m0, mx1 = m1;
            #pragma unroll
            for (int nt = 0; nt < 4; nt++) {
                mx0 = fmaxf(mx0, fmaxf(s[nt][0], s[nt][1]));
                mx1 = fmaxf(mx1, fmaxf(s[nt][2], s[nt][3]));
            }
            mx0 = fmaxf(mx0, __shfl_xor_sync(0xffffffff, mx0, 1));
            mx0 = fmaxf(mx0, __shfl_xor_sync(0xffffffff, mx0, 2));
            mx1 = fmaxf(mx1, __shfl_xor_sync(0xffffffff, mx1, 1));
            mx1 = fmaxf(mx1, __shfl_xor_sync(0xffffffff, mx1, 2));

            float alpha0 = __expf(m0 - mx0);
            float alpha1 = __expf(m1 - mx1);
            float sum0 = 0.f, sum1 = 0.f;
            #pragma unroll
            for (int nt = 0; nt < 4; nt++) {
                s[nt][0] = __expf(s[nt][0] - mx0);
                s[nt][1] = __expf(s[nt][1] - mx0);
                s[nt][2] = __expf(s[nt][2] - mx1);
                s[nt][3] = __expf(s[nt][3] - mx1);
                sum0 += s[nt][0] + s[nt][1];
                sum1 += s[nt][2] + s[nt][3];
            }
            sum0 += __shfl_xor_sync(0xffffffff, sum0, 1);
            sum0 += __shfl_xor_sync(0xffffffff, sum0, 2);
            sum1 += __shfl_xor_sync(0xffffffff, sum1, 1);
            sum1 += __shfl_xor_sync(0xffffffff, sum1, 2);
            l0 = l0 * alpha0 + sum0;  m0 = mx0;
            l1 = l1 * alpha1 + sum1;  m1 = mx1;

            unsigned pa[2][4];
            #pragma unroll
            for (int t16 = 0; t16 < 2; t16++) {
                pa[t16][0] = h2pack(s[2 * t16][0],     s[2 * t16][1]);
                pa[t16][1] = h2pack(s[2 * t16][2],     s[2 * t16][3]);
                pa[t16][2] = h2pack(s[2 * t16 + 1][0], s[2 * t16 + 1][1]);
                pa[t16][3] = h2pack(s[2 * t16 + 1][2], s[2 * t16 + 1][3]);
            }

            #pragma unroll
            for (int nt = 0; nt < 16; nt++) {
                O[nt][0] *= alpha0; O[nt][1] *= alpha0;
                O[nt][2] *= alpha1; O[nt][3] *= alpha1;
            }

            // V arrival (once per tile)
            if (half == 0) {
                if (hasNext) { CP_WAIT(1); } else { CP_WAIT(0); }
                __syncthreads();
            }

            // ---- PV ----
            #pragma unroll
            for (int t16 = 0; t16 < 2; t16++) {
                int kpb = half * 16 + t16 * 8;
                #pragma unroll
                for (int nt = 0; nt < 16; nt++) {
                    int n = nt * 8 + lr;
                    unsigned b0 = Vp[(kpb + lc) * VPSTR + n];
                    unsigned b1 = Vp[(kpb + 4 + lc) * VPSTR + n];
                    mma_f16(O[nt], pa[t16][0], pa[t16][1], pa[t16][2], pa[t16][3], b0, b1);
                }
            }
        }
        kcur = knext;
    }

    // epilogue
    float linv0 = 1.f / l0;
    float linv1 = 1.f / l1;
    int r0 = qb + wRow + lr;
    int r1 = r0 + 8;
    unsigned* outvW = (unsigned*)outv;
    unsigned* outgW = (unsigned*)outg;
    #pragma unroll
    for (int nt = 0; nt < 16; nt++) {
        int c = nt * 8 + 2 * lc;
        unsigned w0 = h2pack(O[nt][0] * linv0, O[nt][1] * linv0);
        unsigned w1 = h2pack(O[nt][2] * linv1, O[nt][3] * linv1);
        if (c < 32) {
            outvW[(size_t)r0 * 128 + (hof + c) / 2] = w0;
            outvW[(size_t)r1 * 128 + (hof + c) / 2] = w1;
        } else {
            int ch = (c - 32) >> 5;
            int d  = (c - 32) & 31;
            outgW[((size_t)r0 * 3 + ch) * 128 + (hof + d) / 2] = w0;
            outgW[((size_t)r1 * 3 + ch) * 128 + (hof + d) / 2] = w1;
        }
    }
}

// ---------------------------------------------------------------------------
// Host orchestration (multi-stream fork/join, capture-safe)
// ---------------------------------------------------------------------------
extern "C" void kernel_launch(void* const* d_in, const int* in_sizes, int n_in,
                              void* d_out, int out_size)
{
    const float* equ    = (const float*)d_in[0];
    const float* h      = (const float*)d_in[1];
    const float* W_equ  = (const float*)d_in[4];
    const float* W_gproj= (const float*)d_in[5];
    const float* W_vg   = (const float*)d_in[6];
    const float* W_g1   = (const float*)d_in[7];
    const float* b_g1   = (const float*)d_in[8];
    const float* W_g2   = (const float*)d_in[9];
    const float* b_g2   = (const float*)d_in[10];
    const float* W_q    = (const float*)d_in[11];
    const float* b_q    = (const float*)d_in[12];
    const float* W_k    = (const float*)d_in[13];
    const float* b_k    = (const float*)d_in[14];
    const float* W_v    = (const float*)d_in[15];
    const float* b_v    = (const float*)d_in[16];
    const float* W_ng   = (const float*)d_in[17];
    const float* b_ng   = (const float*)d_in[18];
    const float* W_gout = (const float*)d_in[19];
    const float* W_gdec = (const float*)d_in[20];
    const float* W_hdec = (const float*)d_in[21];
    const float* b_hdec = (const float*)d_in[22];

    float* out = (float*)d_out;

    static cudaStream_t s1 = nullptr, s2 = nullptr;
    static cudaEvent_t evRoot, evPrep, evPack, evH2, evVg, evAttn, evS1, evHout;
    if (!s1) {
        cudaStreamCreateWithFlags(&s1, cudaStreamNonBlocking);
        cudaStreamCreateWithFlags(&s2, cudaStreamNonBlocking);
        cudaEventCreateWithFlags(&evRoot, cudaEventDisableTiming);
        cudaEventCreateWithFlags(&evPrep, cudaEventDisableTiming);
        cudaEventCreateWithFlags(&evPack, cudaEventDisableTiming);
        cudaEventCreateWithFlags(&evH2, cudaEventDisableTiming);
        cudaEventCreateWithFlags(&evVg, cudaEventDisableTiming);
        cudaEventCreateWithFlags(&evAttn, cudaEventDisableTiming);
        cudaEventCreateWithFlags(&evS1, cudaEventDisableTiming);
        cudaEventCreateWithFlags(&evHout, cudaEventDisableTiming);
    }

    float* S = nullptr;
    cudaGetSymbolAddress((void**)&S, scratch);

    const int SM1 = (3 * ASZ + 3 * BSZ) * 4;        // 56832
    const int SM3 = SM1 * 2;                        // 113664
    cudaFuncSetAttribute(hgemm<1, true>,  cudaFuncAttributeMaxDynamicSharedMemorySize, SM1);
    cudaFuncSetAttribute(hgemm<1, false>, cudaFuncAttributeMaxDynamicSharedMemorySize, SM1);
    cudaFuncSetAttribute(hgemm<3, false>, cudaFuncAttributeMaxDynamicSharedMemorySize, SM3);
    cudaFuncSetAttribute(qkv_hgemm, cudaFuncAttributeMaxDynamicSharedMemorySize, SM3);
    cudaFuncSetAttribute(attn_kernel, cudaFuncAttributeMaxDynamicSharedMemorySize, ATTN_SMEM);

    __half* gram_h = (__half*)(S + OFF_GRAM);
    __half* hid_h  = (__half*)(S + OFF_HID);
    __half* h2hi   = (__half*)(S + OFF_H2HI);
    __half* h2lo   = (__half*)(S + OFF_H2LO);
    __half* qhi    = (__half*)(S + OFF_QHI);
    __half* qlo    = (__half*)(S + OFF_QLO);
    __half* khi    = (__half*)(S + OFF_KHI);
    __half* klo    = (__half*)(S + OFF_KLO);
    unsigned* vpair= (unsigned*)(S + OFF_VPAIR);
    __half* outv_h = (__half*)(S + OFF_OUTV);
    __half* outg_h = (__half*)(S + OFF_OUTG);
    float*  hpre   = S + OFF_HPRE;
    unsigned* Pg1  = (unsigned*)(S + OFF_PG1);
    unsigned* Pg2  = (unsigned*)(S + OFF_PG2);
    unsigned* Pqh  = (unsigned*)(S + OFF_PQH);
    unsigned* Pql  = (unsigned*)(S + OFF_PQL);
    unsigned* Pkh  = (unsigned*)(S + OFF_PKH);
    unsigned* Pkl  = (unsigned*)(S + OFF_PKL);
    unsigned* Pv   = (unsigned*)(S + OFF_PV);
    unsigned* Phdh = (unsigned*)(S + OFF_PHDH);
    unsigned* Phdl = (unsigned*)(S + OFF_PHDL);
    unsigned* W3p  = (unsigned*)(S + OFF_W3P);
    float* Wg      = S + OFF_WG;
    float* W1      = S + OFF_W1;
    float* Wvg2    = S + OFF_WVG2;
    float* W2f     = S + OFF_W2F;
    float* bias2   = S + OFF_BIAS2;

    const float scaling = 0.17677669529663687f;

    // ---- fork ----
    cudaEventRecord(evRoot, 0);
    cudaStreamWaitEvent(s1, evRoot, 0);
    cudaStreamWaitEvent(s2, evRoot, 0);

    // s2: h2fill early (only needs h)
    h2fill_kernel<<<(NN * EE + 255) / 256, 256, 0, s2>>>(h, h2hi, h2lo);
    cudaEventRecord(evH2, s2);

    // s1: weight packing + W3/bias2 + hpre
    pack_weights<<<2176, 256, 0, s1>>>(W_g1, W_g2, W_q, W_k, W_v, W_hdec,
                                       Pg1, Pg2, Pqh, Pql, Pkh, Pkl, Pv, Phdh, Phdl);
    cudaEventRecord(evPack, s1);
    prep_w3<<<129, 256, 0, s1>>>(W_ng, W_hdec, b_ng, b_hdec, W3p, bias2);
    cudaStreamWaitEvent(s1, evH2, 0);
    hgemm<3, false><<<dim3(2, 32), 256, SM3, s1>>>(h2hi + 256, h2lo + 256, 512,
                                                   Phdh, Phdl, 256,
                                                   bias2, nullptr, 0, 0.f, 1.f,
                                                   hpre, nullptr, nullptr, 256, 256);
    cudaEventRecord(evS1, s1);

    // main: prep combos
    prep_small<<<35, 256>>>(W_equ, W_gproj, W_gdec, W_vg, W_gout, Wg, W1, Wvg2, W2f);
    cudaEventRecord(evPrep, 0);

    // s2: vg -> vpair direct
    cudaStreamWaitEvent(s2, evPrep, 0);
    vg_small<<<192, 256, 0, s2>>>(equ, Wvg2, (__half*)vpair);
    cudaEventRecord(evVg, s2);

    // main: gram -> MLP -> qkv -> attention
    g2p_gram<<<NN, 128>>>(equ, Wg, gram_h);
    cudaStreamWaitEvent(0, evPack, 0);
    hgemm<1, true><<<dim3(4, 32), 256, SM1>>>(gram_h, nullptr, 1024, Pg1, nullptr, 512,
                                              b_g1, nullptr, 0, 0.f, 1.f,
                                              nullptr, hid_h, nullptr, 512, 1024);
    hgemm<1, false><<<dim3(2, 32), 256, SM1>>>(hid_h, nullptr, 512, Pg2, nullptr, 256,
                                               b_g2, nullptr, 0, 0.f, 1.f,
                                               nullptr, h2hi, h2lo, 512, 512);
    cudaStreamWaitEvent(0, evH2, 0);
    qkv_hgemm<<<dim3(2, 32, 3), 256, SM3>>>(h2hi, h2lo, Pqh, Pql, Pkh, Pkl, Pv,
                                            b_q, b_k, b_v, qhi, qlo, khi, klo,
                                            (__half*)vpair, scaling);
    cudaStreamWaitEvent(0, evVg, 0);
    attn_kernel<<<dim3(NN / AQ, HH), 256, ATTN_SMEM>>>(
        (const unsigned*)qhi, (const unsigned*)qlo,
        (const unsigned*)khi, (const unsigned*)klo,
        vpair, outv_h, outg_h);
    cudaEventRecord(evAttn, 0);

    // s2: h_out = outv@W3 + hpre
    cudaStreamWaitEvent(s2, evAttn, 0);
    cudaStreamWaitEvent(s2, evS1, 0);
    hgemm<1, false><<<dim3(2, 32), 256, SM1, s2>>>(outv_h, nullptr, 256, W3p, nullptr, 256,
                                                   nullptr, hpre, 256, 1.f, 1.f,
                                                   out + (size_t)ROWS * MMDIM,
                                                   nullptr, nullptr, 256, 256);
    cudaEventRecord(evHout, s2);

    // main: equ_out = equ@W1 + outg@W2f
    equ_out_kernel<<<768, 256>>>(equ, outg_h, W1, W2f, out);

    // ---- join ----
    cudaStreamWaitEvent(0, evHout, 0);
}

// round 8
// speedup vs baseline: 6.4978x; 1.0466x over previous
#include <cuda_runtime.h>
#include <cuda_fp16.h>
#include <math.h>

#define NN 4096
#define NV 3
#define MMDIM 16
#define EE 256
#define HH 8
#define DD 32
#define ROWS (NN*NV)

__device__ float scratch[26607616];

// word offsets
#define OFF_GRAM    0u          // h16 [4096,1024]
#define OFF_HID     2097152u    // h16 [4096,512]
#define OFF_H2HI    3145728u    // h16 [4096,512]
#define OFF_H2LO    4194304u
#define OFF_QHI     5242880u    // h16 [4096,256]
#define OFF_QLO     5767168u
#define OFF_KHI     6291456u
#define OFF_KLO     6815744u
#define OFF_VPAIR   9437184u    // half2 [2048][8][128]
#define OFF_OUTV    11534336u   // h16 [4096,256]
#define OFF_OUTG    12058624u   // h16 [12288,256]
#define OFF_HPRE    13631488u   // f32 [4096,256]
#define OFF_PG1     14680064u
#define OFF_PG2     14942208u
#define OFF_PQH     15007744u
#define OFF_PQL     15073280u
#define OFF_PKH     15138816u
#define OFF_PKL     15204352u
#define OFF_PV      15269888u
#define OFF_PHDH    15335424u
#define OFF_PHDL    15368192u
#define OFF_W3P     15400960u
#define OFF_WG      15433728u
#define OFF_W1      15434240u
#define OFF_WVG2    15434496u
#define OFF_W2F     15438592u
#define OFF_BIAS2   15442688u

// ---------------------------------------------------------------------------
// helpers
// ---------------------------------------------------------------------------
__device__ __forceinline__ void mma_f16(float c[4],
                                        unsigned a0, unsigned a1, unsigned a2, unsigned a3,
                                        unsigned b0, unsigned b1) {
    asm volatile(
        "mma.sync.aligned.m16n8k16.row.col.f32.f16.f16.f32 "
        "{%0,%1,%2,%3}, {%4,%5,%6,%7}, {%8,%9}, {%0,%1,%2,%3};"
        : "+f"(c[0]), "+f"(c[1]), "+f"(c[2]), "+f"(c[3])
        : "r"(a0), "r"(a1), "r"(a2), "r"(a3), "r"(b0), "r"(b1));
}

__device__ __forceinline__ unsigned h2pack(float a, float b) {
    __half2 h = __floats2half2_rn(a, b);
    return *(unsigned*)&h;
}

__device__ __forceinline__ void cp_async16(void* smem, const void* gmem) {
    unsigned s = (unsigned)__cvta_generic_to_shared(smem);
    asm volatile("cp.async.cg.shared.global [%0], [%1], 16;" :: "r"(s), "l"(gmem));
}
#define CP_COMMIT() asm volatile("cp.async.commit_group;")
#define CP_WAIT(n)  asm volatile("cp.async.wait_group %0;" :: "n"(n))

// ---------------------------------------------------------------------------
// Weight packing (half2 kp-pairs)
// ---------------------------------------------------------------------------
__device__ __forceinline__ void pack_one(const float* __restrict__ W, int N, int i,
                                         unsigned* __restrict__ H, unsigned* __restrict__ L)
{
    int kp = i / N, n = i - kp * N;
    float x0 = W[(size_t)(2 * kp) * N + n];
    float x1 = W[(size_t)(2 * kp + 1) * N + n];
    __half h0 = __float2half_rn(x0), h1 = __float2half_rn(x1);
    __half2 hh = __halves2half2(h0, h1);
    H[i] = *(unsigned*)&hh;
    if (L) {
        __half2 ll = __floats2half2_rn(x0 - __half2float(h0), x1 - __half2float(h1));
        L[i] = *(unsigned*)&ll;
    }
}

__global__ void pack_weights(const float* Wg1, const float* Wg2, const float* Wq,
                             const float* Wk, const float* Wv, const float* Whd,
                             unsigned* Pg1, unsigned* Pg2,
                             unsigned* Pqh, unsigned* Pql,
                             unsigned* Pkh, unsigned* Pkl,
                             unsigned* Pv, unsigned* Phdh, unsigned* Phdl)
{
    int idx = blockIdx.x * 256 + threadIdx.x;
    if (idx < 262144) { pack_one(Wg1, 512, idx, Pg1, nullptr); return; }
    idx -= 262144;
    if (idx < 65536) { pack_one(Wg2, 256, idx, Pg2, nullptr); return; }
    idx -= 65536;
    if (idx < 65536) { pack_one(Wq, 256, idx, Pqh, Pql); return; }
    idx -= 65536;
    if (idx < 65536) { pack_one(Wk, 256, idx, Pkh, Pkl); return; }
    idx -= 65536;
    if (idx < 65536) { pack_one(Wv, 256, idx, Pv, nullptr); return; }
    idx -= 65536;
    if (idx < 32768) { pack_one(Whd, 256, idx, Phdh, Phdl); return; }
}

// ---------------------------------------------------------------------------
// Prep: small weight combinations (fp32)
// ---------------------------------------------------------------------------
__global__ void prep_small(const float* __restrict__ We, const float* __restrict__ Wgp,
                           const float* __restrict__ Wgd, const float* __restrict__ Wvg,
                           const float* __restrict__ Wgo,
                           float* Wg, float* W1, float* Wvg2, float* W2f)
{
    int idx = blockIdx.x * 256 + threadIdx.x;
    if (idx < 512) {
        int m = idx >> 5, n = idx & 31;
        float a = 0;
        for (int e = 0; e < 256; e++) a += We[m * 256 + e] * Wgp[e * 32 + n];
        Wg[idx] = 16.f * a; return;
    }
    idx -= 512;
    if (idx < 256) {
        int m = idx >> 4, j = idx & 15;
        float a = 0;
        for (int e = 0; e < 256; e++) a += We[m * 256 + e] * Wgd[e * 16 + j];
        W1[idx] = 16.f * a; return;
    }
    idx -= 256;
    if (idx < 4096) {
        int m = idx >> 8, c = idx & 255;
        float a = 0;
        for (int e = 0; e < 256; e++) a += We[m * 256 + e] * Wvg[e * 256 + c];
        Wvg2[idx] = 16.f * a; return;
    }
    idx -= 4096;
    if (idx < 4096) {
        int k = idx >> 4, j = idx & 15;
        float a = 0;
        for (int e = 0; e < 256; e++) a += Wgo[k * 256 + e] * Wgd[e * 16 + j];
        W2f[idx] = a;
    }
}

// W3p = pack(W_ng @ W_hdec); bias2 = b_ng@W_hdec + b_hdec
__global__ void prep_w3(const float* __restrict__ Wng, const float* __restrict__ Whd,
                        const float* __restrict__ bng, const float* __restrict__ bhd,
                        unsigned* W3p, float* bias2)
{
    int idx = blockIdx.x * 256 + threadIdx.x;
    if (idx < 32768) {
        int kp = idx >> 8, n = idx & 255;
        float a0 = 0, a1 = 0;
        for (int e = 0; e < 256; e++) {
            float w = Whd[e * 256 + n];
            a0 += Wng[(2 * kp) * 256 + e] * w;
            a1 += Wng[(2 * kp + 1) * 256 + e] * w;
        }
        __half2 h = __floats2half2_rn(a0, a1);
        W3p[idx] = *(unsigned*)&h;
        return;
    }
    idx -= 32768;
    if (idx < 256) {
        float a = bhd[idx];
        for (int k = 0; k < 256; k++) a += bng[k] * Whd[k * 256 + idx];
        bias2[idx] = a;
    }
}

// ---------------------------------------------------------------------------
// Fused g2p + gram
// ---------------------------------------------------------------------------
__global__ __launch_bounds__(128)
void g2p_gram(const float* __restrict__ equ, const float* __restrict__ Wg,
              __half* __restrict__ gram)
{
    __shared__ float wgs[512];
    __shared__ float es[48];
    __shared__ float g2s[96];
    int t = threadIdx.x;
    int node = blockIdx.x;
    #pragma unroll
    for (int i = 0; i < 4; i++) wgs[t + i * 128] = Wg[t + i * 128];
    if (t < 48) es[t] = equ[(size_t)node * 48 + t];
    __syncthreads();
    if (t < 96) {
        int i = t >> 5, a = t & 31;
        float acc = 0;
        #pragma unroll
        for (int k = 0; k < 16; k++) acc += es[i * 16 + k] * wgs[k * 32 + a];
        g2s[t] = acc;
    }
    __syncthreads();
    #pragma unroll
    for (int o = t; o < 1024; o += 128) {
        int a = o >> 5, b = o & 31;
        gram[(size_t)node * 1024 + o] = __float2half_rn(
            g2s[a] * g2s[b] + g2s[32 + a] * g2s[32 + b] + g2s[64 + a] * g2s[64 + b]);
    }
}

// vg = equ @ Wvg2 (K=16), written directly into paired attention layout.
__global__ __launch_bounds__(256)
void vg_small(const float* __restrict__ equ, const float* __restrict__ Wvg2,
              __half* __restrict__ vpH)
{
    __shared__ float ws[16 * 256];
    __shared__ float es[64 * 16];
    int tid = threadIdx.x;
    #pragma unroll
    for (int i = 0; i < 16; i++) ws[tid + i * 256] = Wvg2[tid + i * 256];
    int r0 = blockIdx.x * 64;
    #pragma unroll
    for (int i = 0; i < 4; i++) {
        int idx = tid + i * 256;
        es[idx] = equ[(size_t)r0 * 16 + idx];
    }
    __syncthreads();
    const int head = tid >> 5, d = tid & 31;
    for (int r = 0; r < 64; r++) {
        float acc = 0;
        #pragma unroll
        for (int k = 0; k < 16; k++) acc += es[r * 16 + k] * ws[k * 256 + tid];
        int gr = r0 + r;
        int node = gr / 3;
        int ch = gr - 3 * node;
        size_t w = ((size_t)(node >> 1) * 1024 + head * 128 + 32 + ch * 32 + d) * 2 + (node & 1);
        vpH[w] = __float2half_rn(acc);
    }
}

// h2 right half = 16h split hi/lo
__global__ void h2fill_kernel(const float* __restrict__ h,
                              __half* __restrict__ h2hi, __half* __restrict__ h2lo)
{
    int idx = blockIdx.x * blockDim.x + threadIdx.x;
    if (idx < NN * EE) {
        int r = idx >> 8, c = idx & 255;
        float v = 16.f * h[idx];
        __half hi = __float2half_rn(v);
        size_t o = (size_t)r * 512 + 256 + c;
        h2hi[o] = hi;
        h2lo[o] = __float2half_rn(v - __half2float(hi));
    }
}

// equ_out = equ@W1 + outg@W2f  (N=16 fused)
__global__ __launch_bounds__(256)
void equ_out_kernel(const float* __restrict__ equ, const __half* __restrict__ outg,
                    const float* __restrict__ W1, const float* __restrict__ W2,
                    float* __restrict__ out)
{
    __shared__ float w1s[256];
    __shared__ float w2s[4096];
    int tid = threadIdx.x;
    w1s[tid] = W1[tid];
    #pragma unroll
    for (int i = 0; i < 16; i++) w2s[tid + i * 256] = W2[tid + i * 256];
    __syncthreads();
    int lane = tid & 31, warp = tid >> 5;
    int row = blockIdx.x * 16 + warp * 2 + (lane >> 4);
    int j = lane & 15;
    float acc = 0;
    const float* er = equ + (size_t)row * 16;
    #pragma unroll
    for (int k = 0; k < 16; k++) acc += er[k] * w1s[k * 16 + j];
    const __half2* og = (const __half2*)(outg + (size_t)row * 256);
    #pragma unroll 8
    for (int kp = 0; kp < 128; kp++) {
        float2 v = __half22float2(og[kp]);
        acc += v.x * w2s[(2 * kp) * 16 + j] + v.y * w2s[(2 * kp + 1) * 16 + j];
    }
    out[(size_t)row * 16 + j] = acc;
}

// ---------------------------------------------------------------------------
// FP16 GEMM, 64x128 tile (8 warps, warp tile 32x32), 3-stage cp.async pipeline.
// Doubled block-count vs 128x128 to fill 148 SMs.
// ---------------------------------------------------------------------------
#define HA_STR 20
#define HB_STR 136
#define ASZ (64*HA_STR)
#define BSZ (16*HB_STR)

__device__ __forceinline__ void epi_store(float v0, float v1,
                                          float* outF, __half* outH, __half* outL,
                                          size_t off)
{
    if (outF) {
        *(float2*)&outF[off] = make_float2(v0, v1);
    } else if (outL) {
        __half h0 = __float2half_rn(v0), h1 = __float2half_rn(v1);
        __half2 hh = __halves2half2(h0, h1);
        ((__half2*)outH)[off >> 1] = hh;
        ((__half2*)outL)[off >> 1] =
            __floats2half2_rn(v0 - __half2float(h0), v1 - __half2float(h1));
    } else {
        ((__half2*)outH)[off >> 1] = __floats2half2_rn(v0, v1);
    }
}

#define STAGE_A_G(SRC, DST, K0) { \
    int row_ = tid >> 2, seg_ = tid & 3; \
    cp_async16(&(DST)[row_ * HA_STR + seg_ * 4], \
               &(SRC)[(size_t)(bm + row_) * lda + (K0) + seg_ * 8]); }
#define STAGE_B_G(SRC, DST, K0) { \
    _Pragma("unroll") \
    for (int i = 0; i < 2; i++) { \
        int idx = tid + i * 256; \
        int kp = idx >> 5, s = idx & 31; \
        cp_async16(&(DST)[kp * HB_STR + s * 4], \
                   &(SRC)[(size_t)(((K0) >> 1) + kp) * ldbw + bn + s * 4]); \
    } }

template<int NPASS, bool RELU>
__global__ __launch_bounds__(256)
void hgemm(const __half* __restrict__ A, const __half* __restrict__ Al, int lda,
           const unsigned* __restrict__ Bp, const unsigned* __restrict__ Bl, int ldbw,
           const float* __restrict__ bias,
           const float* __restrict__ Res, int ldres, float resScale, float alpha,
           float* __restrict__ outF, __half* __restrict__ outH, __half* __restrict__ outL,
           int ldc, int K)
{
    extern __shared__ unsigned smw[];
    unsigned* As  = smw;                 // 3 stages
    unsigned* Bs  = smw + 3 * ASZ;
    unsigned* Als = Bs + 3 * BSZ;
    unsigned* Bls = Als + 3 * ASZ;

    const int tid  = threadIdx.x;
    const int lane = tid & 31;
    const int warp = tid >> 5;
    const int bm   = blockIdx.y * 64;
    const int bn   = blockIdx.x * 128;
    const int wM   = (warp >> 2) * 32;
    const int wN   = (warp & 3) * 32;
    const int lr   = lane >> 2;
    const int lc   = lane & 3;

    float acc[2][4][4] = {};
    const int KT = K / 32;   // >= 3

    STAGE_A_G(A, As, 0);
    if (NPASS == 3) STAGE_A_G(Al, Als, 0);
    STAGE_B_G(Bp, Bs, 0);
    if (NPASS == 3) STAGE_B_G(Bl, Bls, 0);
    CP_COMMIT();
    STAGE_A_G(A, As + ASZ, 32);
    if (NPASS == 3) STAGE_A_G(Al, Als + ASZ, 32);
    STAGE_B_G(Bp, Bs + BSZ, 32);
    if (NPASS == 3) STAGE_B_G(Bl, Bls + BSZ, 32);
    CP_COMMIT();

    int scur = 0;
    for (int kt = 0; kt < KT; kt++) {
        if (kt + 2 < KT) {
            int s2 = scur + 2; if (s2 >= 3) s2 -= 3;
            int k0 = (kt + 2) * 32;
            STAGE_A_G(A, As + s2 * ASZ, k0);
            if (NPASS == 3) STAGE_A_G(Al, Als + s2 * ASZ, k0);
            STAGE_B_G(Bp, Bs + s2 * BSZ, k0);
            if (NPASS == 3) STAGE_B_G(Bl, Bls + s2 * BSZ, k0);
            CP_COMMIT();
            CP_WAIT(2);
        } else if (kt + 1 < KT) {
            CP_WAIT(1);
        } else {
            CP_WAIT(0);
        }
        __syncthreads();

        const unsigned* Ac  = As  + scur * ASZ;
        const unsigned* Bc  = Bs  + scur * BSZ;
        const unsigned* Alc = Als + scur * ASZ;
        const unsigned* Blc = Bls + scur * BSZ;

        #pragma unroll
        for (int ks = 0; ks < 2; ks++) {
            unsigned ah[2][4], al[2][4];
            #pragma unroll
            for (int mt = 0; mt < 2; mt++) {
                int rb = wM + mt * 16 + lr;
                int c  = ks * 8 + lc;
                ah[mt][0] = Ac[rb * HA_STR + c];
                ah[mt][1] = Ac[(rb + 8) * HA_STR + c];
                ah[mt][2] = Ac[rb * HA_STR + c + 4];
                ah[mt][3] = Ac[(rb + 8) * HA_STR + c + 4];
                if (NPASS == 3) {
                    al[mt][0] = Alc[rb * HA_STR + c];
                    al[mt][1] = Alc[(rb + 8) * HA_STR + c];
                    al[mt][2] = Alc[rb * HA_STR + c + 4];
                    al[mt][3] = Alc[(rb + 8) * HA_STR + c + 4];
                }
            }
            unsigned bh[4][2], bl[4][2];
            #pragma unroll
            for (int nt = 0; nt < 4; nt++) {
                int n  = wN + nt * 8 + lr;
                int kp = ks * 8 + lc;
                bh[nt][0] = Bc[kp * HB_STR + n];
                bh[nt][1] = Bc[(kp + 4) * HB_STR + n];
                if (NPASS == 3) {
                    bl[nt][0] = Blc[kp * HB_STR + n];
                    bl[nt][1] = Blc[(kp + 4) * HB_STR + n];
                }
            }
            #pragma unroll
            for (int mt = 0; mt < 2; mt++)
                #pragma unroll
                for (int nt = 0; nt < 4; nt++) {
                    mma_f16(acc[mt][nt], ah[mt][0], ah[mt][1], ah[mt][2], ah[mt][3],
                            bh[nt][0], bh[nt][1]);
                    if (NPASS == 3) {
                        mma_f16(acc[mt][nt], ah[mt][0], ah[mt][1], ah[mt][2], ah[mt][3],
                                bl[nt][0], bl[nt][1]);
                        mma_f16(acc[mt][nt], al[mt][0], al[mt][1], al[mt][2], al[mt][3],
                                bh[nt][0], bh[nt][1]);
                    }
                }
        }
        __syncthreads();
        scur = scur + 1; if (scur == 3) scur = 0;
    }

    #pragma unroll
    for (int mt = 0; mt < 2; mt++) {
        #pragma unroll
        for (int nt = 0; nt < 4; nt++) {
            int col = bn + wN + nt * 8 + 2 * lc;
            #pragma unroll
            for (int half = 0; half < 2; half++) {
                int r = bm + wM + mt * 16 + lr + half * 8;
                float v0 = acc[mt][nt][half * 2 + 0];
                float v1 = acc[mt][nt][half * 2 + 1];
                if (bias) { v0 += bias[col]; v1 += bias[col + 1]; }
                v0 *= alpha; v1 *= alpha;
                if (Res) {
                    v0 = fmaf(resScale, Res[(size_t)r * ldres + col], v0);
                    v1 = fmaf(resScale, Res[(size_t)r * ldres + col + 1], v1);
                }
                if (RELU) { v0 = fmaxf(v0, 0.f); v1 = fmaxf(v1, 0.f); }
                epi_store(v0, v1, outF, outH, outL, (size_t)r * ldc + col);
            }
        }
    }
}

// ---------------------------------------------------------------------------
// Fused QKV (q/k x3 split-out; v x1 direct to vpair layout). 64x128 tiles.
// ---------------------------------------------------------------------------
__global__ __launch_bounds__(256)
void qkv_hgemm(const __half* __restrict__ A, const __half* __restrict__ Al,
               const unsigned* __restrict__ Pqh, const unsigned* __restrict__ Pql,
               const unsigned* __restrict__ Pkh, const unsigned* __restrict__ Pkl,
               const unsigned* __restrict__ Pv,
               const float* __restrict__ bq, const float* __restrict__ bk,
               const float* __restrict__ bv,
               __half* qh, __half* ql, __half* kh, __half* kl,
               __half* __restrict__ vpH,
               float scaling)
{
    extern __shared__ unsigned smw[];
    unsigned* As  = smw;
    unsigned* Bs  = smw + 3 * ASZ;
    unsigned* Als = Bs + 3 * BSZ;
    unsigned* Bls = Als + 3 * ASZ;

    const int seg = blockIdx.z;
    const bool x3 = (seg < 2);
    const unsigned* Bp = (seg == 0) ? Pqh : (seg == 1) ? Pkh : Pv;
    const unsigned* Bl = (seg == 0) ? Pql : (seg == 1) ? Pkl : nullptr;
    const float* bias  = (seg == 0) ? bq : (seg == 1) ? bk : bv;
    __half* outH = (seg == 0) ? qh : kh;
    __half* outL = (seg == 0) ? ql : kl;
    const float alpha = (seg == 0) ? scaling : 1.f;
    const int lda = 512, ldbw = 256, ldc = 256, K = 512;

    const int tid  = threadIdx.x;
    const int lane = tid & 31;
    const int warp = tid >> 5;
    const int bm   = blockIdx.y * 64;
    const int bn   = blockIdx.x * 128;
    const int wM   = (warp >> 2) * 32;
    const int wN   = (warp & 3) * 32;
    const int lr   = lane >> 2;
    const int lc   = lane & 3;

    float acc[2][4][4] = {};
    const int KT = K / 32;   // 16

    STAGE_A_G(A, As, 0);
    if (x3) STAGE_A_G(Al, Als, 0);
    STAGE_B_G(Bp, Bs, 0);
    if (x3) STAGE_B_G(Bl, Bls, 0);
    CP_COMMIT();
    STAGE_A_G(A, As + ASZ, 32);
    if (x3) STAGE_A_G(Al, Als + ASZ, 32);
    STAGE_B_G(Bp, Bs + BSZ, 32);
    if (x3) STAGE_B_G(Bl, Bls + BSZ, 32);
    CP_COMMIT();

    int scur = 0;
    for (int kt = 0; kt < KT; kt++) {
        if (kt + 2 < KT) {
            int s2 = scur + 2; if (s2 >= 3) s2 -= 3;
            int k0 = (kt + 2) * 32;
            STAGE_A_G(A, As + s2 * ASZ, k0);
            if (x3) STAGE_A_G(Al, Als + s2 * ASZ, k0);
            STAGE_B_G(Bp, Bs + s2 * BSZ, k0);
            if (x3) STAGE_B_G(Bl, Bls + s2 * BSZ, k0);
            CP_COMMIT();
            CP_WAIT(2);
        } else if (kt + 1 < KT) {
            CP_WAIT(1);
        } else {
            CP_WAIT(0);
        }
        __syncthreads();

        const unsigned* Ac  = As  + scur * ASZ;
        const unsigned* Bc  = Bs  + scur * BSZ;
        const unsigned* Alc = Als + scur * ASZ;
        const unsigned* Blc = Bls + scur * BSZ;

        #pragma unroll
        for (int ks = 0; ks < 2; ks++) {
            unsigned ah[2][4], al[2][4];
            #pragma unroll
            for (int mt = 0; mt < 2; mt++) {
                int rb = wM + mt * 16 + lr;
                int c  = ks * 8 + lc;
                ah[mt][0] = Ac[rb * HA_STR + c];
                ah[mt][1] = Ac[(rb + 8) * HA_STR + c];
                ah[mt][2] = Ac[rb * HA_STR + c + 4];
                ah[mt][3] = Ac[(rb + 8) * HA_STR + c + 4];
                if (x3) {
                    al[mt][0] = Alc[rb * HA_STR + c];
                    al[mt][1] = Alc[(rb + 8) * HA_STR + c];
                    al[mt][2] = Alc[rb * HA_STR + c + 4];
                    al[mt][3] = Alc[(rb + 8) * HA_STR + c + 4];
                }
            }
            unsigned bh[4][2], bl[4][2];
            #pragma unroll
            for (int nt = 0; nt < 4; nt++) {
                int n  = wN + nt * 8 + lr;
                int kp = ks * 8 + lc;
                bh[nt][0] = Bc[kp * HB_STR + n];
                bh[nt][1] = Bc[(kp + 4) * HB_STR + n];
                if (x3) {
                    bl[nt][0] = Blc[kp * HB_STR + n];
                    bl[nt][1] = Blc[(kp + 4) * HB_STR + n];
                }
            }
            #pragma unroll
            for (int mt = 0; mt < 2; mt++)
                #pragma unroll
                for (int nt = 0; nt < 4; nt++) {
                    mma_f16(acc[mt][nt], ah[mt][0], ah[mt][1], ah[mt][2], ah[mt][3],
                            bh[nt][0], bh[nt][1]);
                    if (x3) {
                        mma_f16(acc[mt][nt], ah[mt][0], ah[mt][1], ah[mt][2], ah[mt][3],
                                bl[nt][0], bl[nt][1]);
                        mma_f16(acc[mt][nt], al[mt][0], al[mt][1], al[mt][2], al[mt][3],
                                bh[nt][0], bh[nt][1]);
                    }
                }
        }
        __syncthreads();
        scur = scur + 1; if (scur == 3) scur = 0;
    }

    #pragma unroll
    for (int mt = 0; mt < 2; mt++) {
        #pragma unroll
        for (int nt = 0; nt < 4; nt++) {
            int col = bn + wN + nt * 8 + 2 * lc;
            #pragma unroll
            for (int half = 0; half < 2; half++) {
                int r = bm + wM + mt * 16 + lr + half * 8;
                float v0 = (acc[mt][nt][half * 2 + 0] + bias[col]) * alpha;
                float v1 = (acc[mt][nt][half * 2 + 1] + bias[col + 1]) * alpha;
                if (seg == 2) {
                    int head = col >> 5, d = col & 31;
                    size_t w = ((size_t)(r >> 1) * 1024 + head * 128 + d) * 2 + (r & 1);
                    vpH[w]     = __float2half_rn(v0);
                    vpH[w + 2] = __float2half_rn(v1);
                } else {
                    epi_store(v0, v1, nullptr, outH, outL, (size_t)r * ldc + col);
                }
            }
        }
    }
}

// ---------------------------------------------------------------------------
// Flash attention v7: K and V triple-buffered rings, ONE sync per tile,
// full-tile prefetch distance.
// ---------------------------------------------------------------------------
#define AQ 128
#define AK 64
#define QP 20
#define VPSTR 136
#define KBUF 1280
#define VBUF 4352

#define ATTN_WORDS (2560*2 + 3*KBUF*2 + 3*VBUF)   // 25856
#define ATTN_SMEM  (ATTN_WORDS * 4)               // 103424

__global__ __launch_bounds__(256, 2)
void attn_kernel(const unsigned* __restrict__ qhiW, const unsigned* __restrict__ qloW,
                 const unsigned* __restrict__ khiW, const unsigned* __restrict__ kloW,
                 const unsigned* __restrict__ vpW,
                 __half* __restrict__ outv, __half* __restrict__ outg)
{
    extern __shared__ unsigned smw[];
    unsigned* Qhi  = smw;                    // [128][QP]
    unsigned* Qlo  = Qhi + 2560;
    unsigned* Khi3 = Qlo + 2560;             // 3 x [64][QP]
    unsigned* Klo3 = Khi3 + 3 * KBUF;
    unsigned* Vp3  = Klo3 + 3 * KBUF;        // 3 x [32][VPSTR]

    const int head = blockIdx.y;
    const int qb   = blockIdx.x * AQ;
    const int tid  = threadIdx.x;
    const int lane = tid & 31;
    const int warp = tid >> 5;
    const int hofw = head * 16;
    const int hof  = head * DD;
    const int lr   = lane >> 2;
    const int lc   = lane & 3;
    const int wRow = warp * 16;

    // prologue: V(0) group, then K(0)+Q group
    {
        #pragma unroll
        for (int i = 0; i < 4; i++) {
            int idx = tid + i * 256;
            int pr = idx >> 5, s = idx & 31;
            cp_async16(&Vp3[pr * VPSTR + s * 4],
                       &vpW[(size_t)pr * 1024 + head * 128 + s * 4]);
        }
        CP_COMMIT();
    }
    {
        int key = tid >> 2, seg = tid & 3;
        cp_async16(&Khi3[key * QP + seg * 4], &khiW[(size_t)key * 128 + hofw + seg * 4]);
        cp_async16(&Klo3[key * QP + seg * 4], &kloW[(size_t)key * 128 + hofw + seg * 4]);
        #pragma unroll
        for (int i = 0; i < 2; i++) {
            int idx = tid + i * 256;
            int row = idx >> 2, sg = idx & 3;
            cp_async16(&Qhi[row * QP + sg * 4], &qhiW[(size_t)(qb + row) * 128 + hofw + sg * 4]);
            cp_async16(&Qlo[row * QP + sg * 4], &qloW[(size_t)(qb + row) * 128 + hofw + sg * 4]);
        }
        CP_COMMIT();
    }

    float O[16][4] = {};
    float m0 = -1e30f, m1 = -1e30f, l0 = 0.f, l1 = 0.f;

    int bcur = 0;   // buffer index t % 3
    for (int t = 0; t < NN / AK; t++) {
        const bool hasNext = (t + 1 < NN / AK);
        int bnext = bcur + 1; if (bnext == 3) bnext = 0;

        if (hasNext) {
            const int kb1 = (t + 1) * AK;
            // V(t+1) group
            unsigned* Vd = Vp3 + bnext * VBUF;
            const int p0 = kb1 >> 1;
            #pragma unroll
            for (int i = 0; i < 4; i++) {
                int idx = tid + i * 256;
                int pr = idx >> 5, s = idx & 31;
                cp_async16(&Vd[pr * VPSTR + s * 4],
                           &vpW[((size_t)(p0 + pr)) * 1024 + head * 128 + s * 4]);
            }
            CP_COMMIT();
            // K(t+1) group
            unsigned* Kdh = Khi3 + bnext * KBUF;
            unsigned* Kdl = Klo3 + bnext * KBUF;
            int key = tid >> 2, seg = tid & 3;
            cp_async16(&Kdh[key * QP + seg * 4],
                       &khiW[(size_t)(kb1 + key) * 128 + hofw + seg * 4]);
            cp_async16(&Kdl[key * QP + seg * 4],
                       &kloW[(size_t)(kb1 + key) * 128 + hofw + seg * 4]);
            CP_COMMIT();
            CP_WAIT(2);   // V(t), K(t) (and Q at t=0) complete
        } else {
            CP_WAIT(0);
        }
        __syncthreads();

        const unsigned* Kh = Khi3 + bcur * KBUF;
        const unsigned* Kl = Klo3 + bcur * KBUF;
        const unsigned* Vp = Vp3 + bcur * VBUF;

        #pragma unroll
        for (int half = 0; half < 2; half++) {
            // ---- S = Q K^T (fp16x3) ----
            float s[4][4] = {};
            #pragma unroll
            for (int ks = 0; ks < 2; ks++) {
                int rb = wRow + lr;
                int c  = ks * 8 + lc;
                unsigned ah0 = Qhi[rb * QP + c],     ah1 = Qhi[(rb + 8) * QP + c];
                unsigned ah2 = Qhi[rb * QP + c + 4], ah3 = Qhi[(rb + 8) * QP + c + 4];
                unsigned al0 = Qlo[rb * QP + c],     al1 = Qlo[(rb + 8) * QP + c];
                unsigned al2 = Qlo[rb * QP + c + 4], al3 = Qlo[(rb + 8) * QP + c + 4];
                #pragma unroll
                for (int nt = 0; nt < 4; nt++) {
                    int key = half * 32 + nt * 8 + lr;
                    unsigned bh0 = Kh[key * QP + c];
                    unsigned bh1 = Kh[key * QP + c + 4];
                    unsigned bl0 = Kl[key * QP + c];
                    unsigned bl1 = Kl[key * QP + c + 4];
                    mma_f16(s[nt], ah0, ah1, ah2, ah3, bh0, bh1);
                    mma_f16(s[nt], ah0, ah1, ah2, ah3, bl0, bl1);
                    mma_f16(s[nt], al0, al1, al2, al3, bh0, bh1);
                }
            }

            // ---- online softmax ----
            float mx0 = m0, mx1 = m1;
            #pragma unroll
            for (int nt = 0; nt < 4; nt++) {
                mx0 = fmaxf(mx0, fmaxf(s[nt][0], s[nt][1]));
                mx1 = fmaxf(mx1, fmaxf(s[nt][2], s[nt][3]));
            }
            mx0 = fmaxf(mx0, __shfl_xor_sync(0xffffffff, mx0, 1));
            mx0 = fmaxf(mx0, __shfl_xor_sync(0xffffffff, mx0, 2));
            mx1 = fmaxf(mx1, __shfl_xor_sync(0xffffffff, mx1, 1));
            mx1 = fmaxf(mx1, __shfl_xor_sync(0xffffffff, mx1, 2));

            float alpha0 = __expf(m0 - mx0);
            float alpha1 = __expf(m1 - mx1);
            float sum0 = 0.f, sum1 = 0.f;
            #pragma unroll
            for (int nt = 0; nt < 4; nt++) {
                s[nt][0] = __expf(s[nt][0] - mx0);
                s[nt][1] = __expf(s[nt][1] - mx0);
                s[nt][2] = __expf(s[nt][2] - mx1);
                s[nt][3] = __expf(s[nt][3] - mx1);
                sum0 += s[nt][0] + s[nt][1];
                sum1 += s[nt][2] + s[nt][3];
            }
            sum0 += __shfl_xor_sync(0xffffffff, sum0, 1);
            sum0 += __shfl_xor_sync(0xffffffff, sum0, 2);
            sum1 += __shfl_xor_sync(0xffffffff, sum1, 1);
            sum1 += __shfl_xor_sync(0xffffffff, sum1, 2);
            l0 = l0 * alpha0 + sum0;  m0 = mx0;
            l1 = l1 * alpha1 + sum1;  m1 = mx1;

            unsigned pa[2][4];
            #pragma unroll
            for (int t16 = 0; t16 < 2; t16++) {
                pa[t16][0] = h2pack(s[2 * t16][0],     s[2 * t16][1]);
                pa[t16][1] = h2pack(s[2 * t16][2],     s[2 * t16][3]);
                pa[t16][2] = h2pack(s[2 * t16 + 1][0], s[2 * t16 + 1][1]);
                pa[t16][3] = h2pack(s[2 * t16 + 1][2], s[2 * t16 + 1][3]);
            }

            #pragma unroll
            for (int nt = 0; nt < 16; nt++) {
                O[nt][0] *= alpha0; O[nt][1] *= alpha0;
                O[nt][2] *= alpha1; O[nt][3] *= alpha1;
            }

            // ---- PV ----
            #pragma unroll
            for (int t16 = 0; t16 < 2; t16++) {
                int kpb = half * 16 + t16 * 8;
                #pragma unroll
                for (int nt = 0; nt < 16; nt++) {
                    int n = nt * 8 + lr;
                    unsigned b0 = Vp[(kpb + lc) * VPSTR + n];
                    unsigned b1 = Vp[(kpb + 4 + lc) * VPSTR + n];
                    mma_f16(O[nt], pa[t16][0], pa[t16][1], pa[t16][2], pa[t16][3], b0, b1);
                }
            }
        }
        bcur = bnext;
    }

    // epilogue
    float linv0 = 1.f / l0;
    float linv1 = 1.f / l1;
    int r0 = qb + wRow + lr;
    int r1 = r0 + 8;
    unsigned* outvW = (unsigned*)outv;
    unsigned* outgW = (unsigned*)outg;
    #pragma unroll
    for (int nt = 0; nt < 16; nt++) {
        int c = nt * 8 + 2 * lc;
        unsigned w0 = h2pack(O[nt][0] * linv0, O[nt][1] * linv0);
        unsigned w1 = h2pack(O[nt][2] * linv1, O[nt][3] * linv1);
        if (c < 32) {
            outvW[(size_t)r0 * 128 + (hof + c) / 2] = w0;
            outvW[(size_t)r1 * 128 + (hof + c) / 2] = w1;
        } else {
            int ch = (c - 32) >> 5;
            int d  = (c - 32) & 31;
            outgW[((size_t)r0 * 3 + ch) * 128 + (hof + d) / 2] = w0;
            outgW[((size_t)r1 * 3 + ch) * 128 + (hof + d) / 2] = w1;
        }
    }
}

// ---------------------------------------------------------------------------
// Host orchestration (multi-stream fork/join, capture-safe)
// ---------------------------------------------------------------------------
extern "C" void kernel_launch(void* const* d_in, const int* in_sizes, int n_in,
                              void* d_out, int out_size)
{
    const float* equ    = (const float*)d_in[0];
    const float* h      = (const float*)d_in[1];
    const float* W_equ  = (const float*)d_in[4];
    const float* W_gproj= (const float*)d_in[5];
    const float* W_vg   = (const float*)d_in[6];
    const float* W_g1   = (const float*)d_in[7];
    const float* b_g1   = (const float*)d_in[8];
    const float* W_g2   = (const float*)d_in[9];
    const float* b_g2   = (const float*)d_in[10];
    const float* W_q    = (const float*)d_in[11];
    const float* b_q    = (const float*)d_in[12];
    const float* W_k    = (const float*)d_in[13];
    const float* b_k    = (const float*)d_in[14];
    const float* W_v    = (const float*)d_in[15];
    const float* b_v    = (const float*)d_in[16];
    const float* W_ng   = (const float*)d_in[17];
    const float* b_ng   = (const float*)d_in[18];
    const float* W_gout = (const float*)d_in[19];
    const float* W_gdec = (const float*)d_in[20];
    const float* W_hdec = (const float*)d_in[21];
    const float* b_hdec = (const float*)d_in[22];

    float* out = (float*)d_out;

    static cudaStream_t s1 = nullptr, s2 = nullptr;
    static cudaEvent_t evRoot, evPrep, evPack, evH2, evVg, evAttn, evS1, evHout;
    if (!s1) {
        cudaStreamCreateWithFlags(&s1, cudaStreamNonBlocking);
        cudaStreamCreateWithFlags(&s2, cudaStreamNonBlocking);
        cudaEventCreateWithFlags(&evRoot, cudaEventDisableTiming);
        cudaEventCreateWithFlags(&evPrep, cudaEventDisableTiming);
        cudaEventCreateWithFlags(&evPack, cudaEventDisableTiming);
        cudaEventCreateWithFlags(&evH2, cudaEventDisableTiming);
        cudaEventCreateWithFlags(&evVg, cudaEventDisableTiming);
        cudaEventCreateWithFlags(&evAttn, cudaEventDisableTiming);
        cudaEventCreateWithFlags(&evS1, cudaEventDisableTiming);
        cudaEventCreateWithFlags(&evHout, cudaEventDisableTiming);
    }

    float* S = nullptr;
    cudaGetSymbolAddress((void**)&S, scratch);

    const int SM1 = (3 * ASZ + 3 * BSZ) * 4;        // 41472
    const int SM3 = SM1 * 2;                        // 82944
    cudaFuncSetAttribute(hgemm<1, true>,  cudaFuncAttributeMaxDynamicSharedMemorySize, SM1);
    cudaFuncSetAttribute(hgemm<1, false>, cudaFuncAttributeMaxDynamicSharedMemorySize, SM1);
    cudaFuncSetAttribute(hgemm<3, false>, cudaFuncAttributeMaxDynamicSharedMemorySize, SM3);
    cudaFuncSetAttribute(qkv_hgemm, cudaFuncAttributeMaxDynamicSharedMemorySize, SM3);
    cudaFuncSetAttribute(attn_kernel, cudaFuncAttributeMaxDynamicSharedMemorySize, ATTN_SMEM);

    __half* gram_h = (__half*)(S + OFF_GRAM);
    __half* hid_h  = (__half*)(S + OFF_HID);
    __half* h2hi   = (__half*)(S + OFF_H2HI);
    __half* h2lo   = (__half*)(S + OFF_H2LO);
    __half* qhi    = (__half*)(S + OFF_QHI);
    __half* qlo    = (__half*)(S + OFF_QLO);
    __half* khi    = (__half*)(S + OFF_KHI);
    __half* klo    = (__half*)(S + OFF_KLO);
    unsigned* vpair= (unsigned*)(S + OFF_VPAIR);
    __half* outv_h = (__half*)(S + OFF_OUTV);
    __half* outg_h = (__half*)(S + OFF_OUTG);
    float*  hpre   = S + OFF_HPRE;
    unsigned* Pg1  = (unsigned*)(S + OFF_PG1);
    unsigned* Pg2  = (unsigned*)(S + OFF_PG2);
    unsigned* Pqh  = (unsigned*)(S + OFF_PQH);
    unsigned* Pql  = (unsigned*)(S + OFF_PQL);
    unsigned* Pkh  = (unsigned*)(S + OFF_PKH);
    unsigned* Pkl  = (unsigned*)(S + OFF_PKL);
    unsigned* Pv   = (unsigned*)(S + OFF_PV);
    unsigned* Phdh = (unsigned*)(S + OFF_PHDH);
    unsigned* Phdl = (unsigned*)(S + OFF_PHDL);
    unsigned* W3p  = (unsigned*)(S + OFF_W3P);
    float* Wg      = S + OFF_WG;
    float* W1      = S + OFF_W1;
    float* Wvg2    = S + OFF_WVG2;
    float* W2f     = S + OFF_W2F;
    float* bias2   = S + OFF_BIAS2;

    const float scaling = 0.17677669529663687f;

    // ---- fork ----
    cudaEventRecord(evRoot, 0);
    cudaStreamWaitEvent(s1, evRoot, 0);
    cudaStreamWaitEvent(s2, evRoot, 0);

    // s2: h2fill early (only needs h)
    h2fill_kernel<<<(NN * EE + 255) / 256, 256, 0, s2>>>(h, h2hi, h2lo);
    cudaEventRecord(evH2, s2);

    // s1: weight packing + W3/bias2 + hpre
    pack_weights<<<2176, 256, 0, s1>>>(W_g1, W_g2, W_q, W_k, W_v, W_hdec,
                                       Pg1, Pg2, Pqh, Pql, Pkh, Pkl, Pv, Phdh, Phdl);
    cudaEventRecord(evPack, s1);
    prep_w3<<<129, 256, 0, s1>>>(W_ng, W_hdec, b_ng, b_hdec, W3p, bias2);
    cudaStreamWaitEvent(s1, evH2, 0);
    hgemm<3, false><<<dim3(2, 64), 256, SM3, s1>>>(h2hi + 256, h2lo + 256, 512,
                                                   Phdh, Phdl, 256,
                                                   bias2, nullptr, 0, 0.f, 1.f,
                                                   hpre, nullptr, nullptr, 256, 256);
    cudaEventRecord(evS1, s1);

    // main: prep combos
    prep_small<<<35, 256>>>(W_equ, W_gproj, W_gdec, W_vg, W_gout, Wg, W1, Wvg2, W2f);
    cudaEventRecord(evPrep, 0);

    // s2: vg -> vpair direct
    cudaStreamWaitEvent(s2, evPrep, 0);
    vg_small<<<192, 256, 0, s2>>>(equ, Wvg2, (__half*)vpair);
    cudaEventRecord(evVg, s2);

    // main: gram -> MLP -> qkv -> attention
    g2p_gram<<<NN, 128>>>(equ, Wg, gram_h);
    cudaStreamWaitEvent(0, evPack, 0);
    hgemm<1, true><<<dim3(4, 64), 256, SM1>>>(gram_h, nullptr, 1024, Pg1, nullptr, 512,
                                              b_g1, nullptr, 0, 0.f, 1.f,
                                              nullptr, hid_h, nullptr, 512, 1024);
    hgemm<1, false><<<dim3(2, 64), 256, SM1>>>(hid_h, nullptr, 512, Pg2, nullptr, 256,
                                               b_g2, nullptr, 0, 0.f, 1.f,
                                               nullptr, h2hi, h2lo, 512, 512);
    cudaStreamWaitEvent(0, evH2, 0);
    qkv_hgemm<<<dim3(2, 64, 3), 256, SM3>>>(h2hi, h2lo, Pqh, Pql, Pkh, Pkl, Pv,
                                            b_q, b_k, b_v, qhi, qlo, khi, klo,
                                            (__half*)vpair, scaling);
    cudaStreamWaitEvent(0, evVg, 0);
    attn_kernel<<<dim3(NN / AQ, HH), 256, ATTN_SMEM>>>(
        (const unsigned*)qhi, (const unsigned*)qlo,
        (const unsigned*)khi, (const unsigned*)klo,
        vpair, outv_h, outg_h);
    cudaEventRecord(evAttn, 0);

    // s2: h_out = outv@W3 + hpre
    cudaStreamWaitEvent(s2, evAttn, 0);
    cudaStreamWaitEvent(s2, evS1, 0);
    hgemm<1, false><<<dim3(2, 64), 256, SM1, s2>>>(outv_h, nullptr, 256, W3p, nullptr, 256,
                                                   nullptr, hpre, 256, 1.f, 1.f,
                                                   out + (size_t)ROWS * MMDIM,
                                                   nullptr, nullptr, 256, 256);
    cudaEventRecord(evHout, s2);

    // main: equ_out = equ@W1 + outg@W2f
    equ_out_kernel<<<768, 256>>>(equ, outg_h, W1, W2f, out);

    // ---- join ----
    cudaStreamWaitEvent(0, evHout, 0);
}